// round 2
// baseline (speedup 1.0000x reference)
#include <cuda_runtime.h>
#include <cuda_bf16.h>
#include <math.h>

// ---------------------------------------------------------------------------
// Problem constants (fixed shapes from setup_inputs)
// ---------------------------------------------------------------------------
#define BATCH 16
#define CH 3
#define IMG 512
#define PATCH 16
#define NPATCH 32              // IMG/PATCH per side
#define NTOK 1024              // NPATCH*NPATCH tokens per image
#define MTOT (BATCH * NTOK)    // 16384 total rows
#define DMODEL 768
#define FDIM 3072
#define QKVDIM 2304
#define NHEAD 12
#define DHEAD 64
#define WINSZ 64
#define NWIN 16                // NTOK / WINSZ

// ---------------------------------------------------------------------------
// Static device scratch (no runtime allocation allowed)
// ---------------------------------------------------------------------------
__device__ float g_im2col[(size_t)MTOT * DMODEL];   // 50 MB
__device__ float g_wT[(size_t)DMODEL * DMODEL];     // 2.3 MB  patch weight transposed [k][d]
__device__ float g_x0[(size_t)MTOT * DMODEL];       // 50 MB   LN+PE output (identity 1)
__device__ float g_h[(size_t)MTOT * FDIM];          // 201 MB  FF hidden
__device__ float g_y[(size_t)MTOT * DMODEL];        // 50 MB   scratch / ff out
__device__ float g_qkv[(size_t)MTOT * QKVDIM];      // 151 MB
__device__ float g_attn[(size_t)MTOT * DMODEL];     // 50 MB
__device__ float g_x2[(size_t)MTOT * DMODEL];       // 50 MB   identity 2

// ---------------------------------------------------------------------------
// im2col: A[m][k], m = b*1024 + hp*32 + wp, k = c*256 + p*16 + q
// ---------------------------------------------------------------------------
__global__ void im2col_kernel(const float* __restrict__ in) {
    size_t idx = (size_t)blockIdx.x * blockDim.x + threadIdx.x;
    size_t total = (size_t)MTOT * DMODEL;
    if (idx >= total) return;
    int k = (int)(idx % DMODEL);
    int m = (int)(idx / DMODEL);
    int q = k & 15;
    int p = (k >> 4) & 15;
    int c = k >> 8;
    int wp = m & 31;
    int hp = (m >> 5) & 31;
    int b = m >> 10;
    size_t src = (((size_t)(b * CH + c) * IMG) + (hp * PATCH + p)) * IMG + (wp * PATCH + q);
    g_im2col[idx] = in[src];
}

// patch_w [d][c][p][q] row-major -> wT[k][d]
__global__ void pack_wT_kernel(const float* __restrict__ pw) {
    int idx = blockIdx.x * blockDim.x + threadIdx.x;
    if (idx >= DMODEL * DMODEL) return;
    int d = idx % DMODEL;
    int k = idx / DMODEL;
    g_wT[idx] = pw[(size_t)d * DMODEL + k];
}

// ---------------------------------------------------------------------------
// Generic tiled SGEMM: C[M,N] = A[M,K] @ B[K,N] + bias (+gelu) (+res)
// BM=BN=128, BK=16, 256 threads, 8x8 per thread. M,N %128==0, K %16==0.
// ---------------------------------------------------------------------------
__device__ __forceinline__ float gelu_tanh(float x) {
    float x3 = x * x * x;
    return 0.5f * x * (1.0f + tanhf(0.7978845608028654f * (x + 0.044715f * x3)));
}

template <bool GELU, bool RES>
__global__ __launch_bounds__(256) void sgemm_kernel(
    const float* __restrict__ A, const float* __restrict__ B,
    const float* __restrict__ bias, const float* __restrict__ res,
    float* __restrict__ C, int M, int N, int K)
{
    constexpr int BM = 128, BN = 128, BK = 16;
    __shared__ float As[BK][BM];
    __shared__ float Bs[BK][BN];

    const int bx = blockIdx.x;   // N tile
    const int by = blockIdx.y;   // M tile
    const int tid = threadIdx.x;
    const int tx = tid & 15;     // 0..15 -> 8 cols each
    const int ty = tid >> 4;     // 0..15 -> 8 rows each

    const float* Ab = A + (size_t)by * BM * K;
    const float* Bb = B + (size_t)bx * BN;

    const int aRow = tid >> 2;          // 0..63
    const int aCol = (tid & 3) * 4;     // 0,4,8,12
    const int bRow = tid >> 5;          // 0..7
    const int bCol = (tid & 31) * 4;    // 0..124

    float acc[8][8];
#pragma unroll
    for (int i = 0; i < 8; i++)
#pragma unroll
        for (int j = 0; j < 8; j++) acc[i][j] = 0.f;

    for (int k0 = 0; k0 < K; k0 += BK) {
#pragma unroll
        for (int s = 0; s < 2; s++) {
            float4 v = *(const float4*)(Ab + (size_t)(aRow + s * 64) * K + k0 + aCol);
            As[aCol + 0][aRow + s * 64] = v.x;
            As[aCol + 1][aRow + s * 64] = v.y;
            As[aCol + 2][aRow + s * 64] = v.z;
            As[aCol + 3][aRow + s * 64] = v.w;
        }
#pragma unroll
        for (int s = 0; s < 2; s++) {
            *(float4*)(&Bs[bRow + s * 8][bCol]) =
                *(const float4*)(Bb + (size_t)(k0 + bRow + s * 8) * N + bCol);
        }
        __syncthreads();
#pragma unroll
        for (int kk = 0; kk < BK; kk++) {
            float ra[8], rb[8];
            *(float4*)(ra)     = *(const float4*)(&As[kk][ty * 8]);
            *(float4*)(ra + 4) = *(const float4*)(&As[kk][ty * 8 + 4]);
            *(float4*)(rb)     = *(const float4*)(&Bs[kk][tx * 8]);
            *(float4*)(rb + 4) = *(const float4*)(&Bs[kk][tx * 8 + 4]);
#pragma unroll
            for (int i = 0; i < 8; i++)
#pragma unroll
                for (int j = 0; j < 8; j++)
                    acc[i][j] = fmaf(ra[i], rb[j], acc[i][j]);
        }
        __syncthreads();
    }

#pragma unroll
    for (int i = 0; i < 8; i++) {
        int row = by * BM + ty * 8 + i;
#pragma unroll
        for (int j = 0; j < 8; j += 4) {
            int col = bx * BN + tx * 8 + j;
            float4 o;
            o.x = acc[i][j + 0] + bias[col + 0];
            o.y = acc[i][j + 1] + bias[col + 1];
            o.z = acc[i][j + 2] + bias[col + 2];
            o.w = acc[i][j + 3] + bias[col + 3];
            if (GELU) {
                o.x = gelu_tanh(o.x); o.y = gelu_tanh(o.y);
                o.z = gelu_tanh(o.z); o.w = gelu_tanh(o.w);
            }
            if (RES) {
                const float4 r = *(const float4*)(res + (size_t)row * N + col);
                o.x += r.x; o.y += r.y; o.z += r.z; o.w += r.w;
            }
            *(float4*)(C + (size_t)row * N + col) = o;
        }
    }
}

// ---------------------------------------------------------------------------
// LayerNorm + sinusoidal PE. One block (256 thr) per row; 768 = 3*256.
// Block reduction broadcasts partials through shared memory (the R1 bug was
// a cross-warp shuffle that only warp 0 could see).
// ---------------------------------------------------------------------------
__global__ void ln_pe_kernel(const float* __restrict__ x,
                             const float* __restrict__ gamma,
                             const float* __restrict__ beta,
                             float* __restrict__ out)
{
    const int row = blockIdx.x;
    const int tid = threadIdx.x;
    const float* xr = x + (size_t)row * DMODEL;

    float v0 = xr[tid], v1 = xr[tid + 256], v2 = xr[tid + 512];

    __shared__ float red[8];

    // ---- mean ----
    float s = v0 + v1 + v2;
#pragma unroll
    for (int o = 16; o > 0; o >>= 1) s += __shfl_xor_sync(0xffffffffu, s, o);
    if ((tid & 31) == 0) red[tid >> 5] = s;
    __syncthreads();
    float tot = red[0] + red[1] + red[2] + red[3] +
                red[4] + red[5] + red[6] + red[7];
    const float mean = tot / (float)DMODEL;
    __syncthreads();   // protect red before reuse

    float d0 = v0 - mean, d1 = v1 - mean, d2 = v2 - mean;

    // ---- var ----
    float sq = d0 * d0 + d1 * d1 + d2 * d2;
#pragma unroll
    for (int o = 16; o > 0; o >>= 1) sq += __shfl_xor_sync(0xffffffffu, sq, o);
    if ((tid & 31) == 0) red[tid >> 5] = sq;
    __syncthreads();
    float tot2 = red[0] + red[1] + red[2] + red[3] +
                 red[4] + red[5] + red[6] + red[7];
    const float inv = rsqrtf(tot2 / (float)DMODEL + 1e-5f);

    const float n = (float)(row & (NTOK - 1));
    float* orow = out + (size_t)row * DMODEL;
    const float dv[3] = {d0, d1, d2};
#pragma unroll
    for (int j = 0; j < 3; j++) {
        int d = tid + j * 256;
        float freq = expf((float)(d & ~1) * (-9.210340371976184f / (float)DMODEL));
        float ang = n * freq;
        float pe = (d & 1) ? cosf(ang) : sinf(ang);
        orow[d] = dv[j] * inv * gamma[d] + beta[d] + pe;
    }
}

// ---------------------------------------------------------------------------
// Windowed attention: one block per (b, window, head). 64x64 per head.
// ---------------------------------------------------------------------------
__global__ void attn_kernel(const float* __restrict__ qkv, float* __restrict__ out) {
    extern __shared__ float sm[];
    float* Qs = sm;                    // 64*65
    float* Ks = sm + 64 * 65;
    float* Vs = sm + 2 * 64 * 65;
    float* Ss = sm + 3 * 64 * 65;

    const int blk = blockIdx.x;
    const int h = blk % NHEAD;
    const int w = (blk / NHEAD) % NWIN;
    const int b = blk / (NHEAD * NWIN);
    const int m0 = b * NTOK + w * WINSZ;
    const int tid = threadIdx.x;

    for (int idx = tid; idx < WINSZ * DHEAD; idx += 256) {
        int t = idx >> 6, d = idx & 63;
        size_t base = (size_t)(m0 + t) * QKVDIM + h * DHEAD + d;
        Qs[t * 65 + d] = qkv[base];
        Ks[t * 65 + d] = qkv[base + DMODEL];
        Vs[t * 65 + d] = qkv[base + 2 * DMODEL];
    }
    __syncthreads();

    for (int idx = tid; idx < WINSZ * WINSZ; idx += 256) {
        int q = idx >> 6, k = idx & 63;
        float s = 0.f;
#pragma unroll
        for (int i = 0; i < DHEAD; i++) s = fmaf(Qs[q * 65 + i], Ks[k * 65 + i], s);
        Ss[q * 65 + k] = s * 0.125f;   // dh^-0.5 = 1/8
    }
    __syncthreads();

    if (tid < WINSZ) {
        float mx = -1e30f;
#pragma unroll 8
        for (int k = 0; k < WINSZ; k++) mx = fmaxf(mx, Ss[tid * 65 + k]);
        float sum = 0.f;
#pragma unroll 8
        for (int k = 0; k < WINSZ; k++) {
            float e = expf(Ss[tid * 65 + k] - mx);
            Ss[tid * 65 + k] = e;
            sum += e;
        }
        float invs = 1.f / sum;
#pragma unroll 8
        for (int k = 0; k < WINSZ; k++) Ss[tid * 65 + k] *= invs;
    }
    __syncthreads();

    for (int idx = tid; idx < WINSZ * DHEAD; idx += 256) {
        int q = idx >> 6, d = idx & 63;
        float o = 0.f;
#pragma unroll
        for (int k = 0; k < WINSZ; k++) o = fmaf(Ss[q * 65 + k], Vs[k * 65 + d], o);
        out[(size_t)(m0 + q) * DMODEL + h * DHEAD + d] = o;
    }
}

// ---------------------------------------------------------------------------
// Launch pipeline
// ---------------------------------------------------------------------------
extern "C" void kernel_launch(void* const* d_in, const int* in_sizes, int n_in,
                              void* d_out, int out_size)
{
    const float* input   = (const float*)d_in[0];
    const float* patch_w = (const float*)d_in[1];
    const float* patch_b = (const float*)d_in[2];
    const float* ln_g    = (const float*)d_in[3];
    const float* ln_b    = (const float*)d_in[4];
    const float* qkv_w   = (const float*)d_in[5];
    const float* qkv_b   = (const float*)d_in[6];
    const float* proj_w  = (const float*)d_in[7];
    const float* proj_b  = (const float*)d_in[8];
    const float* ff1_w   = (const float*)d_in[9];
    const float* ff1_b   = (const float*)d_in[10];
    const float* ff2_w   = (const float*)d_in[11];
    const float* ff2_b   = (const float*)d_in[12];
    float* out = (float*)d_out;

    float *im2col_p, *wT_p, *x0_p, *h_p, *y_p, *qkv_p, *attn_p, *x2_p;
    cudaGetSymbolAddress((void**)&im2col_p, g_im2col);
    cudaGetSymbolAddress((void**)&wT_p, g_wT);
    cudaGetSymbolAddress((void**)&x0_p, g_x0);
    cudaGetSymbolAddress((void**)&h_p, g_h);
    cudaGetSymbolAddress((void**)&y_p, g_y);
    cudaGetSymbolAddress((void**)&qkv_p, g_qkv);
    cudaGetSymbolAddress((void**)&attn_p, g_attn);
    cudaGetSymbolAddress((void**)&x2_p, g_x2);

    const int ATTN_SMEM = 4 * 64 * 65 * sizeof(float);
    cudaFuncSetAttribute(attn_kernel, cudaFuncAttributeMaxDynamicSharedMemorySize, ATTN_SMEM);

    // 1. im2col
    {
        size_t total = (size_t)MTOT * DMODEL;
        im2col_kernel<<<(unsigned)((total + 255) / 256), 256>>>(input);
    }
    // 2. pack transposed patch weight
    pack_wT_kernel<<<(DMODEL * DMODEL + 255) / 256, 256>>>(patch_w);

    dim3 gD(DMODEL / 128, MTOT / 128);     // (6,128)
    dim3 gF(FDIM / 128, MTOT / 128);       // (24,128)
    dim3 gQ(QKVDIM / 128, MTOT / 128);     // (18,128)

    // 3. patch embed GEMM -> g_y
    sgemm_kernel<false, false><<<gD, 256>>>(im2col_p, wT_p, patch_b, nullptr, y_p,
                                            MTOT, DMODEL, DMODEL);
    // 4. LN + PE -> g_x0 (identity 1)
    ln_pe_kernel<<<MTOT, 256>>>(y_p, ln_g, ln_b, x0_p);

    // 5. ff1 + gelu -> g_h
    sgemm_kernel<true, false><<<gF, 256>>>(x0_p, ff1_w, ff1_b, nullptr, h_p,
                                           MTOT, FDIM, DMODEL);
    // 6. ff2 -> g_y
    sgemm_kernel<false, false><<<gD, 256>>>(h_p, ff2_w, ff2_b, nullptr, y_p,
                                            MTOT, DMODEL, FDIM);
    // 7. qkv -> g_qkv
    sgemm_kernel<false, false><<<gQ, 256>>>(y_p, qkv_w, qkv_b, nullptr, qkv_p,
                                            MTOT, QKVDIM, DMODEL);
    // 8. attention -> g_attn
    attn_kernel<<<BATCH * NWIN * NHEAD, 256, ATTN_SMEM>>>(qkv_p, attn_p);

    // 9. proj + residual(x0) -> g_x2 (identity 2)
    sgemm_kernel<false, true><<<gD, 256>>>(attn_p, proj_w, proj_b, x0_p, x2_p,
                                           MTOT, DMODEL, DMODEL);
    // 10. ff1 + gelu -> g_h
    sgemm_kernel<true, false><<<gF, 256>>>(x2_p, ff1_w, ff1_b, nullptr, h_p,
                                           MTOT, FDIM, DMODEL);
    // 11. ff2 + residual(x2) -> d_out
    sgemm_kernel<false, true><<<gD, 256>>>(h_p, ff2_w, ff2_b, x2_p, out,
                                           MTOT, DMODEL, FDIM);
}

// round 3
// speedup vs baseline: 1.7334x; 1.7334x over previous
#include <cuda_runtime.h>
#include <cuda_bf16.h>
#include <math.h>
#include <stdint.h>

// ---------------------------------------------------------------------------
// Problem constants
// ---------------------------------------------------------------------------
#define BATCH 16
#define CH 3
#define IMG 512
#define PATCH 16
#define NTOK 1024
#define MTOT (BATCH * NTOK)    // 16384
#define DMODEL 768
#define FDIM 3072
#define QKVDIM 2304
#define NHEAD 12
#define DHEAD 64
#define WINSZ 64
#define NWIN 16

// ---------------------------------------------------------------------------
// Static device scratch
// ---------------------------------------------------------------------------
__device__ float g_im2col[(size_t)MTOT * DMODEL];
__device__ float g_wT[(size_t)DMODEL * DMODEL];
__device__ float g_x0[(size_t)MTOT * DMODEL];
__device__ float g_h[(size_t)MTOT * FDIM];
__device__ float g_y[(size_t)MTOT * DMODEL];
__device__ float g_qkv[(size_t)MTOT * QKVDIM];
__device__ float g_attn[(size_t)MTOT * DMODEL];
__device__ float g_x2[(size_t)MTOT * DMODEL];

// ---------------------------------------------------------------------------
// im2col
// ---------------------------------------------------------------------------
__global__ void im2col_kernel(const float* __restrict__ in) {
    size_t idx = (size_t)blockIdx.x * blockDim.x + threadIdx.x;
    size_t total = (size_t)MTOT * DMODEL;
    if (idx >= total) return;
    int k = (int)(idx % DMODEL);
    int m = (int)(idx / DMODEL);
    int q = k & 15;
    int p = (k >> 4) & 15;
    int c = k >> 8;
    int wp = m & 31;
    int hp = (m >> 5) & 31;
    int b = m >> 10;
    size_t src = (((size_t)(b * CH + c) * IMG) + (hp * PATCH + p)) * IMG + (wp * PATCH + q);
    g_im2col[idx] = in[src];
}

__global__ void pack_wT_kernel(const float* __restrict__ pw) {
    int idx = blockIdx.x * blockDim.x + threadIdx.x;
    if (idx >= DMODEL * DMODEL) return;
    int d = idx % DMODEL;
    int k = idx / DMODEL;
    g_wT[idx] = pw[(size_t)d * DMODEL + k];
}

// ---------------------------------------------------------------------------
// Tensor-core GEMM: split-bf16 (hi/lo), 3 MMAs per logical fp32 product.
// C = A[M,K] @ B[K,N] (+bias)(+gelu)(+res). Block 128x128, BK=32, 8 warps.
// ---------------------------------------------------------------------------
__device__ __forceinline__ float gelu_tanh(float x) {
    float x3 = x * x * x;
    return 0.5f * x * (1.0f + tanhf(0.7978845608028654f * (x + 0.044715f * x3)));
}

__device__ __forceinline__ uint32_t smem_u32(const void* p) {
    return (uint32_t)__cvta_generic_to_shared(p);
}

__device__ __forceinline__ void ldsmx4(uint32_t& r0, uint32_t& r1, uint32_t& r2, uint32_t& r3, uint32_t a) {
    asm volatile("ldmatrix.sync.aligned.m8n8.x4.shared.b16 {%0,%1,%2,%3},[%4];"
                 : "=r"(r0), "=r"(r1), "=r"(r2), "=r"(r3) : "r"(a));
}
__device__ __forceinline__ void ldsmx4t(uint32_t& r0, uint32_t& r1, uint32_t& r2, uint32_t& r3, uint32_t a) {
    asm volatile("ldmatrix.sync.aligned.m8n8.x4.trans.shared.b16 {%0,%1,%2,%3},[%4];"
                 : "=r"(r0), "=r"(r1), "=r"(r2), "=r"(r3) : "r"(a));
}
__device__ __forceinline__ void mma_bf16(float* d, const uint32_t* a, const uint32_t* b) {
    asm volatile("mma.sync.aligned.m16n8k16.row.col.f32.bf16.bf16.f32 "
                 "{%0,%1,%2,%3},{%4,%5,%6,%7},{%8,%9},{%0,%1,%2,%3};"
                 : "+f"(d[0]), "+f"(d[1]), "+f"(d[2]), "+f"(d[3])
                 : "r"(a[0]), "r"(a[1]), "r"(a[2]), "r"(a[3]), "r"(b[0]), "r"(b[1]));
}

__device__ __forceinline__ uint32_t pk(__nv_bfloat16 a, __nv_bfloat16 b) {
    __nv_bfloat162 t = __halves2bfloat162(a, b);
    return *(uint32_t*)&t;
}
// split pair (x,y) into packed hi-u32 and lo-u32
__device__ __forceinline__ void split2(float x, float y, uint32_t& hi, uint32_t& lo) {
    __nv_bfloat16 hx = __float2bfloat16(x), hy = __float2bfloat16(y);
    __nv_bfloat16 lx = __float2bfloat16(x - __bfloat162float(hx));
    __nv_bfloat16 ly = __float2bfloat16(y - __bfloat162float(hy));
    hi = pk(hx, hy);
    lo = pk(lx, ly);
}

#define AST 40   // As row stride (bf16 elems): 32 + 8 pad -> conflict-free
#define BST 136  // Bs row stride: 128 + 8 pad -> conflict-free

template <bool GELU, bool RES>
__global__ __launch_bounds__(256) void mma_gemm(
    const float* __restrict__ A, const float* __restrict__ B,
    const float* __restrict__ bias, const float* __restrict__ res,
    float* __restrict__ C, int M, int N, int K)
{
    __shared__ __nv_bfloat16 As_hi[128 * AST];
    __shared__ __nv_bfloat16 As_lo[128 * AST];
    __shared__ __nv_bfloat16 Bs_hi[32 * BST];
    __shared__ __nv_bfloat16 Bs_lo[32 * BST];

    const int tid = threadIdx.x;
    const int l = tid & 31;
    const int w = tid >> 5;
    const int wm = (w & 1) * 64;    // warp m-offset within block
    const int wn = (w >> 1) * 32;   // warp n-offset within block
    const int m0 = blockIdx.y * 128;
    const int n0 = blockIdx.x * 128;

    const uint32_t sAh = smem_u32(As_hi), sAl = smem_u32(As_lo);
    const uint32_t sBh = smem_u32(Bs_hi), sBl = smem_u32(Bs_lo);

    float acc[4][4][4];
#pragma unroll
    for (int i = 0; i < 4; i++)
#pragma unroll
        for (int j = 0; j < 4; j++)
#pragma unroll
            for (int r = 0; r < 4; r++) acc[i][j][r] = 0.f;

    const int arow = tid >> 3, acol = (tid & 7) * 4;
    const int bk = tid >> 3, bn = (tid & 7) * 4;

    for (int k0 = 0; k0 < K; k0 += 32) {
        // ---- stage A (fp32 -> hi/lo bf16) ----
#pragma unroll
        for (int s = 0; s < 4; s++) {
            int m = arow + s * 32;
            float4 v = *(const float4*)(A + (size_t)(m0 + m) * K + k0 + acol);
            uint32_t h0, l0, h1, l1;
            split2(v.x, v.y, h0, l0);
            split2(v.z, v.w, h1, l1);
            uint2 ph = make_uint2(h0, h1), pl = make_uint2(l0, l1);
            *(uint2*)&As_hi[m * AST + acol] = ph;
            *(uint2*)&As_lo[m * AST + acol] = pl;
        }
        // ---- stage B ----
#pragma unroll
        for (int s = 0; s < 4; s++) {
            int n = bn + s * 32;
            float4 v = *(const float4*)(B + (size_t)(k0 + bk) * N + n0 + n);
            uint32_t h0, l0, h1, l1;
            split2(v.x, v.y, h0, l0);
            split2(v.z, v.w, h1, l1);
            uint2 ph = make_uint2(h0, h1), pl = make_uint2(l0, l1);
            *(uint2*)&Bs_hi[bk * BST + n] = ph;
            *(uint2*)&Bs_lo[bk * BST + n] = pl;
        }
        __syncthreads();

#pragma unroll
        for (int ks = 0; ks < 2; ks++) {
            // B fragments: 4 n-frags (8 cols each), hi and lo
            uint32_t bh[4][2], bl[4][2];
#pragma unroll
            for (int nf2 = 0; nf2 < 2; nf2++) {
                int row = ks * 16 + (l & 7) + ((l >> 3) & 1) * 8;
                int col = wn + nf2 * 16 + (l >> 4) * 8;
                uint32_t off = (uint32_t)(row * BST + col) * 2;
                ldsmx4t(bh[nf2 * 2][0], bh[nf2 * 2][1], bh[nf2 * 2 + 1][0], bh[nf2 * 2 + 1][1], sBh + off);
                ldsmx4t(bl[nf2 * 2][0], bl[nf2 * 2][1], bl[nf2 * 2 + 1][0], bl[nf2 * 2 + 1][1], sBl + off);
            }
#pragma unroll
            for (int mf = 0; mf < 4; mf++) {
                int row = wm + mf * 16 + (l & 7) + ((l >> 3) & 1) * 8;
                int col = ks * 16 + (l >> 4) * 8;
                uint32_t off = (uint32_t)(row * AST + col) * 2;
                uint32_t ah[4], al[4];
                ldsmx4(ah[0], ah[1], ah[2], ah[3], sAh + off);
                ldsmx4(al[0], al[1], al[2], al[3], sAl + off);
#pragma unroll
                for (int nf = 0; nf < 4; nf++) {
                    mma_bf16(acc[mf][nf], ah, bh[nf]);
                    mma_bf16(acc[mf][nf], ah, bl[nf]);
                    mma_bf16(acc[mf][nf], al, bh[nf]);
                }
            }
        }
        __syncthreads();
    }

    // ---- epilogue ----
#pragma unroll
    for (int mf = 0; mf < 4; mf++) {
        int r0 = m0 + wm + mf * 16 + (l >> 2);
#pragma unroll
        for (int nf = 0; nf < 4; nf++) {
            int col = n0 + wn + nf * 8 + (l & 3) * 2;
            float bx = bias[col], by = bias[col + 1];
            float2 o0 = make_float2(acc[mf][nf][0] + bx, acc[mf][nf][1] + by);
            float2 o1 = make_float2(acc[mf][nf][2] + bx, acc[mf][nf][3] + by);
            if (GELU) {
                o0.x = gelu_tanh(o0.x); o0.y = gelu_tanh(o0.y);
                o1.x = gelu_tanh(o1.x); o1.y = gelu_tanh(o1.y);
            }
            if (RES) {
                float2 ra = *(const float2*)(res + (size_t)r0 * N + col);
                float2 rb = *(const float2*)(res + (size_t)(r0 + 8) * N + col);
                o0.x += ra.x; o0.y += ra.y;
                o1.x += rb.x; o1.y += rb.y;
            }
            *(float2*)(C + (size_t)r0 * N + col) = o0;
            *(float2*)(C + (size_t)(r0 + 8) * N + col) = o1;
        }
    }
}

// ---------------------------------------------------------------------------
// LayerNorm + sinusoidal PE (R2-verified)
// ---------------------------------------------------------------------------
__global__ void ln_pe_kernel(const float* __restrict__ x,
                             const float* __restrict__ gamma,
                             const float* __restrict__ beta,
                             float* __restrict__ out)
{
    const int row = blockIdx.x;
    const int tid = threadIdx.x;
    const float* xr = x + (size_t)row * DMODEL;

    float v0 = xr[tid], v1 = xr[tid + 256], v2 = xr[tid + 512];

    __shared__ float red[8];

    float s = v0 + v1 + v2;
#pragma unroll
    for (int o = 16; o > 0; o >>= 1) s += __shfl_xor_sync(0xffffffffu, s, o);
    if ((tid & 31) == 0) red[tid >> 5] = s;
    __syncthreads();
    float tot = red[0] + red[1] + red[2] + red[3] + red[4] + red[5] + red[6] + red[7];
    const float mean = tot / (float)DMODEL;
    __syncthreads();

    float d0 = v0 - mean, d1 = v1 - mean, d2 = v2 - mean;

    float sq = d0 * d0 + d1 * d1 + d2 * d2;
#pragma unroll
    for (int o = 16; o > 0; o >>= 1) sq += __shfl_xor_sync(0xffffffffu, sq, o);
    if ((tid & 31) == 0) red[tid >> 5] = sq;
    __syncthreads();
    float tot2 = red[0] + red[1] + red[2] + red[3] + red[4] + red[5] + red[6] + red[7];
    const float inv = rsqrtf(tot2 / (float)DMODEL + 1e-5f);

    const float n = (float)(row & (NTOK - 1));
    float* orow = out + (size_t)row * DMODEL;
    const float dv[3] = {d0, d1, d2};
#pragma unroll
    for (int j = 0; j < 3; j++) {
        int d = tid + j * 256;
        float freq = expf((float)(d & ~1) * (-9.210340371976184f / (float)DMODEL));
        float ang = n * freq;
        float pe = (d & 1) ? cosf(ang) : sinf(ang);
        orow[d] = dv[j] * inv * gamma[d] + beta[d] + pe;
    }
}

// ---------------------------------------------------------------------------
// Windowed attention (R2-verified)
// ---------------------------------------------------------------------------
__global__ void attn_kernel(const float* __restrict__ qkv, float* __restrict__ out) {
    extern __shared__ float sm[];
    float* Qs = sm;
    float* Ks = sm + 64 * 65;
    float* Vs = sm + 2 * 64 * 65;
    float* Ss = sm + 3 * 64 * 65;

    const int blk = blockIdx.x;
    const int h = blk % NHEAD;
    const int w = (blk / NHEAD) % NWIN;
    const int b = blk / (NHEAD * NWIN);
    const int m0 = b * NTOK + w * WINSZ;
    const int tid = threadIdx.x;

    for (int idx = tid; idx < WINSZ * DHEAD; idx += 256) {
        int t = idx >> 6, d = idx & 63;
        size_t base = (size_t)(m0 + t) * QKVDIM + h * DHEAD + d;
        Qs[t * 65 + d] = qkv[base];
        Ks[t * 65 + d] = qkv[base + DMODEL];
        Vs[t * 65 + d] = qkv[base + 2 * DMODEL];
    }
    __syncthreads();

    for (int idx = tid; idx < WINSZ * WINSZ; idx += 256) {
        int q = idx >> 6, k = idx & 63;
        float s = 0.f;
#pragma unroll
        for (int i = 0; i < DHEAD; i++) s = fmaf(Qs[q * 65 + i], Ks[k * 65 + i], s);
        Ss[q * 65 + k] = s * 0.125f;
    }
    __syncthreads();

    if (tid < WINSZ) {
        float mx = -1e30f;
#pragma unroll 8
        for (int k = 0; k < WINSZ; k++) mx = fmaxf(mx, Ss[tid * 65 + k]);
        float sum = 0.f;
#pragma unroll 8
        for (int k = 0; k < WINSZ; k++) {
            float e = expf(Ss[tid * 65 + k] - mx);
            Ss[tid * 65 + k] = e;
            sum += e;
        }
        float invs = 1.f / sum;
#pragma unroll 8
        for (int k = 0; k < WINSZ; k++) Ss[tid * 65 + k] *= invs;
    }
    __syncthreads();

    for (int idx = tid; idx < WINSZ * DHEAD; idx += 256) {
        int q = idx >> 6, d = idx & 63;
        float o = 0.f;
#pragma unroll
        for (int k = 0; k < WINSZ; k++) o = fmaf(Ss[q * 65 + k], Vs[k * 65 + d], o);
        out[(size_t)(m0 + q) * DMODEL + h * DHEAD + d] = o;
    }
}

// ---------------------------------------------------------------------------
// Launch pipeline
// ---------------------------------------------------------------------------
extern "C" void kernel_launch(void* const* d_in, const int* in_sizes, int n_in,
                              void* d_out, int out_size)
{
    const float* input   = (const float*)d_in[0];
    const float* patch_w = (const float*)d_in[1];
    const float* patch_b = (const float*)d_in[2];
    const float* ln_g    = (const float*)d_in[3];
    const float* ln_b    = (const float*)d_in[4];
    const float* qkv_w   = (const float*)d_in[5];
    const float* qkv_b   = (const float*)d_in[6];
    const float* proj_w  = (const float*)d_in[7];
    const float* proj_b  = (const float*)d_in[8];
    const float* ff1_w   = (const float*)d_in[9];
    const float* ff1_b   = (const float*)d_in[10];
    const float* ff2_w   = (const float*)d_in[11];
    const float* ff2_b   = (const float*)d_in[12];
    float* out = (float*)d_out;

    float *im2col_p, *wT_p, *x0_p, *h_p, *y_p, *qkv_p, *attn_p, *x2_p;
    cudaGetSymbolAddress((void**)&im2col_p, g_im2col);
    cudaGetSymbolAddress((void**)&wT_p, g_wT);
    cudaGetSymbolAddress((void**)&x0_p, g_x0);
    cudaGetSymbolAddress((void**)&h_p, g_h);
    cudaGetSymbolAddress((void**)&y_p, g_y);
    cudaGetSymbolAddress((void**)&qkv_p, g_qkv);
    cudaGetSymbolAddress((void**)&attn_p, g_attn);
    cudaGetSymbolAddress((void**)&x2_p, g_x2);

    const int ATTN_SMEM = 4 * 64 * 65 * sizeof(float);
    cudaFuncSetAttribute(attn_kernel, cudaFuncAttributeMaxDynamicSharedMemorySize, ATTN_SMEM);

    {
        size_t total = (size_t)MTOT * DMODEL;
        im2col_kernel<<<(unsigned)((total + 255) / 256), 256>>>(input);
    }
    pack_wT_kernel<<<(DMODEL * DMODEL + 255) / 256, 256>>>(patch_w);

    dim3 gD(DMODEL / 128, MTOT / 128);     // (6,128)
    dim3 gF(FDIM / 128, MTOT / 128);       // (24,128)
    dim3 gQ(QKVDIM / 128, MTOT / 128);     // (18,128)

    // patch embed
    mma_gemm<false, false><<<gD, 256>>>(im2col_p, wT_p, patch_b, nullptr, y_p,
                                        MTOT, DMODEL, DMODEL);
    // LN + PE
    ln_pe_kernel<<<MTOT, 256>>>(y_p, ln_g, ln_b, x0_p);

    // ff1 + gelu
    mma_gemm<true, false><<<gF, 256>>>(x0_p, ff1_w, ff1_b, nullptr, h_p,
                                       MTOT, FDIM, DMODEL);
    // ff2
    mma_gemm<false, false><<<gD, 256>>>(h_p, ff2_w, ff2_b, nullptr, y_p,
                                        MTOT, DMODEL, FDIM);
    // qkv
    mma_gemm<false, false><<<gQ, 256>>>(y_p, qkv_w, qkv_b, nullptr, qkv_p,
                                        MTOT, QKVDIM, DMODEL);
    // attention
    attn_kernel<<<BATCH * NWIN * NHEAD, 256, ATTN_SMEM>>>(qkv_p, attn_p);

    // proj + residual(x0)
    mma_gemm<false, true><<<gD, 256>>>(attn_p, proj_w, proj_b, x0_p, x2_p,
                                       MTOT, DMODEL, DMODEL);
    // ff1 + gelu
    mma_gemm<true, false><<<gF, 256>>>(x2_p, ff1_w, ff1_b, nullptr, h_p,
                                       MTOT, FDIM, DMODEL);
    // ff2 + residual(x2)
    mma_gemm<false, true><<<gD, 256>>>(h_p, ff2_w, ff2_b, x2_p, out,
                                       MTOT, DMODEL, FDIM);
}

// round 4
// speedup vs baseline: 2.1573x; 1.2445x over previous
#include <cuda_runtime.h>
#include <cuda_bf16.h>
#include <math.h>
#include <stdint.h>

// ---------------------------------------------------------------------------
// Problem constants
// ---------------------------------------------------------------------------
#define BATCH 16
#define CH 3
#define IMG 512
#define PATCH 16
#define NTOK 1024
#define MTOT (BATCH * NTOK)    // 16384
#define DMODEL 768
#define FDIM 3072
#define QKVDIM 2304
#define NHEAD 12
#define DHEAD 64
#define WINSZ 64
#define NWIN 16

typedef __nv_bfloat16 bf16;

// ---------------------------------------------------------------------------
// Static device scratch: split bf16 hi/lo planes + fp32 where needed
// ---------------------------------------------------------------------------
__device__ bf16 g_Ah0[(size_t)MTOT * DMODEL];   // im2col planes
__device__ bf16 g_Al0[(size_t)MTOT * DMODEL];
__device__ bf16 g_wTh[(size_t)DMODEL * DMODEL]; // patch weight T planes
__device__ bf16 g_wTl[(size_t)DMODEL * DMODEL];
__device__ bf16 g_qkvWh[(size_t)DMODEL * QKVDIM];
__device__ bf16 g_qkvWl[(size_t)DMODEL * QKVDIM];
__device__ bf16 g_projWh[(size_t)DMODEL * DMODEL];
__device__ bf16 g_projWl[(size_t)DMODEL * DMODEL];
__device__ bf16 g_ff1Wh[(size_t)DMODEL * FDIM];
__device__ bf16 g_ff1Wl[(size_t)DMODEL * FDIM];
__device__ bf16 g_ff2Wh[(size_t)FDIM * DMODEL];
__device__ bf16 g_ff2Wl[(size_t)FDIM * DMODEL];

__device__ float g_y[(size_t)MTOT * DMODEL];    // patch-GEMM out (fp32)
__device__ float g_x0[(size_t)MTOT * DMODEL];   // identity 1 fp32
__device__ bf16  g_x0h[(size_t)MTOT * DMODEL];
__device__ bf16  g_x0l[(size_t)MTOT * DMODEL];
__device__ bf16  g_hh[(size_t)MTOT * FDIM];     // ff hidden planes
__device__ bf16  g_hl[(size_t)MTOT * FDIM];
__device__ bf16  g_yh[(size_t)MTOT * DMODEL];   // ff2 out planes (qkv input)
__device__ bf16  g_yl[(size_t)MTOT * DMODEL];
__device__ float g_qkv[(size_t)MTOT * QKVDIM];
__device__ bf16  g_attnh[(size_t)MTOT * DMODEL];
__device__ bf16  g_attnl[(size_t)MTOT * DMODEL];
__device__ float g_x2[(size_t)MTOT * DMODEL];   // identity 2 fp32
__device__ bf16  g_x2h[(size_t)MTOT * DMODEL];
__device__ bf16  g_x2l[(size_t)MTOT * DMODEL];

// ---------------------------------------------------------------------------
// Helpers
// ---------------------------------------------------------------------------
__device__ __forceinline__ void split1(float x, bf16& hi, bf16& lo) {
    hi = __float2bfloat16(x);
    lo = __float2bfloat16(x - __bfloat162float(hi));
}

__device__ __forceinline__ float gelu_tanh(float x) {
    float x3 = x * x * x;
    return 0.5f * x * (1.0f + tanhf(0.7978845608028654f * (x + 0.044715f * x3)));
}

__device__ __forceinline__ uint32_t smem_u32(const void* p) {
    return (uint32_t)__cvta_generic_to_shared(p);
}

__device__ __forceinline__ void cpa16(uint32_t dst, const void* src) {
    asm volatile("cp.async.cg.shared.global [%0], [%1], 16;" :: "r"(dst), "l"(src) : "memory");
}
__device__ __forceinline__ void cpa_commit() {
    asm volatile("cp.async.commit_group;" ::: "memory");
}
template <int N>
__device__ __forceinline__ void cpa_wait() {
    asm volatile("cp.async.wait_group %0;" :: "n"(N) : "memory");
}

__device__ __forceinline__ void ldsmx4(uint32_t& r0, uint32_t& r1, uint32_t& r2, uint32_t& r3, uint32_t a) {
    asm volatile("ldmatrix.sync.aligned.m8n8.x4.shared.b16 {%0,%1,%2,%3},[%4];"
                 : "=r"(r0), "=r"(r1), "=r"(r2), "=r"(r3) : "r"(a));
}
__device__ __forceinline__ void ldsmx4t(uint32_t& r0, uint32_t& r1, uint32_t& r2, uint32_t& r3, uint32_t a) {
    asm volatile("ldmatrix.sync.aligned.m8n8.x4.trans.shared.b16 {%0,%1,%2,%3},[%4];"
                 : "=r"(r0), "=r"(r1), "=r"(r2), "=r"(r3) : "r"(a));
}
__device__ __forceinline__ void mma_bf16(float* d, const uint32_t* a, const uint32_t* b) {
    asm volatile("mma.sync.aligned.m16n8k16.row.col.f32.bf16.bf16.f32 "
                 "{%0,%1,%2,%3},{%4,%5,%6,%7},{%8,%9},{%0,%1,%2,%3};"
                 : "+f"(d[0]), "+f"(d[1]), "+f"(d[2]), "+f"(d[3])
                 : "r"(a[0]), "r"(a[1]), "r"(a[2]), "r"(a[3]), "r"(b[0]), "r"(b[1]));
}

// ---------------------------------------------------------------------------
// Producers: im2col / weight packing / generic convert (fp32 -> hi/lo planes)
// ---------------------------------------------------------------------------
__global__ void im2col_split_kernel(const float* __restrict__ in) {
    size_t idx = (size_t)blockIdx.x * blockDim.x + threadIdx.x;
    size_t total = (size_t)MTOT * DMODEL;
    if (idx >= total) return;
    int k = (int)(idx % DMODEL);
    int m = (int)(idx / DMODEL);
    int q = k & 15;
    int p = (k >> 4) & 15;
    int c = k >> 8;
    int wp = m & 31;
    int hp = (m >> 5) & 31;
    int b = m >> 10;
    size_t src = (((size_t)(b * CH + c) * IMG) + (hp * PATCH + p)) * IMG + (wp * PATCH + q);
    bf16 hi, lo;
    split1(in[src], hi, lo);
    g_Ah0[idx] = hi;
    g_Al0[idx] = lo;
}

__global__ void pack_wT_split_kernel(const float* __restrict__ pw) {
    int idx = blockIdx.x * blockDim.x + threadIdx.x;
    if (idx >= DMODEL * DMODEL) return;
    int d = idx % DMODEL;
    int k = idx / DMODEL;
    bf16 hi, lo;
    split1(pw[(size_t)d * DMODEL + k], hi, lo);
    g_wTh[idx] = hi;
    g_wTl[idx] = lo;
}

__global__ void convert_split_kernel(const float* __restrict__ src,
                                     bf16* __restrict__ hi_p, bf16* __restrict__ lo_p, int n) {
    int idx = blockIdx.x * blockDim.x + threadIdx.x;
    if (idx >= n) return;
    bf16 hi, lo;
    split1(src[idx], hi, lo);
    hi_p[idx] = hi;
    lo_p[idx] = lo;
}

// ---------------------------------------------------------------------------
// Tensor-core GEMM on pre-split planes. Block 128x128, BK=32, 8 warps,
// cp.async double-buffered. 3 MMAs per logical fp32 product (hh + hl + lh).
// ---------------------------------------------------------------------------
#define AST 40   // As row stride (bf16): 32 + 8 pad
#define BST 136  // Bs row stride: 128 + 8 pad
#define ASZ (128 * AST)
#define BSZ (32 * BST)
#define GEMM_SMEM ((4 * ASZ + 4 * BSZ) * 2)   // bytes: 2 stages x 2 planes x (A+B)

template <bool GELU, bool RES, bool WF32, bool WSPLIT>
__global__ __launch_bounds__(256) void mma_gemm(
    const bf16* __restrict__ Ah, const bf16* __restrict__ Al,
    const bf16* __restrict__ Bh, const bf16* __restrict__ Bl,
    const float* __restrict__ bias, const float* __restrict__ res,
    float* __restrict__ Cf, bf16* __restrict__ Ch, bf16* __restrict__ Cl,
    int M, int N, int K)
{
    extern __shared__ bf16 sm_[];
    const uint32_t base = smem_u32(sm_);
    // byte offsets per stage/plane
    auto offAh = [&](int st) { return (uint32_t)(st * ASZ) * 2; };
    auto offAl = [&](int st) { return (uint32_t)((2 + st) * ASZ) * 2; };
    auto offBh = [&](int st) { return (uint32_t)(4 * ASZ + st * BSZ) * 2; };
    auto offBl = [&](int st) { return (uint32_t)(4 * ASZ + (2 + st) * BSZ) * 2; };

    const int tid = threadIdx.x;
    const int l = tid & 31;
    const int w = tid >> 5;
    const int wm = (w & 1) * 64;
    const int wn = (w >> 1) * 32;
    const int m0 = blockIdx.y * 128;
    const int n0 = blockIdx.x * 128;

    float acc[4][4][4];
#pragma unroll
    for (int i = 0; i < 4; i++)
#pragma unroll
        for (int j = 0; j < 4; j++)
#pragma unroll
            for (int r = 0; r < 4; r++) acc[i][j][r] = 0.f;

    // ---- async tile loader ----
    auto load_tile = [&](int st, int k0) {
#pragma unroll
        for (int s = 0; s < 2; s++) {
            int c = tid + s * 256;          // 0..511
            int row = c >> 2, cc = (c & 3) * 8;
            size_t g = (size_t)(m0 + row) * K + k0 + cc;
            uint32_t d = (uint32_t)(row * AST + cc) * 2;
            cpa16(base + offAh(st) + d, Ah + g);
            cpa16(base + offAl(st) + d, Al + g);
        }
#pragma unroll
        for (int s = 0; s < 2; s++) {
            int c = tid + s * 256;
            int row = c >> 4, cc = (c & 15) * 8;
            size_t g = (size_t)(k0 + row) * N + n0 + cc;
            uint32_t d = (uint32_t)(row * BST + cc) * 2;
            cpa16(base + offBh(st) + d, Bh + g);
            cpa16(base + offBl(st) + d, Bl + g);
        }
        cpa_commit();
    };

    auto compute_tile = [&](int st) {
        const uint32_t sAh = base + offAh(st), sAl = base + offAl(st);
        const uint32_t sBh = base + offBh(st), sBl = base + offBl(st);
#pragma unroll
        for (int ks = 0; ks < 2; ks++) {
            uint32_t bh[4][2], bl[4][2];
#pragma unroll
            for (int nf2 = 0; nf2 < 2; nf2++) {
                int row = ks * 16 + (l & 7) + ((l >> 3) & 1) * 8;
                int col = wn + nf2 * 16 + (l >> 4) * 8;
                uint32_t off = (uint32_t)(row * BST + col) * 2;
                ldsmx4t(bh[nf2 * 2][0], bh[nf2 * 2][1], bh[nf2 * 2 + 1][0], bh[nf2 * 2 + 1][1], sBh + off);
                ldsmx4t(bl[nf2 * 2][0], bl[nf2 * 2][1], bl[nf2 * 2 + 1][0], bl[nf2 * 2 + 1][1], sBl + off);
            }
#pragma unroll
            for (int mf = 0; mf < 4; mf++) {
                int row = wm + mf * 16 + (l & 7) + ((l >> 3) & 1) * 8;
                int col = ks * 16 + (l >> 4) * 8;
                uint32_t off = (uint32_t)(row * AST + col) * 2;
                uint32_t ah[4], al[4];
                ldsmx4(ah[0], ah[1], ah[2], ah[3], sAh + off);
                ldsmx4(al[0], al[1], al[2], al[3], sAl + off);
#pragma unroll
                for (int nf = 0; nf < 4; nf++) {
                    mma_bf16(acc[mf][nf], ah, bh[nf]);
                    mma_bf16(acc[mf][nf], ah, bl[nf]);
                    mma_bf16(acc[mf][nf], al, bh[nf]);
                }
            }
        }
    };

    const int NT = K / 32;
    load_tile(0, 0);
    for (int t = 0; t < NT; t++) {
        if (t + 1 < NT) {
            load_tile((t + 1) & 1, (t + 1) * 32);
            cpa_wait<1>();
        } else {
            cpa_wait<0>();
        }
        __syncthreads();
        compute_tile(t & 1);
        __syncthreads();
    }

    // ---- epilogue ----
#pragma unroll
    for (int mf = 0; mf < 4; mf++) {
        int r0 = m0 + wm + mf * 16 + (l >> 2);
#pragma unroll
        for (int nf = 0; nf < 4; nf++) {
            int col = n0 + wn + nf * 8 + (l & 3) * 2;
            float bx = bias[col], by = bias[col + 1];
            float2 o0 = make_float2(acc[mf][nf][0] + bx, acc[mf][nf][1] + by);
            float2 o1 = make_float2(acc[mf][nf][2] + bx, acc[mf][nf][3] + by);
            if (GELU) {
                o0.x = gelu_tanh(o0.x); o0.y = gelu_tanh(o0.y);
                o1.x = gelu_tanh(o1.x); o1.y = gelu_tanh(o1.y);
            }
            if (RES) {
                float2 ra = *(const float2*)(res + (size_t)r0 * N + col);
                float2 rb = *(const float2*)(res + (size_t)(r0 + 8) * N + col);
                o0.x += ra.x; o0.y += ra.y;
                o1.x += rb.x; o1.y += rb.y;
            }
            size_t i0 = (size_t)r0 * N + col;
            size_t i1 = (size_t)(r0 + 8) * N + col;
            if (WF32) {
                *(float2*)(Cf + i0) = o0;
                *(float2*)(Cf + i1) = o1;
            }
            if (WSPLIT) {
                bf16 h0, l0h, h1, l1h, h2, l2h, h3, l3h;
                split1(o0.x, h0, l0h); split1(o0.y, h1, l1h);
                split1(o1.x, h2, l2h); split1(o1.y, h3, l3h);
                *(__nv_bfloat162*)(Ch + i0) = __halves2bfloat162(h0, h1);
                *(__nv_bfloat162*)(Cl + i0) = __halves2bfloat162(l0h, l1h);
                *(__nv_bfloat162*)(Ch + i1) = __halves2bfloat162(h2, h3);
                *(__nv_bfloat162*)(Cl + i1) = __halves2bfloat162(l2h, l3h);
            }
        }
    }
}

// ---------------------------------------------------------------------------
// LayerNorm + sinusoidal PE -> fp32 + split planes
// ---------------------------------------------------------------------------
__global__ void ln_pe_kernel(const float* __restrict__ x,
                             const float* __restrict__ gamma,
                             const float* __restrict__ beta,
                             float* __restrict__ outf,
                             bf16* __restrict__ outh, bf16* __restrict__ outl)
{
    const int row = blockIdx.x;
    const int tid = threadIdx.x;
    const float* xr = x + (size_t)row * DMODEL;

    float v0 = xr[tid], v1 = xr[tid + 256], v2 = xr[tid + 512];

    __shared__ float red[8];

    float s = v0 + v1 + v2;
#pragma unroll
    for (int o = 16; o > 0; o >>= 1) s += __shfl_xor_sync(0xffffffffu, s, o);
    if ((tid & 31) == 0) red[tid >> 5] = s;
    __syncthreads();
    float tot = red[0] + red[1] + red[2] + red[3] + red[4] + red[5] + red[6] + red[7];
    const float mean = tot / (float)DMODEL;
    __syncthreads();

    float d0 = v0 - mean, d1 = v1 - mean, d2 = v2 - mean;

    float sq = d0 * d0 + d1 * d1 + d2 * d2;
#pragma unroll
    for (int o = 16; o > 0; o >>= 1) sq += __shfl_xor_sync(0xffffffffu, sq, o);
    if ((tid & 31) == 0) red[tid >> 5] = sq;
    __syncthreads();
    float tot2 = red[0] + red[1] + red[2] + red[3] + red[4] + red[5] + red[6] + red[7];
    const float inv = rsqrtf(tot2 / (float)DMODEL + 1e-5f);

    const float n = (float)(row & (NTOK - 1));
    const float dv[3] = {d0, d1, d2};
    size_t rbase = (size_t)row * DMODEL;
#pragma unroll
    for (int j = 0; j < 3; j++) {
        int d = tid + j * 256;
        float freq = expf((float)(d & ~1) * (-9.210340371976184f / (float)DMODEL));
        float ang = n * freq;
        float pe = (d & 1) ? cosf(ang) : sinf(ang);
        float val = dv[j] * inv * gamma[d] + beta[d] + pe;
        outf[rbase + d] = val;
        bf16 hi, lo;
        split1(val, hi, lo);
        outh[rbase + d] = hi;
        outl[rbase + d] = lo;
    }
}

// ---------------------------------------------------------------------------
// Windowed attention -> split planes
// ---------------------------------------------------------------------------
__global__ void attn_kernel(const float* __restrict__ qkv,
                            bf16* __restrict__ outh, bf16* __restrict__ outl) {
    extern __shared__ float sm[];
    float* Qs = sm;
    float* Ks = sm + 64 * 65;
    float* Vs = sm + 2 * 64 * 65;
    float* Ss = sm + 3 * 64 * 65;

    const int blk = blockIdx.x;
    const int h = blk % NHEAD;
    const int w = (blk / NHEAD) % NWIN;
    const int b = blk / (NHEAD * NWIN);
    const int m0 = b * NTOK + w * WINSZ;
    const int tid = threadIdx.x;

    for (int idx = tid; idx < WINSZ * DHEAD; idx += 256) {
        int t = idx >> 6, d = idx & 63;
        size_t base = (size_t)(m0 + t) * QKVDIM + h * DHEAD + d;
        Qs[t * 65 + d] = qkv[base];
        Ks[t * 65 + d] = qkv[base + DMODEL];
        Vs[t * 65 + d] = qkv[base + 2 * DMODEL];
    }
    __syncthreads();

    for (int idx = tid; idx < WINSZ * WINSZ; idx += 256) {
        int q = idx >> 6, k = idx & 63;
        float s = 0.f;
#pragma unroll
        for (int i = 0; i < DHEAD; i++) s = fmaf(Qs[q * 65 + i], Ks[k * 65 + i], s);
        Ss[q * 65 + k] = s * 0.125f;
    }
    __syncthreads();

    if (tid < WINSZ) {
        float mx = -1e30f;
#pragma unroll 8
        for (int k = 0; k < WINSZ; k++) mx = fmaxf(mx, Ss[tid * 65 + k]);
        float sum = 0.f;
#pragma unroll 8
        for (int k = 0; k < WINSZ; k++) {
            float e = expf(Ss[tid * 65 + k] - mx);
            Ss[tid * 65 + k] = e;
            sum += e;
        }
        float invs = 1.f / sum;
#pragma unroll 8
        for (int k = 0; k < WINSZ; k++) Ss[tid * 65 + k] *= invs;
    }
    __syncthreads();

    for (int idx = tid; idx < WINSZ * DHEAD; idx += 256) {
        int q = idx >> 6, d = idx & 63;
        float o = 0.f;
#pragma unroll
        for (int k = 0; k < WINSZ; k++) o = fmaf(Ss[q * 65 + k], Vs[k * 65 + d], o);
        size_t oi = (size_t)(m0 + q) * DMODEL + h * DHEAD + d;
        bf16 hi, lo;
        split1(o, hi, lo);
        outh[oi] = hi;
        outl[oi] = lo;
    }
}

// ---------------------------------------------------------------------------
// Launch pipeline
// ---------------------------------------------------------------------------
extern "C" void kernel_launch(void* const* d_in, const int* in_sizes, int n_in,
                              void* d_out, int out_size)
{
    const float* input   = (const float*)d_in[0];
    const float* patch_w = (const float*)d_in[1];
    const float* patch_b = (const float*)d_in[2];
    const float* ln_g    = (const float*)d_in[3];
    const float* ln_b    = (const float*)d_in[4];
    const float* qkv_w   = (const float*)d_in[5];
    const float* qkv_b   = (const float*)d_in[6];
    const float* proj_w  = (const float*)d_in[7];
    const float* proj_b  = (const float*)d_in[8];
    const float* ff1_w   = (const float*)d_in[9];
    const float* ff1_b   = (const float*)d_in[10];
    const float* ff2_w   = (const float*)d_in[11];
    const float* ff2_b   = (const float*)d_in[12];
    float* out = (float*)d_out;

    // resolve scratch addresses
    bf16 *Ah0, *Al0, *wTh, *wTl, *qkvWh, *qkvWl, *projWh, *projWl, *ff1Wh, *ff1Wl, *ff2Wh, *ff2Wl;
    bf16 *x0h, *x0l, *hh, *hl, *yh, *yl, *attnh, *attnl, *x2h, *x2l;
    float *y, *x0, *qkvb, *x2;
    cudaGetSymbolAddress((void**)&Ah0, g_Ah0);   cudaGetSymbolAddress((void**)&Al0, g_Al0);
    cudaGetSymbolAddress((void**)&wTh, g_wTh);   cudaGetSymbolAddress((void**)&wTl, g_wTl);
    cudaGetSymbolAddress((void**)&qkvWh, g_qkvWh); cudaGetSymbolAddress((void**)&qkvWl, g_qkvWl);
    cudaGetSymbolAddress((void**)&projWh, g_projWh); cudaGetSymbolAddress((void**)&projWl, g_projWl);
    cudaGetSymbolAddress((void**)&ff1Wh, g_ff1Wh); cudaGetSymbolAddress((void**)&ff1Wl, g_ff1Wl);
    cudaGetSymbolAddress((void**)&ff2Wh, g_ff2Wh); cudaGetSymbolAddress((void**)&ff2Wl, g_ff2Wl);
    cudaGetSymbolAddress((void**)&x0h, g_x0h);   cudaGetSymbolAddress((void**)&x0l, g_x0l);
    cudaGetSymbolAddress((void**)&hh, g_hh);     cudaGetSymbolAddress((void**)&hl, g_hl);
    cudaGetSymbolAddress((void**)&yh, g_yh);     cudaGetSymbolAddress((void**)&yl, g_yl);
    cudaGetSymbolAddress((void**)&attnh, g_attnh); cudaGetSymbolAddress((void**)&attnl, g_attnl);
    cudaGetSymbolAddress((void**)&x2h, g_x2h);   cudaGetSymbolAddress((void**)&x2l, g_x2l);
    cudaGetSymbolAddress((void**)&y, g_y);
    cudaGetSymbolAddress((void**)&x0, g_x0);
    cudaGetSymbolAddress((void**)&qkvb, g_qkv);
    cudaGetSymbolAddress((void**)&x2, g_x2);

    const int ATTN_SMEM = 4 * 64 * 65 * sizeof(float);
    cudaFuncSetAttribute(attn_kernel, cudaFuncAttributeMaxDynamicSharedMemorySize, ATTN_SMEM);
    cudaFuncSetAttribute(mma_gemm<false, false, true, false>, cudaFuncAttributeMaxDynamicSharedMemorySize, GEMM_SMEM);
    cudaFuncSetAttribute(mma_gemm<true, false, false, true>, cudaFuncAttributeMaxDynamicSharedMemorySize, GEMM_SMEM);
    cudaFuncSetAttribute(mma_gemm<false, false, false, true>, cudaFuncAttributeMaxDynamicSharedMemorySize, GEMM_SMEM);
    cudaFuncSetAttribute(mma_gemm<false, true, true, true>, cudaFuncAttributeMaxDynamicSharedMemorySize, GEMM_SMEM);
    cudaFuncSetAttribute(mma_gemm<false, true, true, false>, cudaFuncAttributeMaxDynamicSharedMemorySize, GEMM_SMEM);

    // --- producers ---
    {
        size_t total = (size_t)MTOT * DMODEL;
        im2col_split_kernel<<<(unsigned)((total + 255) / 256), 256>>>(input);
    }
    pack_wT_split_kernel<<<(DMODEL * DMODEL + 255) / 256, 256>>>(patch_w);
    convert_split_kernel<<<(DMODEL * QKVDIM + 255) / 256, 256>>>(qkv_w, qkvWh, qkvWl, DMODEL * QKVDIM);
    convert_split_kernel<<<(DMODEL * DMODEL + 255) / 256, 256>>>(proj_w, projWh, projWl, DMODEL * DMODEL);
    convert_split_kernel<<<(DMODEL * FDIM + 255) / 256, 256>>>(ff1_w, ff1Wh, ff1Wl, DMODEL * FDIM);
    convert_split_kernel<<<(DMODEL * FDIM + 255) / 256, 256>>>(ff2_w, ff2Wh, ff2Wl, DMODEL * FDIM);

    dim3 gD(DMODEL / 128, MTOT / 128);
    dim3 gF(FDIM / 128, MTOT / 128);
    dim3 gQ(QKVDIM / 128, MTOT / 128);

    // patch embed -> fp32 y
    mma_gemm<false, false, true, false><<<gD, 256, GEMM_SMEM>>>(
        Ah0, Al0, wTh, wTl, patch_b, nullptr, y, nullptr, nullptr, MTOT, DMODEL, DMODEL);
    // LN + PE -> x0 fp32 + planes
    ln_pe_kernel<<<MTOT, 256>>>(y, ln_g, ln_b, x0, x0h, x0l);

    // ff1 + gelu -> h planes
    mma_gemm<true, false, false, true><<<gF, 256, GEMM_SMEM>>>(
        x0h, x0l, ff1Wh, ff1Wl, ff1_b, nullptr, nullptr, hh, hl, MTOT, FDIM, DMODEL);
    // ff2 -> y planes (qkv input)
    mma_gemm<false, false, false, true><<<gD, 256, GEMM_SMEM>>>(
        hh, hl, ff2Wh, ff2Wl, ff2_b, nullptr, nullptr, yh, yl, MTOT, DMODEL, FDIM);
    // qkv -> fp32
    mma_gemm<false, false, true, false><<<gQ, 256, GEMM_SMEM>>>(
        yh, yl, qkvWh, qkvWl, qkv_b, nullptr, qkvb, nullptr, nullptr, MTOT, QKVDIM, DMODEL);
    // attention -> planes
    attn_kernel<<<BATCH * NWIN * NHEAD, 256, ATTN_SMEM>>>(qkvb, attnh, attnl);

    // proj + residual(x0) -> x2 fp32 + planes
    mma_gemm<false, true, true, true><<<gD, 256, GEMM_SMEM>>>(
        attnh, attnl, projWh, projWl, proj_b, x0, x2, x2h, x2l, MTOT, DMODEL, DMODEL);
    // ff1 + gelu -> h planes
    mma_gemm<true, false, false, true><<<gF, 256, GEMM_SMEM>>>(
        x2h, x2l, ff1Wh, ff1Wl, ff1_b, nullptr, nullptr, hh, hl, MTOT, FDIM, DMODEL);
    // ff2 + residual(x2) -> d_out
    mma_gemm<false, true, true, false><<<gD, 256, GEMM_SMEM>>>(
        hh, hl, ff2Wh, ff2Wl, ff2_b, x2, out, nullptr, nullptr, MTOT, DMODEL, FDIM);
}

// round 6
// speedup vs baseline: 2.3058x; 1.0688x over previous
#include <cuda_runtime.h>
#include <cuda_bf16.h>
#include <math.h>
#include <stdint.h>

// ---------------------------------------------------------------------------
// Problem constants
// ---------------------------------------------------------------------------
#define BATCH 16
#define CH 3
#define IMG 512
#define PATCH 16
#define NTOK 1024
#define MTOT (BATCH * NTOK)    // 16384
#define DMODEL 768
#define FDIM 3072
#define QKVDIM 2304
#define NHEAD 12
#define DHEAD 64
#define WINSZ 64
#define NWIN 16

typedef __nv_bfloat16 bf16;

// ---------------------------------------------------------------------------
// Static device scratch: split bf16 hi/lo planes + fp32 where needed
// Weights stored [K][N] (natural layout), loaded with trans ldmatrix.
// ---------------------------------------------------------------------------
__device__ bf16 g_Ah0[(size_t)MTOT * DMODEL];   // im2col planes [M][K]
__device__ bf16 g_Al0[(size_t)MTOT * DMODEL];
__device__ bf16 g_wTh[(size_t)DMODEL * DMODEL]; // patch weight T [k][d]
__device__ bf16 g_wTl[(size_t)DMODEL * DMODEL];
__device__ bf16 g_qkvWh[(size_t)DMODEL * QKVDIM];
__device__ bf16 g_qkvWl[(size_t)DMODEL * QKVDIM];
__device__ bf16 g_projWh[(size_t)DMODEL * DMODEL];
__device__ bf16 g_projWl[(size_t)DMODEL * DMODEL];
__device__ bf16 g_ff1Wh[(size_t)DMODEL * FDIM];
__device__ bf16 g_ff1Wl[(size_t)DMODEL * FDIM];
__device__ bf16 g_ff2Wh[(size_t)FDIM * DMODEL];
__device__ bf16 g_ff2Wl[(size_t)FDIM * DMODEL];

__device__ float g_y[(size_t)MTOT * DMODEL];    // patch-GEMM out (fp32)
__device__ float g_x0[(size_t)MTOT * DMODEL];   // identity 1 fp32
__device__ bf16  g_x0h[(size_t)MTOT * DMODEL];
__device__ bf16  g_x0l[(size_t)MTOT * DMODEL];
__device__ bf16  g_hh[(size_t)MTOT * FDIM];     // ff hidden planes
__device__ bf16  g_hl[(size_t)MTOT * FDIM];
__device__ bf16  g_yh[(size_t)MTOT * DMODEL];   // ff2 out planes (qkv input)
__device__ bf16  g_yl[(size_t)MTOT * DMODEL];
__device__ float g_qkv[(size_t)MTOT * QKVDIM];
__device__ bf16  g_attnh[(size_t)MTOT * DMODEL];
__device__ bf16  g_attnl[(size_t)MTOT * DMODEL];
__device__ float g_x2[(size_t)MTOT * DMODEL];   // identity 2 fp32
__device__ bf16  g_x2h[(size_t)MTOT * DMODEL];
__device__ bf16  g_x2l[(size_t)MTOT * DMODEL];

// ---------------------------------------------------------------------------
// Helpers
// ---------------------------------------------------------------------------
__device__ __forceinline__ void split1(float x, bf16& hi, bf16& lo) {
    hi = __float2bfloat16(x);
    lo = __float2bfloat16(x - __bfloat162float(hi));
}
__device__ __forceinline__ float gelu_tanh(float x) {
    float x3 = x * x * x;
    return 0.5f * x * (1.0f + tanhf(0.7978845608028654f * (x + 0.044715f * x3)));
}
__device__ __forceinline__ uint32_t smem_u32(const void* p) {
    return (uint32_t)__cvta_generic_to_shared(p);
}
__device__ __forceinline__ void cpa16(uint32_t dst, const void* src) {
    asm volatile("cp.async.cg.shared.global [%0], [%1], 16;" :: "r"(dst), "l"(src) : "memory");
}
__device__ __forceinline__ void cpa_commit() {
    asm volatile("cp.async.commit_group;" ::: "memory");
}
template <int N>
__device__ __forceinline__ void cpa_wait() {
    asm volatile("cp.async.wait_group %0;" :: "n"(N) : "memory");
}
__device__ __forceinline__ void ldsmx4(uint32_t& r0, uint32_t& r1, uint32_t& r2, uint32_t& r3, uint32_t a) {
    asm volatile("ldmatrix.sync.aligned.m8n8.x4.shared.b16 {%0,%1,%2,%3},[%4];"
                 : "=r"(r0), "=r"(r1), "=r"(r2), "=r"(r3) : "r"(a));
}
__device__ __forceinline__ void ldsmx4t(uint32_t& r0, uint32_t& r1, uint32_t& r2, uint32_t& r3, uint32_t a) {
    asm volatile("ldmatrix.sync.aligned.m8n8.x4.trans.shared.b16 {%0,%1,%2,%3},[%4];"
                 : "=r"(r0), "=r"(r1), "=r"(r2), "=r"(r3) : "r"(a));
}
__device__ __forceinline__ void mma_bf16(float* d, const uint32_t* a, const uint32_t* b) {
    asm volatile("mma.sync.aligned.m16n8k16.row.col.f32.bf16.bf16.f32 "
                 "{%0,%1,%2,%3},{%4,%5,%6,%7},{%8,%9},{%0,%1,%2,%3};"
                 : "+f"(d[0]), "+f"(d[1]), "+f"(d[2]), "+f"(d[3])
                 : "r"(a[0]), "r"(a[1]), "r"(a[2]), "r"(a[3]), "r"(b[0]), "r"(b[1]));
}

// ---------------------------------------------------------------------------
// Producers
// ---------------------------------------------------------------------------
__global__ void im2col_split_kernel(const float* __restrict__ in) {
    size_t idx = (size_t)blockIdx.x * blockDim.x + threadIdx.x;
    size_t total = (size_t)MTOT * DMODEL;
    if (idx >= total) return;
    int k = (int)(idx % DMODEL);
    int m = (int)(idx / DMODEL);
    int q = k & 15;
    int p = (k >> 4) & 15;
    int c = k >> 8;
    int wp = m & 31;
    int hp = (m >> 5) & 31;
    int b = m >> 10;
    size_t src = (((size_t)(b * CH + c) * IMG) + (hp * PATCH + p)) * IMG + (wp * PATCH + q);
    bf16 hi, lo;
    split1(in[src], hi, lo);
    g_Ah0[idx] = hi;
    g_Al0[idx] = lo;
}

__global__ void pack_wT_split_kernel(const float* __restrict__ pw) {
    int idx = blockIdx.x * blockDim.x + threadIdx.x;
    if (idx >= DMODEL * DMODEL) return;
    int d = idx % DMODEL;
    int k = idx / DMODEL;
    bf16 hi, lo;
    split1(pw[(size_t)d * DMODEL + k], hi, lo);
    g_wTh[idx] = hi;
    g_wTl[idx] = lo;
}

__global__ void convert_split_kernel(const float* __restrict__ src,
                                     bf16* __restrict__ hi_p, bf16* __restrict__ lo_p, int n) {
    int idx = blockIdx.x * blockDim.x + threadIdx.x;
    if (idx >= n) return;
    bf16 hi, lo;
    split1(src[idx], hi, lo);
    hi_p[idx] = hi;
    lo_p[idx] = lo;
}

// ---------------------------------------------------------------------------
// Tensor-core GEMM on pre-split planes. Block 128x256, BK=32, 8 warps
// (warp tile 64x64), cp.async double-buffered. 3 MMAs per fp32 product.
// ---------------------------------------------------------------------------
#define AST 40    // As row stride (bf16): 32 + 8 pad
#define BST 264   // Bs row stride: 256 + 8 pad
#define A_BYTES (128 * AST * 2)    // 10240
#define B_BYTES (32 * BST * 2)     // 16896
#define STAGE_BYTES (2 * A_BYTES + 2 * B_BYTES)   // 54272
#define GEMM_SMEM (2 * STAGE_BYTES)               // 108544

template <bool GELU, bool RES, bool WF32, bool WSPLIT>
__global__ __launch_bounds__(256, 1) void mma_gemm(
    const bf16* __restrict__ Ah, const bf16* __restrict__ Al,
    const bf16* __restrict__ Bh, const bf16* __restrict__ Bl,
    const float* __restrict__ bias, const float* __restrict__ res,
    float* __restrict__ Cf, bf16* __restrict__ Ch, bf16* __restrict__ Cl,
    int M, int N, int K)
{
    extern __shared__ char dsm[];
    const uint32_t base = smem_u32(dsm);
    auto offAh = [&](int st) { return (uint32_t)(st * STAGE_BYTES); };
    auto offAl = [&](int st) { return (uint32_t)(st * STAGE_BYTES + A_BYTES); };
    auto offBh = [&](int st) { return (uint32_t)(st * STAGE_BYTES + 2 * A_BYTES); };
    auto offBl = [&](int st) { return (uint32_t)(st * STAGE_BYTES + 2 * A_BYTES + B_BYTES); };

    const int tid = threadIdx.x;
    const int l = tid & 31;
    const int w = tid >> 5;
    const int wm = (w & 1) * 64;     // 2 warps in M
    const int wn = (w >> 1) * 64;    // 4 warps in N
    const int m0 = blockIdx.y * 128;
    const int n0 = blockIdx.x * 256;

    float acc[4][8][4];
#pragma unroll
    for (int i = 0; i < 4; i++)
#pragma unroll
        for (int j = 0; j < 8; j++)
#pragma unroll
            for (int r = 0; r < 4; r++) acc[i][j][r] = 0.f;

    // ---- async tile loader ----
    auto load_tile = [&](int st, int k0) {
        // A: 128 rows x 32 cols (bf16), 512 16B-lanes per plane
#pragma unroll
        for (int s = 0; s < 2; s++) {
            int c = tid + s * 256;
            int row = c >> 2, cc = (c & 3) * 8;
            size_t g = (size_t)(m0 + row) * K + k0 + cc;
            uint32_t d = (uint32_t)(row * AST + cc) * 2;
            cpa16(base + offAh(st) + d, Ah + g);
            cpa16(base + offAl(st) + d, Al + g);
        }
        // B: 32 rows x 256 cols, 1024 lanes per plane
#pragma unroll
        for (int s = 0; s < 4; s++) {
            int c = tid + s * 256;
            int row = c >> 5, cc = (c & 31) * 8;
            size_t g = (size_t)(k0 + row) * N + n0 + cc;
            uint32_t d = (uint32_t)(row * BST + cc) * 2;
            cpa16(base + offBh(st) + d, Bh + g);
            cpa16(base + offBl(st) + d, Bl + g);
        }
        cpa_commit();
    };

    auto compute_tile = [&](int st) {
        const uint32_t sAh = base + offAh(st), sAl = base + offAl(st);
        const uint32_t sBh = base + offBh(st), sBl = base + offBl(st);
#pragma unroll
        for (int ks = 0; ks < 2; ks++) {
            // A fragments for this ks: 4 m-frags, hi+lo
            uint32_t ah[4][4], al[4][4];
#pragma unroll
            for (int mf = 0; mf < 4; mf++) {
                int row = wm + mf * 16 + (l & 7) + ((l >> 3) & 1) * 8;
                int col = ks * 16 + (l >> 4) * 8;
                uint32_t off = (uint32_t)(row * AST + col) * 2;
                ldsmx4(ah[mf][0], ah[mf][1], ah[mf][2], ah[mf][3], sAh + off);
                ldsmx4(al[mf][0], al[mf][1], al[mf][2], al[mf][3], sAl + off);
            }
#pragma unroll
            for (int nf2 = 0; nf2 < 4; nf2++) {
                uint32_t bh[4], bl[4];
                int row = ks * 16 + (l & 7) + ((l >> 3) & 1) * 8;
                int col = wn + nf2 * 16 + (l >> 4) * 8;
                uint32_t off = (uint32_t)(row * BST + col) * 2;
                ldsmx4t(bh[0], bh[1], bh[2], bh[3], sBh + off);
                ldsmx4t(bl[0], bl[1], bl[2], bl[3], sBl + off);
#pragma unroll
                for (int mf = 0; mf < 4; mf++) {
                    mma_bf16(acc[mf][nf2 * 2 + 0], ah[mf], bh + 0);
                    mma_bf16(acc[mf][nf2 * 2 + 0], ah[mf], bl + 0);
                    mma_bf16(acc[mf][nf2 * 2 + 0], al[mf], bh + 0);
                    mma_bf16(acc[mf][nf2 * 2 + 1], ah[mf], bh + 2);
                    mma_bf16(acc[mf][nf2 * 2 + 1], ah[mf], bl + 2);
                    mma_bf16(acc[mf][nf2 * 2 + 1], al[mf], bh + 2);
                }
            }
        }
    };

    const int NT = K / 32;
    load_tile(0, 0);
    for (int t = 0; t < NT; t++) {
        if (t + 1 < NT) {
            load_tile((t + 1) & 1, (t + 1) * 32);
            cpa_wait<1>();
        } else {
            cpa_wait<0>();
        }
        __syncthreads();
        compute_tile(t & 1);
        __syncthreads();
    }

    // ---- epilogue ----
#pragma unroll
    for (int mf = 0; mf < 4; mf++) {
        int r0 = m0 + wm + mf * 16 + (l >> 2);
#pragma unroll
        for (int nf = 0; nf < 8; nf++) {
            int col = n0 + wn + nf * 8 + (l & 3) * 2;
            float bx = bias[col], by = bias[col + 1];
            float2 o0 = make_float2(acc[mf][nf][0] + bx, acc[mf][nf][1] + by);
            float2 o1 = make_float2(acc[mf][nf][2] + bx, acc[mf][nf][3] + by);
            if (GELU) {
                o0.x = gelu_tanh(o0.x); o0.y = gelu_tanh(o0.y);
                o1.x = gelu_tanh(o1.x); o1.y = gelu_tanh(o1.y);
            }
            if (RES) {
                float2 ra = *(const float2*)(res + (size_t)r0 * N + col);
                float2 rb = *(const float2*)(res + (size_t)(r0 + 8) * N + col);
                o0.x += ra.x; o0.y += ra.y;
                o1.x += rb.x; o1.y += rb.y;
            }
            size_t i0 = (size_t)r0 * N + col;
            size_t i1 = (size_t)(r0 + 8) * N + col;
            if (WF32) {
                *(float2*)(Cf + i0) = o0;
                *(float2*)(Cf + i1) = o1;
            }
            if (WSPLIT) {
                bf16 h0, l0h, h1, l1h, h2, l2h, h3, l3h;
                split1(o0.x, h0, l0h); split1(o0.y, h1, l1h);
                split1(o1.x, h2, l2h); split1(o1.y, h3, l3h);
                *(__nv_bfloat162*)(Ch + i0) = __halves2bfloat162(h0, h1);
                *(__nv_bfloat162*)(Cl + i0) = __halves2bfloat162(l0h, l1h);
                *(__nv_bfloat162*)(Ch + i1) = __halves2bfloat162(h2, h3);
                *(__nv_bfloat162*)(Cl + i1) = __halves2bfloat162(l2h, l3h);
            }
        }
    }
}

// ---------------------------------------------------------------------------
// LayerNorm + sinusoidal PE -> fp32 + split planes
// ---------------------------------------------------------------------------
__global__ void ln_pe_kernel(const float* __restrict__ x,
                             const float* __restrict__ gamma,
                             const float* __restrict__ beta,
                             float* __restrict__ outf,
                             bf16* __restrict__ outh, bf16* __restrict__ outl)
{
    const int row = blockIdx.x;
    const int tid = threadIdx.x;
    const float* xr = x + (size_t)row * DMODEL;

    float v0 = xr[tid], v1 = xr[tid + 256], v2 = xr[tid + 512];

    __shared__ float red[8];

    float s = v0 + v1 + v2;
#pragma unroll
    for (int o = 16; o > 0; o >>= 1) s += __shfl_xor_sync(0xffffffffu, s, o);
    if ((tid & 31) == 0) red[tid >> 5] = s;
    __syncthreads();
    float tot = red[0] + red[1] + red[2] + red[3] + red[4] + red[5] + red[6] + red[7];
    const float mean = tot / (float)DMODEL;
    __syncthreads();

    float d0 = v0 - mean, d1 = v1 - mean, d2 = v2 - mean;

    float sq = d0 * d0 + d1 * d1 + d2 * d2;
#pragma unroll
    for (int o = 16; o > 0; o >>= 1) sq += __shfl_xor_sync(0xffffffffu, sq, o);
    if ((tid & 31) == 0) red[tid >> 5] = sq;
    __syncthreads();
    float tot2 = red[0] + red[1] + red[2] + red[3] + red[4] + red[5] + red[6] + red[7];
    const float inv = rsqrtf(tot2 / (float)DMODEL + 1e-5f);

    const float n = (float)(row & (NTOK - 1));
    const float dv[3] = {d0, d1, d2};
    size_t rbase = (size_t)row * DMODEL;
#pragma unroll
    for (int j = 0; j < 3; j++) {
        int d = tid + j * 256;
        float freq = expf((float)(d & ~1) * (-9.210340371976184f / (float)DMODEL));
        float ang = n * freq;
        float pe = (d & 1) ? cosf(ang) : sinf(ang);
        float val = dv[j] * inv * gamma[d] + beta[d] + pe;
        outf[rbase + d] = val;
        bf16 hi, lo;
        split1(val, hi, lo);
        outh[rbase + d] = hi;
        outl[rbase + d] = lo;
    }
}

// ---------------------------------------------------------------------------
// Windowed attention -> split planes
// ---------------------------------------------------------------------------
__global__ void attn_kernel(const float* __restrict__ qkv,
                            bf16* __restrict__ outh, bf16* __restrict__ outl) {
    extern __shared__ float sm[];
    float* Qs = sm;
    float* Ks = sm + 64 * 65;
    float* Vs = sm + 2 * 64 * 65;
    float* Ss = sm + 3 * 64 * 65;

    const int blk = blockIdx.x;
    const int h = blk % NHEAD;
    const int w = (blk / NHEAD) % NWIN;
    const int b = blk / (NHEAD * NWIN);
    const int m0 = b * NTOK + w * WINSZ;
    const int tid = threadIdx.x;

    for (int idx = tid; idx < WINSZ * DHEAD; idx += 256) {
        int t = idx >> 6, d = idx & 63;
        size_t base = (size_t)(m0 + t) * QKVDIM + h * DHEAD + d;
        Qs[t * 65 + d] = qkv[base];
        Ks[t * 65 + d] = qkv[base + DMODEL];
        Vs[t * 65 + d] = qkv[base + 2 * DMODEL];
    }
    __syncthreads();

    for (int idx = tid; idx < WINSZ * WINSZ; idx += 256) {
        int q = idx >> 6, k = idx & 63;
        float s = 0.f;
#pragma unroll
        for (int i = 0; i < DHEAD; i++) s = fmaf(Qs[q * 65 + i], Ks[k * 65 + i], s);
        Ss[q * 65 + k] = s * 0.125f;
    }
    __syncthreads();

    if (tid < WINSZ) {
        float mx = -1e30f;
#pragma unroll 8
        for (int k = 0; k < WINSZ; k++) mx = fmaxf(mx, Ss[tid * 65 + k]);
        float sum = 0.f;
#pragma unroll 8
        for (int k = 0; k < WINSZ; k++) {
            float e = expf(Ss[tid * 65 + k] - mx);
            Ss[tid * 65 + k] = e;
            sum += e;
        }
        float invs = 1.f / sum;
#pragma unroll 8
        for (int k = 0; k < WINSZ; k++) Ss[tid * 65 + k] *= invs;
    }
    __syncthreads();

    for (int idx = tid; idx < WINSZ * DHEAD; idx += 256) {
        int q = idx >> 6, d = idx & 63;
        float o = 0.f;
#pragma unroll
        for (int k = 0; k < WINSZ; k++) o = fmaf(Ss[q * 65 + k], Vs[k * 65 + d], o);
        size_t oi = (size_t)(m0 + q) * DMODEL + h * DHEAD + d;
        bf16 hi, lo;
        split1(o, hi, lo);
        outh[oi] = hi;
        outl[oi] = lo;
    }
}

// ---------------------------------------------------------------------------
// Launch pipeline (ordered so ncu's captured launch #6 is the ff1 GEMM)
// ---------------------------------------------------------------------------
extern "C" void kernel_launch(void* const* d_in, const int* in_sizes, int n_in,
                              void* d_out, int out_size)
{
    const float* input   = (const float*)d_in[0];
    const float* patch_w = (const float*)d_in[1];
    const float* patch_b = (const float*)d_in[2];
    const float* ln_g    = (const float*)d_in[3];
    const float* ln_b    = (const float*)d_in[4];
    const float* qkv_w   = (const float*)d_in[5];
    const float* qkv_b   = (const float*)d_in[6];
    const float* proj_w  = (const float*)d_in[7];
    const float* proj_b  = (const float*)d_in[8];
    const float* ff1_w   = (const float*)d_in[9];
    const float* ff1_b   = (const float*)d_in[10];
    const float* ff2_w   = (const float*)d_in[11];
    const float* ff2_b   = (const float*)d_in[12];
    float* out = (float*)d_out;

    bf16 *Ah0, *Al0, *wTh, *wTl, *qkvWh, *qkvWl, *projWh, *projWl, *ff1Wh, *ff1Wl, *ff2Wh, *ff2Wl;
    bf16 *x0h, *x0l, *hh, *hl, *yh, *yl, *attnh, *attnl, *x2h, *x2l;
    float *y, *x0, *qkvb, *x2;
    cudaGetSymbolAddress((void**)&Ah0, g_Ah0);   cudaGetSymbolAddress((void**)&Al0, g_Al0);
    cudaGetSymbolAddress((void**)&wTh, g_wTh);   cudaGetSymbolAddress((void**)&wTl, g_wTl);
    cudaGetSymbolAddress((void**)&qkvWh, g_qkvWh); cudaGetSymbolAddress((void**)&qkvWl, g_qkvWl);
    cudaGetSymbolAddress((void**)&projWh, g_projWh); cudaGetSymbolAddress((void**)&projWl, g_projWl);
    cudaGetSymbolAddress((void**)&ff1Wh, g_ff1Wh); cudaGetSymbolAddress((void**)&ff1Wl, g_ff1Wl);
    cudaGetSymbolAddress((void**)&ff2Wh, g_ff2Wh); cudaGetSymbolAddress((void**)&ff2Wl, g_ff2Wl);
    cudaGetSymbolAddress((void**)&x0h, g_x0h);   cudaGetSymbolAddress((void**)&x0l, g_x0l);
    cudaGetSymbolAddress((void**)&hh, g_hh);     cudaGetSymbolAddress((void**)&hl, g_hl);
    cudaGetSymbolAddress((void**)&yh, g_yh);     cudaGetSymbolAddress((void**)&yl, g_yl);
    cudaGetSymbolAddress((void**)&attnh, g_attnh); cudaGetSymbolAddress((void**)&attnl, g_attnl);
    cudaGetSymbolAddress((void**)&x2h, g_x2h);   cudaGetSymbolAddress((void**)&x2l, g_x2l);
    cudaGetSymbolAddress((void**)&y, g_y);
    cudaGetSymbolAddress((void**)&x0, g_x0);
    cudaGetSymbolAddress((void**)&qkvb, g_qkv);
    cudaGetSymbolAddress((void**)&x2, g_x2);

    const int ATTN_SMEM = 4 * 64 * 65 * sizeof(float);
    cudaFuncSetAttribute(attn_kernel, cudaFuncAttributeMaxDynamicSharedMemorySize, ATTN_SMEM);
    cudaFuncSetAttribute(mma_gemm<false, false, true, false>, cudaFuncAttributeMaxDynamicSharedMemorySize, GEMM_SMEM);
    cudaFuncSetAttribute(mma_gemm<true, false, false, true>, cudaFuncAttributeMaxDynamicSharedMemorySize, GEMM_SMEM);
    cudaFuncSetAttribute(mma_gemm<false, false, false, true>, cudaFuncAttributeMaxDynamicSharedMemorySize, GEMM_SMEM);
    cudaFuncSetAttribute(mma_gemm<false, true, true, true>, cudaFuncAttributeMaxDynamicSharedMemorySize, GEMM_SMEM);
    cudaFuncSetAttribute(mma_gemm<false, true, true, false>, cudaFuncAttributeMaxDynamicSharedMemorySize, GEMM_SMEM);

    dim3 gD(DMODEL / 256, MTOT / 128);     // (3,128)
    dim3 gF(FDIM / 256, MTOT / 128);       // (12,128)
    dim3 gQ(QKVDIM / 256, MTOT / 128);     // (9,128)

    // 1. im2col
    {
        size_t total = (size_t)MTOT * DMODEL;
        im2col_split_kernel<<<(unsigned)((total + 255) / 256), 256>>>(input);
    }
    // 2. patch weight
    pack_wT_split_kernel<<<(DMODEL * DMODEL + 255) / 256, 256>>>(patch_w);
    // 3. ff1 weight
    convert_split_kernel<<<(DMODEL * FDIM + 255) / 256, 256>>>(ff1_w, ff1Wh, ff1Wl, DMODEL * FDIM);
    // 4. patch embed -> fp32 y
    mma_gemm<false, false, true, false><<<gD, 256, GEMM_SMEM>>>(
        Ah0, Al0, wTh, wTl, patch_b, nullptr, y, nullptr, nullptr, MTOT, DMODEL, DMODEL);
    // 5. LN + PE -> x0 fp32 + planes
    ln_pe_kernel<<<MTOT, 256>>>(y, ln_g, ln_b, x0, x0h, x0l);
    // 6. ff1 + gelu -> h planes   (PROFILED LAUNCH)
    mma_gemm<true, false, false, true><<<gF, 256, GEMM_SMEM>>>(
        x0h, x0l, ff1Wh, ff1Wl, ff1_b, nullptr, nullptr, hh, hl, MTOT, FDIM, DMODEL);
    // 7. ff2 weight
    convert_split_kernel<<<(DMODEL * FDIM + 255) / 256, 256>>>(ff2_w, ff2Wh, ff2Wl, DMODEL * FDIM);
    // 8. ff2 -> y planes
    mma_gemm<false, false, false, true><<<gD, 256, GEMM_SMEM>>>(
        hh, hl, ff2Wh, ff2Wl, ff2_b, nullptr, nullptr, yh, yl, MTOT, DMODEL, FDIM);
    // 9. qkv weight
    convert_split_kernel<<<(DMODEL * QKVDIM + 255) / 256, 256>>>(qkv_w, qkvWh, qkvWl, DMODEL * QKVDIM);
    // 10. qkv -> fp32
    mma_gemm<false, false, true, false><<<gQ, 256, GEMM_SMEM>>>(
        yh, yl, qkvWh, qkvWl, qkv_b, nullptr, qkvb, nullptr, nullptr, MTOT, QKVDIM, DMODEL);
    // 11. attention -> planes
    attn_kernel<<<BATCH * NWIN * NHEAD, 256, ATTN_SMEM>>>(qkvb, attnh, attnl);
    // 12. proj weight
    convert_split_kernel<<<(DMODEL * DMODEL + 255) / 256, 256>>>(proj_w, projWh, projWl, DMODEL * DMODEL);
    // 13. proj + residual(x0) -> x2 fp32 + planes
    mma_gemm<false, true, true, true><<<gD, 256, GEMM_SMEM>>>(
        attnh, attnl, projWh, projWl, proj_b, x0, x2, x2h, x2l, MTOT, DMODEL, DMODEL);
    // 14. ff1 + gelu -> h planes
    mma_gemm<true, false, false, true><<<gF, 256, GEMM_SMEM>>>(
        x2h, x2l, ff1Wh, ff1Wl, ff1_b, nullptr, nullptr, hh, hl, MTOT, FDIM, DMODEL);
    // 15. ff2 + residual(x2) -> d_out
    mma_gemm<false, true, true, false><<<gD, 256, GEMM_SMEM>>>(
        hh, hl, ff2Wh, ff2Wl, ff2_b, x2, out, nullptr, nullptr, MTOT, DMODEL, FDIM);
}

// round 7
// speedup vs baseline: 2.3379x; 1.0139x over previous
#include <cuda_runtime.h>
#include <cuda_bf16.h>
#include <math.h>
#include <stdint.h>

// ---------------------------------------------------------------------------
// Problem constants
// ---------------------------------------------------------------------------
#define BATCH 16
#define CH 3
#define IMG 512
#define PATCH 16
#define NTOK 1024
#define MTOT (BATCH * NTOK)    // 16384
#define DMODEL 768
#define FDIM 3072
#define QKVDIM 2304
#define NHEAD 12
#define DHEAD 64
#define WINSZ 64
#define NWIN 16

typedef __nv_bfloat16 bf16;

// ---------------------------------------------------------------------------
// Static device scratch
// ---------------------------------------------------------------------------
__device__ bf16 g_Ah0[(size_t)MTOT * DMODEL];
__device__ bf16 g_Al0[(size_t)MTOT * DMODEL];
__device__ bf16 g_wTh[(size_t)DMODEL * DMODEL];
__device__ bf16 g_wTl[(size_t)DMODEL * DMODEL];
__device__ bf16 g_qkvWh[(size_t)DMODEL * QKVDIM];
__device__ bf16 g_qkvWl[(size_t)DMODEL * QKVDIM];
__device__ bf16 g_projWh[(size_t)DMODEL * DMODEL];
__device__ bf16 g_projWl[(size_t)DMODEL * DMODEL];
__device__ bf16 g_ff1Wh[(size_t)DMODEL * FDIM];
__device__ bf16 g_ff1Wl[(size_t)DMODEL * FDIM];
__device__ bf16 g_ff2Wh[(size_t)FDIM * DMODEL];
__device__ bf16 g_ff2Wl[(size_t)FDIM * DMODEL];

__device__ float g_y[(size_t)MTOT * DMODEL];
__device__ float g_x0[(size_t)MTOT * DMODEL];
__device__ bf16  g_x0h[(size_t)MTOT * DMODEL];
__device__ bf16  g_x0l[(size_t)MTOT * DMODEL];
__device__ bf16  g_hh[(size_t)MTOT * FDIM];
__device__ bf16  g_hl[(size_t)MTOT * FDIM];
__device__ bf16  g_yh[(size_t)MTOT * DMODEL];
__device__ bf16  g_yl[(size_t)MTOT * DMODEL];
__device__ float g_qkv[(size_t)MTOT * QKVDIM];
__device__ bf16  g_attnh[(size_t)MTOT * DMODEL];
__device__ bf16  g_attnl[(size_t)MTOT * DMODEL];
__device__ float g_x2[(size_t)MTOT * DMODEL];
__device__ bf16  g_x2h[(size_t)MTOT * DMODEL];
__device__ bf16  g_x2l[(size_t)MTOT * DMODEL];

// ---------------------------------------------------------------------------
// Helpers
// ---------------------------------------------------------------------------
__device__ __forceinline__ void split1(float x, bf16& hi, bf16& lo) {
    hi = __float2bfloat16(x);
    lo = __float2bfloat16(x - __bfloat162float(hi));
}
__device__ __forceinline__ float gelu_tanh(float x) {
    float x3 = x * x * x;
    return 0.5f * x * (1.0f + tanhf(0.7978845608028654f * (x + 0.044715f * x3)));
}
__device__ __forceinline__ uint32_t smem_u32(const void* p) {
    return (uint32_t)__cvta_generic_to_shared(p);
}
__device__ __forceinline__ void cpa16(uint32_t dst, const void* src) {
    asm volatile("cp.async.cg.shared.global [%0], [%1], 16;" :: "r"(dst), "l"(src) : "memory");
}
__device__ __forceinline__ void cpa_commit() {
    asm volatile("cp.async.commit_group;" ::: "memory");
}
template <int N>
__device__ __forceinline__ void cpa_wait() {
    asm volatile("cp.async.wait_group %0;" :: "n"(N) : "memory");
}
__device__ __forceinline__ void ldsmx4(uint32_t& r0, uint32_t& r1, uint32_t& r2, uint32_t& r3, uint32_t a) {
    asm volatile("ldmatrix.sync.aligned.m8n8.x4.shared.b16 {%0,%1,%2,%3},[%4];"
                 : "=r"(r0), "=r"(r1), "=r"(r2), "=r"(r3) : "r"(a));
}
__device__ __forceinline__ void ldsmx4t(uint32_t& r0, uint32_t& r1, uint32_t& r2, uint32_t& r3, uint32_t a) {
    asm volatile("ldmatrix.sync.aligned.m8n8.x4.trans.shared.b16 {%0,%1,%2,%3},[%4];"
                 : "=r"(r0), "=r"(r1), "=r"(r2), "=r"(r3) : "r"(a));
}
__device__ __forceinline__ void mma_bf16(float* d, const uint32_t* a, const uint32_t* b) {
    asm volatile("mma.sync.aligned.m16n8k16.row.col.f32.bf16.bf16.f32 "
                 "{%0,%1,%2,%3},{%4,%5,%6,%7},{%8,%9},{%0,%1,%2,%3};"
                 : "+f"(d[0]), "+f"(d[1]), "+f"(d[2]), "+f"(d[3])
                 : "r"(a[0]), "r"(a[1]), "r"(a[2]), "r"(a[3]), "r"(b[0]), "r"(b[1]));
}

// ---------------------------------------------------------------------------
// Producers
// ---------------------------------------------------------------------------
__global__ void im2col_split_kernel(const float* __restrict__ in) {
    size_t idx = (size_t)blockIdx.x * blockDim.x + threadIdx.x;
    size_t total = (size_t)MTOT * DMODEL;
    if (idx >= total) return;
    int k = (int)(idx % DMODEL);
    int m = (int)(idx / DMODEL);
    int q = k & 15;
    int p = (k >> 4) & 15;
    int c = k >> 8;
    int wp = m & 31;
    int hp = (m >> 5) & 31;
    int b = m >> 10;
    size_t src = (((size_t)(b * CH + c) * IMG) + (hp * PATCH + p)) * IMG + (wp * PATCH + q);
    bf16 hi, lo;
    split1(in[src], hi, lo);
    g_Ah0[idx] = hi;
    g_Al0[idx] = lo;
}

__global__ void pack_wT_split_kernel(const float* __restrict__ pw) {
    int idx = blockIdx.x * blockDim.x + threadIdx.x;
    if (idx >= DMODEL * DMODEL) return;
    int d = idx % DMODEL;
    int k = idx / DMODEL;
    bf16 hi, lo;
    split1(pw[(size_t)d * DMODEL + k], hi, lo);
    g_wTh[idx] = hi;
    g_wTl[idx] = lo;
}

__global__ void convert_split_kernel(const float* __restrict__ src,
                                     bf16* __restrict__ hi_p, bf16* __restrict__ lo_p, int n) {
    int idx = blockIdx.x * blockDim.x + threadIdx.x;
    if (idx >= n) return;
    bf16 hi, lo;
    split1(src[idx], hi, lo);
    hi_p[idx] = hi;
    lo_p[idx] = lo;
}

// ---------------------------------------------------------------------------
// Tensor-core GEMM: block 128x256, BK=32, 8 warps (warp 64x64),
// 3-stage cp.async ring (1 sync/tile), plane-pass MMA ordering (32-deep ILP).
// ---------------------------------------------------------------------------
#define AST 40    // As row stride (bf16): 32 + 8 pad
#define BST 264   // Bs row stride: 256 + 8 pad
#define A_BYTES (128 * AST * 2)    // 10240
#define B_BYTES (32 * BST * 2)     // 16896
#define STAGE_BYTES (2 * A_BYTES + 2 * B_BYTES)   // 54272
#define NSTAGE 3
#define GEMM_SMEM (NSTAGE * STAGE_BYTES)          // 162816

template <bool GELU, bool RES, bool WF32, bool WSPLIT>
__global__ __launch_bounds__(256, 1) void mma_gemm(
    const bf16* __restrict__ Ah, const bf16* __restrict__ Al,
    const bf16* __restrict__ Bh, const bf16* __restrict__ Bl,
    const float* __restrict__ bias, const float* __restrict__ res,
    float* __restrict__ Cf, bf16* __restrict__ Ch, bf16* __restrict__ Cl,
    int M, int N, int K)
{
    extern __shared__ char dsm[];
    const uint32_t base = smem_u32(dsm);
    auto offAh = [&](int st) { return (uint32_t)(st * STAGE_BYTES); };
    auto offAl = [&](int st) { return (uint32_t)(st * STAGE_BYTES + A_BYTES); };
    auto offBh = [&](int st) { return (uint32_t)(st * STAGE_BYTES + 2 * A_BYTES); };
    auto offBl = [&](int st) { return (uint32_t)(st * STAGE_BYTES + 2 * A_BYTES + B_BYTES); };

    const int tid = threadIdx.x;
    const int l = tid & 31;
    const int w = tid >> 5;
    const int wm = (w & 1) * 64;
    const int wn = (w >> 1) * 64;
    const int m0 = blockIdx.y * 128;
    const int n0 = blockIdx.x * 256;

    float acc[4][8][4];
#pragma unroll
    for (int i = 0; i < 4; i++)
#pragma unroll
        for (int j = 0; j < 8; j++)
#pragma unroll
            for (int r = 0; r < 4; r++) acc[i][j][r] = 0.f;

    auto load_tile = [&](int st, int k0) {
#pragma unroll
        for (int s = 0; s < 2; s++) {
            int c = tid + s * 256;
            int row = c >> 2, cc = (c & 3) * 8;
            size_t g = (size_t)(m0 + row) * K + k0 + cc;
            uint32_t d = (uint32_t)(row * AST + cc) * 2;
            cpa16(base + offAh(st) + d, Ah + g);
            cpa16(base + offAl(st) + d, Al + g);
        }
#pragma unroll
        for (int s = 0; s < 4; s++) {
            int c = tid + s * 256;
            int row = c >> 5, cc = (c & 31) * 8;
            size_t g = (size_t)(k0 + row) * N + n0 + cc;
            uint32_t d = (uint32_t)(row * BST + cc) * 2;
            cpa16(base + offBh(st) + d, Bh + g);
            cpa16(base + offBl(st) + d, Bl + g);
        }
        cpa_commit();
    };

    auto compute_tile = [&](int st) {
        const uint32_t sAh = base + offAh(st), sAl = base + offAl(st);
        const uint32_t sBh = base + offBh(st), sBl = base + offBl(st);
#pragma unroll
        for (int ks = 0; ks < 2; ks++) {
            uint32_t ah[4][4], al[4][4], bh[8][2], bl[8][2];
            // preload all fragments for this ks
#pragma unroll
            for (int mf = 0; mf < 4; mf++) {
                int row = wm + mf * 16 + (l & 7) + ((l >> 3) & 1) * 8;
                int col = ks * 16 + (l >> 4) * 8;
                uint32_t off = (uint32_t)(row * AST + col) * 2;
                ldsmx4(ah[mf][0], ah[mf][1], ah[mf][2], ah[mf][3], sAh + off);
                ldsmx4(al[mf][0], al[mf][1], al[mf][2], al[mf][3], sAl + off);
            }
#pragma unroll
            for (int nf2 = 0; nf2 < 4; nf2++) {
                int row = ks * 16 + (l & 7) + ((l >> 3) & 1) * 8;
                int col = wn + nf2 * 16 + (l >> 4) * 8;
                uint32_t off = (uint32_t)(row * BST + col) * 2;
                ldsmx4t(bh[nf2 * 2][0], bh[nf2 * 2][1], bh[nf2 * 2 + 1][0], bh[nf2 * 2 + 1][1], sBh + off);
                ldsmx4t(bl[nf2 * 2][0], bl[nf2 * 2][1], bl[nf2 * 2 + 1][0], bl[nf2 * 2 + 1][1], sBl + off);
            }
            // plane passes: 32 independent MMAs each (RAW distance = 32)
#pragma unroll
            for (int mf = 0; mf < 4; mf++)
#pragma unroll
                for (int nf = 0; nf < 8; nf++)
                    mma_bf16(acc[mf][nf], ah[mf], bh[nf]);
#pragma unroll
            for (int mf = 0; mf < 4; mf++)
#pragma unroll
                for (int nf = 0; nf < 8; nf++)
                    mma_bf16(acc[mf][nf], ah[mf], bl[nf]);
#pragma unroll
            for (int mf = 0; mf < 4; mf++)
#pragma unroll
                for (int nf = 0; nf < 8; nf++)
                    mma_bf16(acc[mf][nf], al[mf], bh[nf]);
        }
    };

    const int NT = K / 32;
    // prologue: fill stages 0..NSTAGE-2
    load_tile(0, 0);
    load_tile(1, 32);
    for (int t = 0; t < NT; t++) {
        cpa_wait<NSTAGE - 2>();     // stage t's group complete
        __syncthreads();
        if (t + NSTAGE - 1 < NT)
            load_tile((t + NSTAGE - 1) % NSTAGE, (t + NSTAGE - 1) * 32);
        else
            cpa_commit();            // empty group keeps the count invariant
        compute_tile(t % NSTAGE);
    }

    // ---- epilogue ----
#pragma unroll
    for (int mf = 0; mf < 4; mf++) {
        int r0 = m0 + wm + mf * 16 + (l >> 2);
#pragma unroll
        for (int nf = 0; nf < 8; nf++) {
            int col = n0 + wn + nf * 8 + (l & 3) * 2;
            float bx = bias[col], by = bias[col + 1];
            float2 o0 = make_float2(acc[mf][nf][0] + bx, acc[mf][nf][1] + by);
            float2 o1 = make_float2(acc[mf][nf][2] + bx, acc[mf][nf][3] + by);
            if (GELU) {
                o0.x = gelu_tanh(o0.x); o0.y = gelu_tanh(o0.y);
                o1.x = gelu_tanh(o1.x); o1.y = gelu_tanh(o1.y);
            }
            if (RES) {
                float2 ra = *(const float2*)(res + (size_t)r0 * N + col);
                float2 rb = *(const float2*)(res + (size_t)(r0 + 8) * N + col);
                o0.x += ra.x; o0.y += ra.y;
                o1.x += rb.x; o1.y += rb.y;
            }
            size_t i0 = (size_t)r0 * N + col;
            size_t i1 = (size_t)(r0 + 8) * N + col;
            if (WF32) {
                *(float2*)(Cf + i0) = o0;
                *(float2*)(Cf + i1) = o1;
            }
            if (WSPLIT) {
                bf16 h0, l0h, h1, l1h, h2, l2h, h3, l3h;
                split1(o0.x, h0, l0h); split1(o0.y, h1, l1h);
                split1(o1.x, h2, l2h); split1(o1.y, h3, l3h);
                *(__nv_bfloat162*)(Ch + i0) = __halves2bfloat162(h0, h1);
                *(__nv_bfloat162*)(Cl + i0) = __halves2bfloat162(l0h, l1h);
                *(__nv_bfloat162*)(Ch + i1) = __halves2bfloat162(h2, h3);
                *(__nv_bfloat162*)(Cl + i1) = __halves2bfloat162(l2h, l3h);
            }
        }
    }
}

// ---------------------------------------------------------------------------
// LayerNorm + sinusoidal PE -> fp32 + split planes
// ---------------------------------------------------------------------------
__global__ void ln_pe_kernel(const float* __restrict__ x,
                             const float* __restrict__ gamma,
                             const float* __restrict__ beta,
                             float* __restrict__ outf,
                             bf16* __restrict__ outh, bf16* __restrict__ outl)
{
    const int row = blockIdx.x;
    const int tid = threadIdx.x;
    const float* xr = x + (size_t)row * DMODEL;

    float v0 = xr[tid], v1 = xr[tid + 256], v2 = xr[tid + 512];

    __shared__ float red[8];

    float s = v0 + v1 + v2;
#pragma unroll
    for (int o = 16; o > 0; o >>= 1) s += __shfl_xor_sync(0xffffffffu, s, o);
    if ((tid & 31) == 0) red[tid >> 5] = s;
    __syncthreads();
    float tot = red[0] + red[1] + red[2] + red[3] + red[4] + red[5] + red[6] + red[7];
    const float mean = tot / (float)DMODEL;
    __syncthreads();

    float d0 = v0 - mean, d1 = v1 - mean, d2 = v2 - mean;

    float sq = d0 * d0 + d1 * d1 + d2 * d2;
#pragma unroll
    for (int o = 16; o > 0; o >>= 1) sq += __shfl_xor_sync(0xffffffffu, sq, o);
    if ((tid & 31) == 0) red[tid >> 5] = sq;
    __syncthreads();
    float tot2 = red[0] + red[1] + red[2] + red[3] + red[4] + red[5] + red[6] + red[7];
    const float inv = rsqrtf(tot2 / (float)DMODEL + 1e-5f);

    const float n = (float)(row & (NTOK - 1));
    const float dv[3] = {d0, d1, d2};
    size_t rbase = (size_t)row * DMODEL;
#pragma unroll
    for (int j = 0; j < 3; j++) {
        int d = tid + j * 256;
        float freq = expf((float)(d & ~1) * (-9.210340371976184f / (float)DMODEL));
        float ang = n * freq;
        float pe = (d & 1) ? cosf(ang) : sinf(ang);
        float val = dv[j] * inv * gamma[d] + beta[d] + pe;
        outf[rbase + d] = val;
        bf16 hi, lo;
        split1(val, hi, lo);
        outh[rbase + d] = hi;
        outl[rbase + d] = lo;
    }
}

// ---------------------------------------------------------------------------
// Windowed attention -> split planes
// ---------------------------------------------------------------------------
__global__ void attn_kernel(const float* __restrict__ qkv,
                            bf16* __restrict__ outh, bf16* __restrict__ outl) {
    extern __shared__ float sm[];
    float* Qs = sm;
    float* Ks = sm + 64 * 65;
    float* Vs = sm + 2 * 64 * 65;
    float* Ss = sm + 3 * 64 * 65;

    const int blk = blockIdx.x;
    const int h = blk % NHEAD;
    const int w = (blk / NHEAD) % NWIN;
    const int b = blk / (NHEAD * NWIN);
    const int m0 = b * NTOK + w * WINSZ;
    const int tid = threadIdx.x;

    for (int idx = tid; idx < WINSZ * DHEAD; idx += 256) {
        int t = idx >> 6, d = idx & 63;
        size_t base = (size_t)(m0 + t) * QKVDIM + h * DHEAD + d;
        Qs[t * 65 + d] = qkv[base];
        Ks[t * 65 + d] = qkv[base + DMODEL];
        Vs[t * 65 + d] = qkv[base + 2 * DMODEL];
    }
    __syncthreads();

    for (int idx = tid; idx < WINSZ * WINSZ; idx += 256) {
        int q = idx >> 6, k = idx & 63;
        float s = 0.f;
#pragma unroll
        for (int i = 0; i < DHEAD; i++) s = fmaf(Qs[q * 65 + i], Ks[k * 65 + i], s);
        Ss[q * 65 + k] = s * 0.125f;
    }
    __syncthreads();

    if (tid < WINSZ) {
        float mx = -1e30f;
#pragma unroll 8
        for (int k = 0; k < WINSZ; k++) mx = fmaxf(mx, Ss[tid * 65 + k]);
        float sum = 0.f;
#pragma unroll 8
        for (int k = 0; k < WINSZ; k++) {
            float e = expf(Ss[tid * 65 + k] - mx);
            Ss[tid * 65 + k] = e;
            sum += e;
        }
        float invs = 1.f / sum;
#pragma unroll 8
        for (int k = 0; k < WINSZ; k++) Ss[tid * 65 + k] *= invs;
    }
    __syncthreads();

    for (int idx = tid; idx < WINSZ * DHEAD; idx += 256) {
        int q = idx >> 6, d = idx & 63;
        float o = 0.f;
#pragma unroll
        for (int k = 0; k < WINSZ; k++) o = fmaf(Ss[q * 65 + k], Vs[k * 65 + d], o);
        size_t oi = (size_t)(m0 + q) * DMODEL + h * DHEAD + d;
        bf16 hi, lo;
        split1(o, hi, lo);
        outh[oi] = hi;
        outl[oi] = lo;
    }
}

// ---------------------------------------------------------------------------
// Launch pipeline (launch #6 = ff1 GEMM, profiled)
// ---------------------------------------------------------------------------
extern "C" void kernel_launch(void* const* d_in, const int* in_sizes, int n_in,
                              void* d_out, int out_size)
{
    const float* input   = (const float*)d_in[0];
    const float* patch_w = (const float*)d_in[1];
    const float* patch_b = (const float*)d_in[2];
    const float* ln_g    = (const float*)d_in[3];
    const float* ln_b    = (const float*)d_in[4];
    const float* qkv_w   = (const float*)d_in[5];
    const float* qkv_b   = (const float*)d_in[6];
    const float* proj_w  = (const float*)d_in[7];
    const float* proj_b  = (const float*)d_in[8];
    const float* ff1_w   = (const float*)d_in[9];
    const float* ff1_b   = (const float*)d_in[10];
    const float* ff2_w   = (const float*)d_in[11];
    const float* ff2_b   = (const float*)d_in[12];
    float* out = (float*)d_out;

    bf16 *Ah0, *Al0, *wTh, *wTl, *qkvWh, *qkvWl, *projWh, *projWl, *ff1Wh, *ff1Wl, *ff2Wh, *ff2Wl;
    bf16 *x0h, *x0l, *hh, *hl, *yh, *yl, *attnh, *attnl, *x2h, *x2l;
    float *y, *x0, *qkvb, *x2;
    cudaGetSymbolAddress((void**)&Ah0, g_Ah0);   cudaGetSymbolAddress((void**)&Al0, g_Al0);
    cudaGetSymbolAddress((void**)&wTh, g_wTh);   cudaGetSymbolAddress((void**)&wTl, g_wTl);
    cudaGetSymbolAddress((void**)&qkvWh, g_qkvWh); cudaGetSymbolAddress((void**)&qkvWl, g_qkvWl);
    cudaGetSymbolAddress((void**)&projWh, g_projWh); cudaGetSymbolAddress((void**)&projWl, g_projWl);
    cudaGetSymbolAddress((void**)&ff1Wh, g_ff1Wh); cudaGetSymbolAddress((void**)&ff1Wl, g_ff1Wl);
    cudaGetSymbolAddress((void**)&ff2Wh, g_ff2Wh); cudaGetSymbolAddress((void**)&ff2Wl, g_ff2Wl);
    cudaGetSymbolAddress((void**)&x0h, g_x0h);   cudaGetSymbolAddress((void**)&x0l, g_x0l);
    cudaGetSymbolAddress((void**)&hh, g_hh);     cudaGetSymbolAddress((void**)&hl, g_hl);
    cudaGetSymbolAddress((void**)&yh, g_yh);     cudaGetSymbolAddress((void**)&yl, g_yl);
    cudaGetSymbolAddress((void**)&attnh, g_attnh); cudaGetSymbolAddress((void**)&attnl, g_attnl);
    cudaGetSymbolAddress((void**)&x2h, g_x2h);   cudaGetSymbolAddress((void**)&x2l, g_x2l);
    cudaGetSymbolAddress((void**)&y, g_y);
    cudaGetSymbolAddress((void**)&x0, g_x0);
    cudaGetSymbolAddress((void**)&qkvb, g_qkv);
    cudaGetSymbolAddress((void**)&x2, g_x2);

    const int ATTN_SMEM = 4 * 64 * 65 * sizeof(float);
    cudaFuncSetAttribute(attn_kernel, cudaFuncAttributeMaxDynamicSharedMemorySize, ATTN_SMEM);
    cudaFuncSetAttribute(mma_gemm<false, false, true, false>, cudaFuncAttributeMaxDynamicSharedMemorySize, GEMM_SMEM);
    cudaFuncSetAttribute(mma_gemm<true, false, false, true>, cudaFuncAttributeMaxDynamicSharedMemorySize, GEMM_SMEM);
    cudaFuncSetAttribute(mma_gemm<false, false, false, true>, cudaFuncAttributeMaxDynamicSharedMemorySize, GEMM_SMEM);
    cudaFuncSetAttribute(mma_gemm<false, true, true, true>, cudaFuncAttributeMaxDynamicSharedMemorySize, GEMM_SMEM);
    cudaFuncSetAttribute(mma_gemm<false, true, true, false>, cudaFuncAttributeMaxDynamicSharedMemorySize, GEMM_SMEM);

    dim3 gD(DMODEL / 256, MTOT / 128);     // (3,128)
    dim3 gF(FDIM / 256, MTOT / 128);       // (12,128)
    dim3 gQ(QKVDIM / 256, MTOT / 128);     // (9,128)

    // 1. im2col
    {
        size_t total = (size_t)MTOT * DMODEL;
        im2col_split_kernel<<<(unsigned)((total + 255) / 256), 256>>>(input);
    }
    // 2. patch weight
    pack_wT_split_kernel<<<(DMODEL * DMODEL + 255) / 256, 256>>>(patch_w);
    // 3. ff1 weight
    convert_split_kernel<<<(DMODEL * FDIM + 255) / 256, 256>>>(ff1_w, ff1Wh, ff1Wl, DMODEL * FDIM);
    // 4. patch embed -> fp32 y
    mma_gemm<false, false, true, false><<<gD, 256, GEMM_SMEM>>>(
        Ah0, Al0, wTh, wTl, patch_b, nullptr, y, nullptr, nullptr, MTOT, DMODEL, DMODEL);
    // 5. LN + PE -> x0 fp32 + planes
    ln_pe_kernel<<<MTOT, 256>>>(y, ln_g, ln_b, x0, x0h, x0l);
    // 6. ff1 + gelu -> h planes   (PROFILED LAUNCH)
    mma_gemm<true, false, false, true><<<gF, 256, GEMM_SMEM>>>(
        x0h, x0l, ff1Wh, ff1Wl, ff1_b, nullptr, nullptr, hh, hl, MTOT, FDIM, DMODEL);
    // 7. ff2 weight
    convert_split_kernel<<<(DMODEL * FDIM + 255) / 256, 256>>>(ff2_w, ff2Wh, ff2Wl, DMODEL * FDIM);
    // 8. ff2 -> y planes
    mma_gemm<false, false, false, true><<<gD, 256, GEMM_SMEM>>>(
        hh, hl, ff2Wh, ff2Wl, ff2_b, nullptr, nullptr, yh, yl, MTOT, DMODEL, FDIM);
    // 9. qkv weight
    convert_split_kernel<<<(DMODEL * QKVDIM + 255) / 256, 256>>>(qkv_w, qkvWh, qkvWl, DMODEL * QKVDIM);
    // 10. qkv -> fp32
    mma_gemm<false, false, true, false><<<gQ, 256, GEMM_SMEM>>>(
        yh, yl, qkvWh, qkvWl, qkv_b, nullptr, qkvb, nullptr, nullptr, MTOT, QKVDIM, DMODEL);
    // 11. attention -> planes
    attn_kernel<<<BATCH * NWIN * NHEAD, 256, ATTN_SMEM>>>(qkvb, attnh, attnl);
    // 12. proj weight
    convert_split_kernel<<<(DMODEL * DMODEL + 255) / 256, 256>>>(proj_w, projWh, projWl, DMODEL * DMODEL);
    // 13. proj + residual(x0) -> x2 fp32 + planes
    mma_gemm<false, true, true, true><<<gD, 256, GEMM_SMEM>>>(
        attnh, attnl, projWh, projWl, proj_b, x0, x2, x2h, x2l, MTOT, DMODEL, DMODEL);
    // 14. ff1 + gelu -> h planes
    mma_gemm<true, false, false, true><<<gF, 256, GEMM_SMEM>>>(
        x2h, x2l, ff1Wh, ff1Wl, ff1_b, nullptr, nullptr, hh, hl, MTOT, FDIM, DMODEL);
    // 15. ff2 + residual(x2) -> d_out
    mma_gemm<false, true, true, false><<<gD, 256, GEMM_SMEM>>>(
        hh, hl, ff2Wh, ff2Wl, ff2_b, x2, out, nullptr, nullptr, MTOT, DMODEL, FDIM);
}

// round 8
// speedup vs baseline: 2.4260x; 1.0377x over previous
#include <cuda_runtime.h>
#include <cuda_bf16.h>
#include <math.h>
#include <stdint.h>

// ---------------------------------------------------------------------------
// Problem constants
// ---------------------------------------------------------------------------
#define BATCH 16
#define CH 3
#define IMG 512
#define PATCH 16
#define NTOK 1024
#define MTOT (BATCH * NTOK)    // 16384
#define DMODEL 768
#define FDIM 3072
#define QKVDIM 2304
#define NHEAD 12
#define DHEAD 64
#define WINSZ 64
#define NWIN 16

typedef __nv_bfloat16 bf16;

// ---------------------------------------------------------------------------
// Static device scratch
// ---------------------------------------------------------------------------
__device__ bf16 g_Ah0[(size_t)MTOT * DMODEL];
__device__ bf16 g_Al0[(size_t)MTOT * DMODEL];
__device__ bf16 g_wTh[(size_t)DMODEL * DMODEL];
__device__ bf16 g_wTl[(size_t)DMODEL * DMODEL];
__device__ bf16 g_qkvWh[(size_t)DMODEL * QKVDIM];
__device__ bf16 g_qkvWl[(size_t)DMODEL * QKVDIM];
__device__ bf16 g_projWh[(size_t)DMODEL * DMODEL];
__device__ bf16 g_projWl[(size_t)DMODEL * DMODEL];
__device__ bf16 g_ff1Wh[(size_t)DMODEL * FDIM];
__device__ bf16 g_ff1Wl[(size_t)DMODEL * FDIM];
__device__ bf16 g_ff2Wh[(size_t)FDIM * DMODEL];
__device__ bf16 g_ff2Wl[(size_t)FDIM * DMODEL];

__device__ float g_y[(size_t)MTOT * DMODEL];
__device__ float g_x0[(size_t)MTOT * DMODEL];
__device__ bf16  g_x0h[(size_t)MTOT * DMODEL];
__device__ bf16  g_x0l[(size_t)MTOT * DMODEL];
__device__ bf16  g_hh[(size_t)MTOT * FDIM];
__device__ bf16  g_hl[(size_t)MTOT * FDIM];
__device__ bf16  g_yh[(size_t)MTOT * DMODEL];
__device__ bf16  g_yl[(size_t)MTOT * DMODEL];
__device__ float g_qkv[(size_t)MTOT * QKVDIM];
__device__ bf16  g_attnh[(size_t)MTOT * DMODEL];
__device__ bf16  g_attnl[(size_t)MTOT * DMODEL];
__device__ float g_x2[(size_t)MTOT * DMODEL];
__device__ bf16  g_x2h[(size_t)MTOT * DMODEL];
__device__ bf16  g_x2l[(size_t)MTOT * DMODEL];

// ---------------------------------------------------------------------------
// Helpers
// ---------------------------------------------------------------------------
__device__ __forceinline__ void split1(float x, bf16& hi, bf16& lo) {
    hi = __float2bfloat16(x);
    lo = __float2bfloat16(x - __bfloat162float(hi));
}
__device__ __forceinline__ float gelu_tanh(float x) {
    float x3 = x * x * x;
    return 0.5f * x * (1.0f + tanhf(0.7978845608028654f * (x + 0.044715f * x3)));
}
__device__ __forceinline__ uint32_t smem_u32(const void* p) {
    return (uint32_t)__cvta_generic_to_shared(p);
}
__device__ __forceinline__ void cpa16(uint32_t dst, const void* src) {
    asm volatile("cp.async.cg.shared.global [%0], [%1], 16;" :: "r"(dst), "l"(src) : "memory");
}
__device__ __forceinline__ void cpa_commit() {
    asm volatile("cp.async.commit_group;" ::: "memory");
}
template <int N>
__device__ __forceinline__ void cpa_wait() {
    asm volatile("cp.async.wait_group %0;" :: "n"(N) : "memory");
}
__device__ __forceinline__ void ldsmx4(uint32_t& r0, uint32_t& r1, uint32_t& r2, uint32_t& r3, uint32_t a) {
    asm volatile("ldmatrix.sync.aligned.m8n8.x4.shared.b16 {%0,%1,%2,%3},[%4];"
                 : "=r"(r0), "=r"(r1), "=r"(r2), "=r"(r3) : "r"(a));
}
__device__ __forceinline__ void ldsmx4t(uint32_t& r0, uint32_t& r1, uint32_t& r2, uint32_t& r3, uint32_t a) {
    asm volatile("ldmatrix.sync.aligned.m8n8.x4.trans.shared.b16 {%0,%1,%2,%3},[%4];"
                 : "=r"(r0), "=r"(r1), "=r"(r2), "=r"(r3) : "r"(a));
}
__device__ __forceinline__ void mma_bf16(float* d, const uint32_t* a, const uint32_t* b) {
    asm volatile("mma.sync.aligned.m16n8k16.row.col.f32.bf16.bf16.f32 "
                 "{%0,%1,%2,%3},{%4,%5,%6,%7},{%8,%9},{%0,%1,%2,%3};"
                 : "+f"(d[0]), "+f"(d[1]), "+f"(d[2]), "+f"(d[3])
                 : "r"(a[0]), "r"(a[1]), "r"(a[2]), "r"(a[3]), "r"(b[0]), "r"(b[1]));
}

// ---------------------------------------------------------------------------
// Producers
// ---------------------------------------------------------------------------
__global__ void im2col_split_kernel(const float* __restrict__ in) {
    size_t idx = (size_t)blockIdx.x * blockDim.x + threadIdx.x;
    size_t total = (size_t)MTOT * DMODEL;
    if (idx >= total) return;
    int k = (int)(idx % DMODEL);
    int m = (int)(idx / DMODEL);
    int q = k & 15;
    int p = (k >> 4) & 15;
    int c = k >> 8;
    int wp = m & 31;
    int hp = (m >> 5) & 31;
    int b = m >> 10;
    size_t src = (((size_t)(b * CH + c) * IMG) + (hp * PATCH + p)) * IMG + (wp * PATCH + q);
    bf16 hi, lo;
    split1(in[src], hi, lo);
    g_Ah0[idx] = hi;
    g_Al0[idx] = lo;
}

__global__ void pack_wT_split_kernel(const float* __restrict__ pw) {
    int idx = blockIdx.x * blockDim.x + threadIdx.x;
    if (idx >= DMODEL * DMODEL) return;
    int d = idx % DMODEL;
    int k = idx / DMODEL;
    bf16 hi, lo;
    split1(pw[(size_t)d * DMODEL + k], hi, lo);
    g_wTh[idx] = hi;
    g_wTl[idx] = lo;
}

__global__ void convert_split_kernel(const float* __restrict__ src,
                                     bf16* __restrict__ hi_p, bf16* __restrict__ lo_p, int n) {
    int idx = blockIdx.x * blockDim.x + threadIdx.x;
    if (idx >= n) return;
    bf16 hi, lo;
    split1(src[idx], hi, lo);
    hi_p[idx] = hi;
    lo_p[idx] = lo;
}

// ---------------------------------------------------------------------------
// Tensor-core GEMM: block 128x128, BK=32, 8 warps (warp tile 64x32),
// 3-stage cp.async ring, plane-pass MMA ordering, 2 CTAs/SM.
// ---------------------------------------------------------------------------
#define AST 40    // As row stride (bf16): 32 + 8 pad
#define BST 136   // Bs row stride: 128 + 8 pad
#define A_BYTES (128 * AST * 2)    // 10240
#define B_BYTES (32 * BST * 2)     // 8704
#define STAGE_BYTES (2 * A_BYTES + 2 * B_BYTES)   // 37888
#define NSTAGE 3
#define GEMM_SMEM (NSTAGE * STAGE_BYTES)          // 113664

template <bool GELU, bool RES, bool WF32, bool WSPLIT>
__global__ __launch_bounds__(256, 2) void mma_gemm(
    const bf16* __restrict__ Ah, const bf16* __restrict__ Al,
    const bf16* __restrict__ Bh, const bf16* __restrict__ Bl,
    const float* __restrict__ bias, const float* __restrict__ res,
    float* __restrict__ Cf, bf16* __restrict__ Ch, bf16* __restrict__ Cl,
    int M, int N, int K)
{
    extern __shared__ char dsm[];
    const uint32_t base = smem_u32(dsm);
    auto offAh = [&](int st) { return (uint32_t)(st * STAGE_BYTES); };
    auto offAl = [&](int st) { return (uint32_t)(st * STAGE_BYTES + A_BYTES); };
    auto offBh = [&](int st) { return (uint32_t)(st * STAGE_BYTES + 2 * A_BYTES); };
    auto offBl = [&](int st) { return (uint32_t)(st * STAGE_BYTES + 2 * A_BYTES + B_BYTES); };

    const int tid = threadIdx.x;
    const int l = tid & 31;
    const int w = tid >> 5;
    const int wm = (w & 1) * 64;     // 2 warps in M
    const int wn = (w >> 1) * 32;    // 4 warps in N
    const int m0 = blockIdx.y * 128;
    const int n0 = blockIdx.x * 128;

    float acc[4][4][4];
#pragma unroll
    for (int i = 0; i < 4; i++)
#pragma unroll
        for (int j = 0; j < 4; j++)
#pragma unroll
            for (int r = 0; r < 4; r++) acc[i][j][r] = 0.f;

    auto load_tile = [&](int st, int k0) {
        // A: 128x32 per plane = 512 16B-lanes
#pragma unroll
        for (int s = 0; s < 2; s++) {
            int c = tid + s * 256;
            int row = c >> 2, cc = (c & 3) * 8;
            size_t g = (size_t)(m0 + row) * K + k0 + cc;
            uint32_t d = (uint32_t)(row * AST + cc) * 2;
            cpa16(base + offAh(st) + d, Ah + g);
            cpa16(base + offAl(st) + d, Al + g);
        }
        // B: 32x128 per plane = 512 lanes
#pragma unroll
        for (int s = 0; s < 2; s++) {
            int c = tid + s * 256;
            int row = c >> 4, cc = (c & 15) * 8;
            size_t g = (size_t)(k0 + row) * N + n0 + cc;
            uint32_t d = (uint32_t)(row * BST + cc) * 2;
            cpa16(base + offBh(st) + d, Bh + g);
            cpa16(base + offBl(st) + d, Bl + g);
        }
        cpa_commit();
    };

    auto compute_tile = [&](int st) {
        const uint32_t sAh = base + offAh(st), sAl = base + offAl(st);
        const uint32_t sBh = base + offBh(st), sBl = base + offBl(st);
#pragma unroll
        for (int ks = 0; ks < 2; ks++) {
            uint32_t ah[4][4], al[4][4], bh[4][2], bl[4][2];
#pragma unroll
            for (int mf = 0; mf < 4; mf++) {
                int row = wm + mf * 16 + (l & 7) + ((l >> 3) & 1) * 8;
                int col = ks * 16 + (l >> 4) * 8;
                uint32_t off = (uint32_t)(row * AST + col) * 2;
                ldsmx4(ah[mf][0], ah[mf][1], ah[mf][2], ah[mf][3], sAh + off);
                ldsmx4(al[mf][0], al[mf][1], al[mf][2], al[mf][3], sAl + off);
            }
            {
                int row = ks * 16 + (l & 7) + ((l >> 3) & 1) * 8;
                int col = wn + (l >> 4) * 8;
                uint32_t off = (uint32_t)(row * BST + col) * 2;
                ldsmx4t(bh[0][0], bh[0][1], bh[1][0], bh[1][1], sBh + off);
                ldsmx4t(bh[2][0], bh[2][1], bh[3][0], bh[3][1], sBh + off + 32);
                ldsmx4t(bl[0][0], bl[0][1], bl[1][0], bl[1][1], sBl + off);
                ldsmx4t(bl[2][0], bl[2][1], bl[3][0], bl[3][1], sBl + off + 32);
            }
            // plane passes: 16 independent MMAs each
#pragma unroll
            for (int mf = 0; mf < 4; mf++)
#pragma unroll
                for (int nf = 0; nf < 4; nf++)
                    mma_bf16(acc[mf][nf], ah[mf], bh[nf]);
#pragma unroll
            for (int mf = 0; mf < 4; mf++)
#pragma unroll
                for (int nf = 0; nf < 4; nf++)
                    mma_bf16(acc[mf][nf], ah[mf], bl[nf]);
#pragma unroll
            for (int mf = 0; mf < 4; mf++)
#pragma unroll
                for (int nf = 0; nf < 4; nf++)
                    mma_bf16(acc[mf][nf], al[mf], bh[nf]);
        }
    };

    const int NT = K / 32;
    load_tile(0, 0);
    load_tile(1, 32);
    for (int t = 0; t < NT; t++) {
        cpa_wait<NSTAGE - 2>();
        __syncthreads();
        if (t + NSTAGE - 1 < NT)
            load_tile((t + NSTAGE - 1) % NSTAGE, (t + NSTAGE - 1) * 32);
        else
            cpa_commit();            // keep group count invariant
        compute_tile(t % NSTAGE);
    }

    // ---- epilogue ----
#pragma unroll
    for (int mf = 0; mf < 4; mf++) {
        int r0 = m0 + wm + mf * 16 + (l >> 2);
#pragma unroll
        for (int nf = 0; nf < 4; nf++) {
            int col = n0 + wn + nf * 8 + (l & 3) * 2;
            float bx = bias[col], by = bias[col + 1];
            float2 o0 = make_float2(acc[mf][nf][0] + bx, acc[mf][nf][1] + by);
            float2 o1 = make_float2(acc[mf][nf][2] + bx, acc[mf][nf][3] + by);
            if (GELU) {
                o0.x = gelu_tanh(o0.x); o0.y = gelu_tanh(o0.y);
                o1.x = gelu_tanh(o1.x); o1.y = gelu_tanh(o1.y);
            }
            if (RES) {
                float2 ra = *(const float2*)(res + (size_t)r0 * N + col);
                float2 rb = *(const float2*)(res + (size_t)(r0 + 8) * N + col);
                o0.x += ra.x; o0.y += ra.y;
                o1.x += rb.x; o1.y += rb.y;
            }
            size_t i0 = (size_t)r0 * N + col;
            size_t i1 = (size_t)(r0 + 8) * N + col;
            if (WF32) {
                *(float2*)(Cf + i0) = o0;
                *(float2*)(Cf + i1) = o1;
            }
            if (WSPLIT) {
                bf16 h0, l0h, h1, l1h, h2, l2h, h3, l3h;
                split1(o0.x, h0, l0h); split1(o0.y, h1, l1h);
                split1(o1.x, h2, l2h); split1(o1.y, h3, l3h);
                *(__nv_bfloat162*)(Ch + i0) = __halves2bfloat162(h0, h1);
                *(__nv_bfloat162*)(Cl + i0) = __halves2bfloat162(l0h, l1h);
                *(__nv_bfloat162*)(Ch + i1) = __halves2bfloat162(h2, h3);
                *(__nv_bfloat162*)(Cl + i1) = __halves2bfloat162(l2h, l3h);
            }
        }
    }
}

// ---------------------------------------------------------------------------
// LayerNorm + sinusoidal PE -> fp32 + split planes
// ---------------------------------------------------------------------------
__global__ void ln_pe_kernel(const float* __restrict__ x,
                             const float* __restrict__ gamma,
                             const float* __restrict__ beta,
                             float* __restrict__ outf,
                             bf16* __restrict__ outh, bf16* __restrict__ outl)
{
    const int row = blockIdx.x;
    const int tid = threadIdx.x;
    const float* xr = x + (size_t)row * DMODEL;

    float v0 = xr[tid], v1 = xr[tid + 256], v2 = xr[tid + 512];

    __shared__ float red[8];

    float s = v0 + v1 + v2;
#pragma unroll
    for (int o = 16; o > 0; o >>= 1) s += __shfl_xor_sync(0xffffffffu, s, o);
    if ((tid & 31) == 0) red[tid >> 5] = s;
    __syncthreads();
    float tot = red[0] + red[1] + red[2] + red[3] + red[4] + red[5] + red[6] + red[7];
    const float mean = tot / (float)DMODEL;
    __syncthreads();

    float d0 = v0 - mean, d1 = v1 - mean, d2 = v2 - mean;

    float sq = d0 * d0 + d1 * d1 + d2 * d2;
#pragma unroll
    for (int o = 16; o > 0; o >>= 1) sq += __shfl_xor_sync(0xffffffffu, sq, o);
    if ((tid & 31) == 0) red[tid >> 5] = sq;
    __syncthreads();
    float tot2 = red[0] + red[1] + red[2] + red[3] + red[4] + red[5] + red[6] + red[7];
    const float inv = rsqrtf(tot2 / (float)DMODEL + 1e-5f);

    const float n = (float)(row & (NTOK - 1));
    const float dv[3] = {d0, d1, d2};
    size_t rbase = (size_t)row * DMODEL;
#pragma unroll
    for (int j = 0; j < 3; j++) {
        int d = tid + j * 256;
        float freq = expf((float)(d & ~1) * (-9.210340371976184f / (float)DMODEL));
        float ang = n * freq;
        float pe = (d & 1) ? cosf(ang) : sinf(ang);
        float val = dv[j] * inv * gamma[d] + beta[d] + pe;
        outf[rbase + d] = val;
        bf16 hi, lo;
        split1(val, hi, lo);
        outh[rbase + d] = hi;
        outl[rbase + d] = lo;
    }
}

// ---------------------------------------------------------------------------
// Windowed attention -> split planes
// ---------------------------------------------------------------------------
__global__ void attn_kernel(const float* __restrict__ qkv,
                            bf16* __restrict__ outh, bf16* __restrict__ outl) {
    extern __shared__ float sm[];
    float* Qs = sm;
    float* Ks = sm + 64 * 65;
    float* Vs = sm + 2 * 64 * 65;
    float* Ss = sm + 3 * 64 * 65;

    const int blk = blockIdx.x;
    const int h = blk % NHEAD;
    const int w = (blk / NHEAD) % NWIN;
    const int b = blk / (NHEAD * NWIN);
    const int m0 = b * NTOK + w * WINSZ;
    const int tid = threadIdx.x;

    for (int idx = tid; idx < WINSZ * DHEAD; idx += 256) {
        int t = idx >> 6, d = idx & 63;
        size_t base = (size_t)(m0 + t) * QKVDIM + h * DHEAD + d;
        Qs[t * 65 + d] = qkv[base];
        Ks[t * 65 + d] = qkv[base + DMODEL];
        Vs[t * 65 + d] = qkv[base + 2 * DMODEL];
    }
    __syncthreads();

    for (int idx = tid; idx < WINSZ * WINSZ; idx += 256) {
        int q = idx >> 6, k = idx & 63;
        float s = 0.f;
#pragma unroll
        for (int i = 0; i < DHEAD; i++) s = fmaf(Qs[q * 65 + i], Ks[k * 65 + i], s);
        Ss[q * 65 + k] = s * 0.125f;
    }
    __syncthreads();

    if (tid < WINSZ) {
        float mx = -1e30f;
#pragma unroll 8
        for (int k = 0; k < WINSZ; k++) mx = fmaxf(mx, Ss[tid * 65 + k]);
        float sum = 0.f;
#pragma unroll 8
        for (int k = 0; k < WINSZ; k++) {
            float e = expf(Ss[tid * 65 + k] - mx);
            Ss[tid * 65 + k] = e;
            sum += e;
        }
        float invs = 1.f / sum;
#pragma unroll 8
        for (int k = 0; k < WINSZ; k++) Ss[tid * 65 + k] *= invs;
    }
    __syncthreads();

    for (int idx = tid; idx < WINSZ * DHEAD; idx += 256) {
        int q = idx >> 6, d = idx & 63;
        float o = 0.f;
#pragma unroll
        for (int k = 0; k < WINSZ; k++) o = fmaf(Ss[q * 65 + k], Vs[k * 65 + d], o);
        size_t oi = (size_t)(m0 + q) * DMODEL + h * DHEAD + d;
        bf16 hi, lo;
        split1(o, hi, lo);
        outh[oi] = hi;
        outl[oi] = lo;
    }
}

// ---------------------------------------------------------------------------
// Launch pipeline
// ---------------------------------------------------------------------------
extern "C" void kernel_launch(void* const* d_in, const int* in_sizes, int n_in,
                              void* d_out, int out_size)
{
    const float* input   = (const float*)d_in[0];
    const float* patch_w = (const float*)d_in[1];
    const float* patch_b = (const float*)d_in[2];
    const float* ln_g    = (const float*)d_in[3];
    const float* ln_b    = (const float*)d_in[4];
    const float* qkv_w   = (const float*)d_in[5];
    const float* qkv_b   = (const float*)d_in[6];
    const float* proj_w  = (const float*)d_in[7];
    const float* proj_b  = (const float*)d_in[8];
    const float* ff1_w   = (const float*)d_in[9];
    const float* ff1_b   = (const float*)d_in[10];
    const float* ff2_w   = (const float*)d_in[11];
    const float* ff2_b   = (const float*)d_in[12];
    float* out = (float*)d_out;

    bf16 *Ah0, *Al0, *wTh, *wTl, *qkvWh, *qkvWl, *projWh, *projWl, *ff1Wh, *ff1Wl, *ff2Wh, *ff2Wl;
    bf16 *x0h, *x0l, *hh, *hl, *yh, *yl, *attnh, *attnl, *x2h, *x2l;
    float *y, *x0, *qkvb, *x2;
    cudaGetSymbolAddress((void**)&Ah0, g_Ah0);   cudaGetSymbolAddress((void**)&Al0, g_Al0);
    cudaGetSymbolAddress((void**)&wTh, g_wTh);   cudaGetSymbolAddress((void**)&wTl, g_wTl);
    cudaGetSymbolAddress((void**)&qkvWh, g_qkvWh); cudaGetSymbolAddress((void**)&qkvWl, g_qkvWl);
    cudaGetSymbolAddress((void**)&projWh, g_projWh); cudaGetSymbolAddress((void**)&projWl, g_projWl);
    cudaGetSymbolAddress((void**)&ff1Wh, g_ff1Wh); cudaGetSymbolAddress((void**)&ff1Wl, g_ff1Wl);
    cudaGetSymbolAddress((void**)&ff2Wh, g_ff2Wh); cudaGetSymbolAddress((void**)&ff2Wl, g_ff2Wl);
    cudaGetSymbolAddress((void**)&x0h, g_x0h);   cudaGetSymbolAddress((void**)&x0l, g_x0l);
    cudaGetSymbolAddress((void**)&hh, g_hh);     cudaGetSymbolAddress((void**)&hl, g_hl);
    cudaGetSymbolAddress((void**)&yh, g_yh);     cudaGetSymbolAddress((void**)&yl, g_yl);
    cudaGetSymbolAddress((void**)&attnh, g_attnh); cudaGetSymbolAddress((void**)&attnl, g_attnl);
    cudaGetSymbolAddress((void**)&x2h, g_x2h);   cudaGetSymbolAddress((void**)&x2l, g_x2l);
    cudaGetSymbolAddress((void**)&y, g_y);
    cudaGetSymbolAddress((void**)&x0, g_x0);
    cudaGetSymbolAddress((void**)&qkvb, g_qkv);
    cudaGetSymbolAddress((void**)&x2, g_x2);

    const int ATTN_SMEM = 4 * 64 * 65 * sizeof(float);
    cudaFuncSetAttribute(attn_kernel, cudaFuncAttributeMaxDynamicSharedMemorySize, ATTN_SMEM);
    cudaFuncSetAttribute(mma_gemm<false, false, true, false>, cudaFuncAttributeMaxDynamicSharedMemorySize, GEMM_SMEM);
    cudaFuncSetAttribute(mma_gemm<true, false, false, true>, cudaFuncAttributeMaxDynamicSharedMemorySize, GEMM_SMEM);
    cudaFuncSetAttribute(mma_gemm<false, false, false, true>, cudaFuncAttributeMaxDynamicSharedMemorySize, GEMM_SMEM);
    cudaFuncSetAttribute(mma_gemm<false, true, true, true>, cudaFuncAttributeMaxDynamicSharedMemorySize, GEMM_SMEM);
    cudaFuncSetAttribute(mma_gemm<false, true, true, false>, cudaFuncAttributeMaxDynamicSharedMemorySize, GEMM_SMEM);

    dim3 gD(DMODEL / 128, MTOT / 128);     // (6,128)
    dim3 gF(FDIM / 128, MTOT / 128);       // (24,128)
    dim3 gQ(QKVDIM / 128, MTOT / 128);     // (18,128)

    // 1. im2col
    {
        size_t total = (size_t)MTOT * DMODEL;
        im2col_split_kernel<<<(unsigned)((total + 255) / 256), 256>>>(input);
    }
    // 2. patch weight
    pack_wT_split_kernel<<<(DMODEL * DMODEL + 255) / 256, 256>>>(patch_w);
    // 3. ff1 weight
    convert_split_kernel<<<(DMODEL * FDIM + 255) / 256, 256>>>(ff1_w, ff1Wh, ff1Wl, DMODEL * FDIM);
    // 4. patch embed -> fp32 y
    mma_gemm<false, false, true, false><<<gD, 256, GEMM_SMEM>>>(
        Ah0, Al0, wTh, wTl, patch_b, nullptr, y, nullptr, nullptr, MTOT, DMODEL, DMODEL);
    // 5. LN + PE -> x0 fp32 + planes
    ln_pe_kernel<<<MTOT, 256>>>(y, ln_g, ln_b, x0, x0h, x0l);
    // 6. ff1 + gelu -> h planes
    mma_gemm<true, false, false, true><<<gF, 256, GEMM_SMEM>>>(
        x0h, x0l, ff1Wh, ff1Wl, ff1_b, nullptr, nullptr, hh, hl, MTOT, FDIM, DMODEL);
    // 7. ff2 weight
    convert_split_kernel<<<(DMODEL * FDIM + 255) / 256, 256>>>(ff2_w, ff2Wh, ff2Wl, DMODEL * FDIM);
    // 8. ff2 -> y planes
    mma_gemm<false, false, false, true><<<gD, 256, GEMM_SMEM>>>(
        hh, hl, ff2Wh, ff2Wl, ff2_b, nullptr, nullptr, yh, yl, MTOT, DMODEL, FDIM);
    // 9. qkv weight
    convert_split_kernel<<<(DMODEL * QKVDIM + 255) / 256, 256>>>(qkv_w, qkvWh, qkvWl, DMODEL * QKVDIM);
    // 10. qkv -> fp32
    mma_gemm<false, false, true, false><<<gQ, 256, GEMM_SMEM>>>(
        yh, yl, qkvWh, qkvWl, qkv_b, nullptr, qkvb, nullptr, nullptr, MTOT, QKVDIM, DMODEL);
    // 11. attention -> planes
    attn_kernel<<<BATCH * NWIN * NHEAD, 256, ATTN_SMEM>>>(qkvb, attnh, attnl);
    // 12. proj weight
    convert_split_kernel<<<(DMODEL * DMODEL + 255) / 256, 256>>>(proj_w, projWh, projWl, DMODEL * DMODEL);
    // 13. proj + residual(x0) -> x2 fp32 + planes
    mma_gemm<false, true, true, true><<<gD, 256, GEMM_SMEM>>>(
        attnh, attnl, projWh, projWl, proj_b, x0, x2, x2h, x2l, MTOT, DMODEL, DMODEL);
    // 14. ff1 + gelu -> h planes
    mma_gemm<true, false, false, true><<<gF, 256, GEMM_SMEM>>>(
        x2h, x2l, ff1Wh, ff1Wl, ff1_b, nullptr, nullptr, hh, hl, MTOT, FDIM, DMODEL);
    // 15. ff2 + residual(x2) -> d_out
    mma_gemm<false, true, true, false><<<gD, 256, GEMM_SMEM>>>(
        hh, hl, ff2Wh, ff2Wl, ff2_b, x2, out, nullptr, nullptr, MTOT, DMODEL, FDIM);
}

// round 9
// speedup vs baseline: 2.4739x; 1.0198x over previous
#include <cuda_runtime.h>
#include <cuda_bf16.h>
#include <math.h>
#include <stdint.h>

// ---------------------------------------------------------------------------
// Problem constants
// ---------------------------------------------------------------------------
#define BATCH 16
#define CH 3
#define IMG 512
#define PATCH 16
#define NTOK 1024
#define MTOT (BATCH * NTOK)    // 16384
#define DMODEL 768
#define FDIM 3072
#define QKVDIM 2304
#define NHEAD 12
#define DHEAD 64
#define WINSZ 64
#define NWIN 16

typedef __nv_bfloat16 bf16;

// ---------------------------------------------------------------------------
// Static device scratch
// ---------------------------------------------------------------------------
__device__ bf16 g_Ah0[(size_t)MTOT * DMODEL];
__device__ bf16 g_Al0[(size_t)MTOT * DMODEL];
__device__ bf16 g_wTh[(size_t)DMODEL * DMODEL];
__device__ bf16 g_wTl[(size_t)DMODEL * DMODEL];
__device__ bf16 g_qkvWh[(size_t)DMODEL * QKVDIM];
__device__ bf16 g_qkvWl[(size_t)DMODEL * QKVDIM];
__device__ bf16 g_projWh[(size_t)DMODEL * DMODEL];
__device__ bf16 g_projWl[(size_t)DMODEL * DMODEL];
__device__ bf16 g_ff1Wh[(size_t)DMODEL * FDIM];
__device__ bf16 g_ff1Wl[(size_t)DMODEL * FDIM];
__device__ bf16 g_ff2Wh[(size_t)FDIM * DMODEL];
__device__ bf16 g_ff2Wl[(size_t)FDIM * DMODEL];

__device__ float g_y[(size_t)MTOT * DMODEL];
__device__ float g_x0[(size_t)MTOT * DMODEL];
__device__ bf16  g_x0h[(size_t)MTOT * DMODEL];
__device__ bf16  g_x0l[(size_t)MTOT * DMODEL];
__device__ bf16  g_hh[(size_t)MTOT * FDIM];
__device__ bf16  g_hl[(size_t)MTOT * FDIM];
__device__ bf16  g_yh[(size_t)MTOT * DMODEL];
__device__ bf16  g_yl[(size_t)MTOT * DMODEL];
__device__ float g_qkv[(size_t)MTOT * QKVDIM];
__device__ bf16  g_attnh[(size_t)MTOT * DMODEL];
__device__ bf16  g_attnl[(size_t)MTOT * DMODEL];
__device__ float g_x2[(size_t)MTOT * DMODEL];
__device__ bf16  g_x2h[(size_t)MTOT * DMODEL];
__device__ bf16  g_x2l[(size_t)MTOT * DMODEL];

// ---------------------------------------------------------------------------
// Helpers
// ---------------------------------------------------------------------------
__device__ __forceinline__ void split1(float x, bf16& hi, bf16& lo) {
    hi = __float2bfloat16(x);
    lo = __float2bfloat16(x - __bfloat162float(hi));
}
__device__ __forceinline__ float gelu_tanh(float x) {
    float x3 = x * x * x;
    return 0.5f * x * (1.0f + tanhf(0.7978845608028654f * (x + 0.044715f * x3)));
}
__device__ __forceinline__ uint32_t smem_u32(const void* p) {
    return (uint32_t)__cvta_generic_to_shared(p);
}
__device__ __forceinline__ void cpa16(uint32_t dst, const void* src) {
    asm volatile("cp.async.cg.shared.global [%0], [%1], 16;" :: "r"(dst), "l"(src) : "memory");
}
__device__ __forceinline__ void cpa_commit() {
    asm volatile("cp.async.commit_group;" ::: "memory");
}
template <int N>
__device__ __forceinline__ void cpa_wait() {
    asm volatile("cp.async.wait_group %0;" :: "n"(N) : "memory");
}
__device__ __forceinline__ void ldsmx4(uint32_t& r0, uint32_t& r1, uint32_t& r2, uint32_t& r3, uint32_t a) {
    asm volatile("ldmatrix.sync.aligned.m8n8.x4.shared.b16 {%0,%1,%2,%3},[%4];"
                 : "=r"(r0), "=r"(r1), "=r"(r2), "=r"(r3) : "r"(a));
}
__device__ __forceinline__ void ldsmx4t(uint32_t& r0, uint32_t& r1, uint32_t& r2, uint32_t& r3, uint32_t a) {
    asm volatile("ldmatrix.sync.aligned.m8n8.x4.trans.shared.b16 {%0,%1,%2,%3},[%4];"
                 : "=r"(r0), "=r"(r1), "=r"(r2), "=r"(r3) : "r"(a));
}
__device__ __forceinline__ void mma_bf16(float* d, const uint32_t* a, const uint32_t* b) {
    asm volatile("mma.sync.aligned.m16n8k16.row.col.f32.bf16.bf16.f32 "
                 "{%0,%1,%2,%3},{%4,%5,%6,%7},{%8,%9},{%0,%1,%2,%3};"
                 : "+f"(d[0]), "+f"(d[1]), "+f"(d[2]), "+f"(d[3])
                 : "r"(a[0]), "r"(a[1]), "r"(a[2]), "r"(a[3]), "r"(b[0]), "r"(b[1]));
}

// ---------------------------------------------------------------------------
// Producers
// ---------------------------------------------------------------------------
__global__ void im2col_split_kernel(const float* __restrict__ in) {
    size_t idx = (size_t)blockIdx.x * blockDim.x + threadIdx.x;
    size_t total = (size_t)MTOT * DMODEL;
    if (idx >= total) return;
    int k = (int)(idx % DMODEL);
    int m = (int)(idx / DMODEL);
    int q = k & 15;
    int p = (k >> 4) & 15;
    int c = k >> 8;
    int wp = m & 31;
    int hp = (m >> 5) & 31;
    int b = m >> 10;
    size_t src = (((size_t)(b * CH + c) * IMG) + (hp * PATCH + p)) * IMG + (wp * PATCH + q);
    bf16 hi, lo;
    split1(in[src], hi, lo);
    g_Ah0[idx] = hi;
    g_Al0[idx] = lo;
}

__global__ void pack_wT_split_kernel(const float* __restrict__ pw) {
    int idx = blockIdx.x * blockDim.x + threadIdx.x;
    if (idx >= DMODEL * DMODEL) return;
    int d = idx % DMODEL;
    int k = idx / DMODEL;
    bf16 hi, lo;
    split1(pw[(size_t)d * DMODEL + k], hi, lo);
    g_wTh[idx] = hi;
    g_wTl[idx] = lo;
}

__global__ void convert_split_kernel(const float* __restrict__ src,
                                     bf16* __restrict__ hi_p, bf16* __restrict__ lo_p, int n) {
    int idx = blockIdx.x * blockDim.x + threadIdx.x;
    if (idx >= n) return;
    bf16 hi, lo;
    split1(src[idx], hi, lo);
    hi_p[idx] = hi;
    lo_p[idx] = lo;
}

// ---------------------------------------------------------------------------
// Tensor-core GEMM: block 128x128, BK=32, 8 warps (warp tile 64x32),
// 3-stage cp.async ring, 2 CTAs/SM, ANTI-PHASED warp halves:
// warps 0-3 process k-slices {0,1}; warps 4-7 process {1,0}. Each SMSP's
// two same-CTA warps (w, w+4) are thus in opposite phases, so one issues
// MMAs while the other does ldmatrix.
// ---------------------------------------------------------------------------
#define AST 40    // As row stride (bf16): 32 + 8 pad
#define BST 136   // Bs row stride: 128 + 8 pad
#define A_BYTES (128 * AST * 2)    // 10240
#define B_BYTES (32 * BST * 2)     // 8704
#define STAGE_BYTES (2 * A_BYTES + 2 * B_BYTES)   // 37888
#define NSTAGE 3
#define GEMM_SMEM (NSTAGE * STAGE_BYTES)          // 113664

template <bool GELU, bool RES, bool WF32, bool WSPLIT>
__global__ __launch_bounds__(256, 2) void mma_gemm(
    const bf16* __restrict__ Ah, const bf16* __restrict__ Al,
    const bf16* __restrict__ Bh, const bf16* __restrict__ Bl,
    const float* __restrict__ bias, const float* __restrict__ res,
    float* __restrict__ Cf, bf16* __restrict__ Ch, bf16* __restrict__ Cl,
    int M, int N, int K)
{
    extern __shared__ char dsm[];
    const uint32_t base = smem_u32(dsm);
    auto offAh = [&](int st) { return (uint32_t)(st * STAGE_BYTES); };
    auto offAl = [&](int st) { return (uint32_t)(st * STAGE_BYTES + A_BYTES); };
    auto offBh = [&](int st) { return (uint32_t)(st * STAGE_BYTES + 2 * A_BYTES); };
    auto offBl = [&](int st) { return (uint32_t)(st * STAGE_BYTES + 2 * A_BYTES + B_BYTES); };

    const int tid = threadIdx.x;
    const int l = tid & 31;
    const int w = tid >> 5;
    const int wm = (w & 1) * 64;     // 2 warps in M
    const int wn = (w >> 1) * 32;    // 4 warps in N
    const int phase = (w >> 2) & 1;  // anti-phase selector
    const int m0 = blockIdx.y * 128;
    const int n0 = blockIdx.x * 128;

    float acc[4][4][4];
#pragma unroll
    for (int i = 0; i < 4; i++)
#pragma unroll
        for (int j = 0; j < 4; j++)
#pragma unroll
            for (int r = 0; r < 4; r++) acc[i][j][r] = 0.f;

    auto load_tile = [&](int st, int k0) {
#pragma unroll
        for (int s = 0; s < 2; s++) {
            int c = tid + s * 256;
            int row = c >> 2, cc = (c & 3) * 8;
            size_t g = (size_t)(m0 + row) * K + k0 + cc;
            uint32_t d = (uint32_t)(row * AST + cc) * 2;
            cpa16(base + offAh(st) + d, Ah + g);
            cpa16(base + offAl(st) + d, Al + g);
        }
#pragma unroll
        for (int s = 0; s < 2; s++) {
            int c = tid + s * 256;
            int row = c >> 4, cc = (c & 15) * 8;
            size_t g = (size_t)(k0 + row) * N + n0 + cc;
            uint32_t d = (uint32_t)(row * BST + cc) * 2;
            cpa16(base + offBh(st) + d, Bh + g);
            cpa16(base + offBl(st) + d, Bl + g);
        }
        cpa_commit();
    };

    auto compute_tile = [&](int st) {
        const uint32_t sAh = base + offAh(st), sAl = base + offAl(st);
        const uint32_t sBh = base + offBh(st), sBl = base + offBl(st);
#pragma unroll
        for (int ksi = 0; ksi < 2; ksi++) {
            const int ks = ksi ^ phase;       // warps 0-3: 0,1  |  warps 4-7: 1,0
            uint32_t ah[4][4], al[4][4], bh[4][2], bl[4][2];
#pragma unroll
            for (int mf = 0; mf < 4; mf++) {
                int row = wm + mf * 16 + (l & 7) + ((l >> 3) & 1) * 8;
                int col = ks * 16 + (l >> 4) * 8;
                uint32_t off = (uint32_t)(row * AST + col) * 2;
                ldsmx4(ah[mf][0], ah[mf][1], ah[mf][2], ah[mf][3], sAh + off);
                ldsmx4(al[mf][0], al[mf][1], al[mf][2], al[mf][3], sAl + off);
            }
            {
                int row = ks * 16 + (l & 7) + ((l >> 3) & 1) * 8;
                int col = wn + (l >> 4) * 8;
                uint32_t off = (uint32_t)(row * BST + col) * 2;
                ldsmx4t(bh[0][0], bh[0][1], bh[1][0], bh[1][1], sBh + off);
                ldsmx4t(bh[2][0], bh[2][1], bh[3][0], bh[3][1], sBh + off + 32);
                ldsmx4t(bl[0][0], bl[0][1], bl[1][0], bl[1][1], sBl + off);
                ldsmx4t(bl[2][0], bl[2][1], bl[3][0], bl[3][1], sBl + off + 32);
            }
#pragma unroll
            for (int mf = 0; mf < 4; mf++)
#pragma unroll
                for (int nf = 0; nf < 4; nf++)
                    mma_bf16(acc[mf][nf], ah[mf], bh[nf]);
#pragma unroll
            for (int mf = 0; mf < 4; mf++)
#pragma unroll
                for (int nf = 0; nf < 4; nf++)
                    mma_bf16(acc[mf][nf], ah[mf], bl[nf]);
#pragma unroll
            for (int mf = 0; mf < 4; mf++)
#pragma unroll
                for (int nf = 0; nf < 4; nf++)
                    mma_bf16(acc[mf][nf], al[mf], bh[nf]);
        }
    };

    const int NT = K / 32;
    load_tile(0, 0);
    load_tile(1, 32);
    for (int t = 0; t < NT; t++) {
        cpa_wait<NSTAGE - 2>();
        __syncthreads();
        if (t + NSTAGE - 1 < NT)
            load_tile((t + NSTAGE - 1) % NSTAGE, (t + NSTAGE - 1) * 32);
        else
            cpa_commit();            // keep group count invariant
        compute_tile(t % NSTAGE);
    }

    // ---- epilogue ----
#pragma unroll
    for (int mf = 0; mf < 4; mf++) {
        int r0 = m0 + wm + mf * 16 + (l >> 2);
#pragma unroll
        for (int nf = 0; nf < 4; nf++) {
            int col = n0 + wn + nf * 8 + (l & 3) * 2;
            float bx = bias[col], by = bias[col + 1];
            float2 o0 = make_float2(acc[mf][nf][0] + bx, acc[mf][nf][1] + by);
            float2 o1 = make_float2(acc[mf][nf][2] + bx, acc[mf][nf][3] + by);
            if (GELU) {
                o0.x = gelu_tanh(o0.x); o0.y = gelu_tanh(o0.y);
                o1.x = gelu_tanh(o1.x); o1.y = gelu_tanh(o1.y);
            }
            if (RES) {
                float2 ra = *(const float2*)(res + (size_t)r0 * N + col);
                float2 rb = *(const float2*)(res + (size_t)(r0 + 8) * N + col);
                o0.x += ra.x; o0.y += ra.y;
                o1.x += rb.x; o1.y += rb.y;
            }
            size_t i0 = (size_t)r0 * N + col;
            size_t i1 = (size_t)(r0 + 8) * N + col;
            if (WF32) {
                *(float2*)(Cf + i0) = o0;
                *(float2*)(Cf + i1) = o1;
            }
            if (WSPLIT) {
                bf16 h0, l0h, h1, l1h, h2, l2h, h3, l3h;
                split1(o0.x, h0, l0h); split1(o0.y, h1, l1h);
                split1(o1.x, h2, l2h); split1(o1.y, h3, l3h);
                *(__nv_bfloat162*)(Ch + i0) = __halves2bfloat162(h0, h1);
                *(__nv_bfloat162*)(Cl + i0) = __halves2bfloat162(l0h, l1h);
                *(__nv_bfloat162*)(Ch + i1) = __halves2bfloat162(h2, h3);
                *(__nv_bfloat162*)(Cl + i1) = __halves2bfloat162(l2h, l3h);
            }
        }
    }
}

// ---------------------------------------------------------------------------
// LayerNorm + sinusoidal PE -> fp32 + split planes
// ---------------------------------------------------------------------------
__global__ void ln_pe_kernel(const float* __restrict__ x,
                             const float* __restrict__ gamma,
                             const float* __restrict__ beta,
                             float* __restrict__ outf,
                             bf16* __restrict__ outh, bf16* __restrict__ outl)
{
    const int row = blockIdx.x;
    const int tid = threadIdx.x;
    const float* xr = x + (size_t)row * DMODEL;

    float v0 = xr[tid], v1 = xr[tid + 256], v2 = xr[tid + 512];

    __shared__ float red[8];

    float s = v0 + v1 + v2;
#pragma unroll
    for (int o = 16; o > 0; o >>= 1) s += __shfl_xor_sync(0xffffffffu, s, o);
    if ((tid & 31) == 0) red[tid >> 5] = s;
    __syncthreads();
    float tot = red[0] + red[1] + red[2] + red[3] + red[4] + red[5] + red[6] + red[7];
    const float mean = tot / (float)DMODEL;
    __syncthreads();

    float d0 = v0 - mean, d1 = v1 - mean, d2 = v2 - mean;

    float sq = d0 * d0 + d1 * d1 + d2 * d2;
#pragma unroll
    for (int o = 16; o > 0; o >>= 1) sq += __shfl_xor_sync(0xffffffffu, sq, o);
    if ((tid & 31) == 0) red[tid >> 5] = sq;
    __syncthreads();
    float tot2 = red[0] + red[1] + red[2] + red[3] + red[4] + red[5] + red[6] + red[7];
    const float inv = rsqrtf(tot2 / (float)DMODEL + 1e-5f);

    const float n = (float)(row & (NTOK - 1));
    const float dv[3] = {d0, d1, d2};
    size_t rbase = (size_t)row * DMODEL;
#pragma unroll
    for (int j = 0; j < 3; j++) {
        int d = tid + j * 256;
        float freq = expf((float)(d & ~1) * (-9.210340371976184f / (float)DMODEL));
        float ang = n * freq;
        float pe = (d & 1) ? cosf(ang) : sinf(ang);
        float val = dv[j] * inv * gamma[d] + beta[d] + pe;
        outf[rbase + d] = val;
        bf16 hi, lo;
        split1(val, hi, lo);
        outh[rbase + d] = hi;
        outl[rbase + d] = lo;
    }
}

// ---------------------------------------------------------------------------
// Windowed attention -> split planes
// ---------------------------------------------------------------------------
__global__ void attn_kernel(const float* __restrict__ qkv,
                            bf16* __restrict__ outh, bf16* __restrict__ outl) {
    extern __shared__ float sm[];
    float* Qs = sm;
    float* Ks = sm + 64 * 65;
    float* Vs = sm + 2 * 64 * 65;
    float* Ss = sm + 3 * 64 * 65;

    const int blk = blockIdx.x;
    const int h = blk % NHEAD;
    const int w = (blk / NHEAD) % NWIN;
    const int b = blk / (NHEAD * NWIN);
    const int m0 = b * NTOK + w * WINSZ;
    const int tid = threadIdx.x;

    for (int idx = tid; idx < WINSZ * DHEAD; idx += 256) {
        int t = idx >> 6, d = idx & 63;
        size_t base = (size_t)(m0 + t) * QKVDIM + h * DHEAD + d;
        Qs[t * 65 + d] = qkv[base];
        Ks[t * 65 + d] = qkv[base + DMODEL];
        Vs[t * 65 + d] = qkv[base + 2 * DMODEL];
    }
    __syncthreads();

    for (int idx = tid; idx < WINSZ * WINSZ; idx += 256) {
        int q = idx >> 6, k = idx & 63;
        float s = 0.f;
#pragma unroll
        for (int i = 0; i < DHEAD; i++) s = fmaf(Qs[q * 65 + i], Ks[k * 65 + i], s);
        Ss[q * 65 + k] = s * 0.125f;
    }
    __syncthreads();

    if (tid < WINSZ) {
        float mx = -1e30f;
#pragma unroll 8
        for (int k = 0; k < WINSZ; k++) mx = fmaxf(mx, Ss[tid * 65 + k]);
        float sum = 0.f;
#pragma unroll 8
        for (int k = 0; k < WINSZ; k++) {
            float e = expf(Ss[tid * 65 + k] - mx);
            Ss[tid * 65 + k] = e;
            sum += e;
        }
        float invs = 1.f / sum;
#pragma unroll 8
        for (int k = 0; k < WINSZ; k++) Ss[tid * 65 + k] *= invs;
    }
    __syncthreads();

    for (int idx = tid; idx < WINSZ * DHEAD; idx += 256) {
        int q = idx >> 6, d = idx & 63;
        float o = 0.f;
#pragma unroll
        for (int k = 0; k < WINSZ; k++) o = fmaf(Ss[q * 65 + k], Vs[k * 65 + d], o);
        size_t oi = (size_t)(m0 + q) * DMODEL + h * DHEAD + d;
        bf16 hi, lo;
        split1(o, hi, lo);
        outh[oi] = hi;
        outl[oi] = lo;
    }
}

// ---------------------------------------------------------------------------
// Launch pipeline
// ---------------------------------------------------------------------------
extern "C" void kernel_launch(void* const* d_in, const int* in_sizes, int n_in,
                              void* d_out, int out_size)
{
    const float* input   = (const float*)d_in[0];
    const float* patch_w = (const float*)d_in[1];
    const float* patch_b = (const float*)d_in[2];
    const float* ln_g    = (const float*)d_in[3];
    const float* ln_b    = (const float*)d_in[4];
    const float* qkv_w   = (const float*)d_in[5];
    const float* qkv_b   = (const float*)d_in[6];
    const float* proj_w  = (const float*)d_in[7];
    const float* proj_b  = (const float*)d_in[8];
    const float* ff1_w   = (const float*)d_in[9];
    const float* ff1_b   = (const float*)d_in[10];
    const float* ff2_w   = (const float*)d_in[11];
    const float* ff2_b   = (const float*)d_in[12];
    float* out = (float*)d_out;

    bf16 *Ah0, *Al0, *wTh, *wTl, *qkvWh, *qkvWl, *projWh, *projWl, *ff1Wh, *ff1Wl, *ff2Wh, *ff2Wl;
    bf16 *x0h, *x0l, *hh, *hl, *yh, *yl, *attnh, *attnl, *x2h, *x2l;
    float *y, *x0, *qkvb, *x2;
    cudaGetSymbolAddress((void**)&Ah0, g_Ah0);   cudaGetSymbolAddress((void**)&Al0, g_Al0);
    cudaGetSymbolAddress((void**)&wTh, g_wTh);   cudaGetSymbolAddress((void**)&wTl, g_wTl);
    cudaGetSymbolAddress((void**)&qkvWh, g_qkvWh); cudaGetSymbolAddress((void**)&qkvWl, g_qkvWl);
    cudaGetSymbolAddress((void**)&projWh, g_projWh); cudaGetSymbolAddress((void**)&projWl, g_projWl);
    cudaGetSymbolAddress((void**)&ff1Wh, g_ff1Wh); cudaGetSymbolAddress((void**)&ff1Wl, g_ff1Wl);
    cudaGetSymbolAddress((void**)&ff2Wh, g_ff2Wh); cudaGetSymbolAddress((void**)&ff2Wl, g_ff2Wl);
    cudaGetSymbolAddress((void**)&x0h, g_x0h);   cudaGetSymbolAddress((void**)&x0l, g_x0l);
    cudaGetSymbolAddress((void**)&hh, g_hh);     cudaGetSymbolAddress((void**)&hl, g_hl);
    cudaGetSymbolAddress((void**)&yh, g_yh);     cudaGetSymbolAddress((void**)&yl, g_yl);
    cudaGetSymbolAddress((void**)&attnh, g_attnh); cudaGetSymbolAddress((void**)&attnl, g_attnl);
    cudaGetSymbolAddress((void**)&x2h, g_x2h);   cudaGetSymbolAddress((void**)&x2l, g_x2l);
    cudaGetSymbolAddress((void**)&y, g_y);
    cudaGetSymbolAddress((void**)&x0, g_x0);
    cudaGetSymbolAddress((void**)&qkvb, g_qkv);
    cudaGetSymbolAddress((void**)&x2, g_x2);

    const int ATTN_SMEM = 4 * 64 * 65 * sizeof(float);
    cudaFuncSetAttribute(attn_kernel, cudaFuncAttributeMaxDynamicSharedMemorySize, ATTN_SMEM);
    cudaFuncSetAttribute(mma_gemm<false, false, true, false>, cudaFuncAttributeMaxDynamicSharedMemorySize, GEMM_SMEM);
    cudaFuncSetAttribute(mma_gemm<true, false, false, true>, cudaFuncAttributeMaxDynamicSharedMemorySize, GEMM_SMEM);
    cudaFuncSetAttribute(mma_gemm<false, false, false, true>, cudaFuncAttributeMaxDynamicSharedMemorySize, GEMM_SMEM);
    cudaFuncSetAttribute(mma_gemm<false, true, true, true>, cudaFuncAttributeMaxDynamicSharedMemorySize, GEMM_SMEM);
    cudaFuncSetAttribute(mma_gemm<false, true, true, false>, cudaFuncAttributeMaxDynamicSharedMemorySize, GEMM_SMEM);

    dim3 gD(DMODEL / 128, MTOT / 128);     // (6,128)
    dim3 gF(FDIM / 128, MTOT / 128);       // (24,128)
    dim3 gQ(QKVDIM / 128, MTOT / 128);     // (18,128)

    // 1. im2col
    {
        size_t total = (size_t)MTOT * DMODEL;
        im2col_split_kernel<<<(unsigned)((total + 255) / 256), 256>>>(input);
    }
    // 2. patch weight
    pack_wT_split_kernel<<<(DMODEL * DMODEL + 255) / 256, 256>>>(patch_w);
    // 3. ff1 weight
    convert_split_kernel<<<(DMODEL * FDIM + 255) / 256, 256>>>(ff1_w, ff1Wh, ff1Wl, DMODEL * FDIM);
    // 4. patch embed -> fp32 y
    mma_gemm<false, false, true, false><<<gD, 256, GEMM_SMEM>>>(
        Ah0, Al0, wTh, wTl, patch_b, nullptr, y, nullptr, nullptr, MTOT, DMODEL, DMODEL);
    // 5. LN + PE -> x0 fp32 + planes
    ln_pe_kernel<<<MTOT, 256>>>(y, ln_g, ln_b, x0, x0h, x0l);
    // 6. ff1 + gelu -> h planes
    mma_gemm<true, false, false, true><<<gF, 256, GEMM_SMEM>>>(
        x0h, x0l, ff1Wh, ff1Wl, ff1_b, nullptr, nullptr, hh, hl, MTOT, FDIM, DMODEL);
    // 7. ff2 weight
    convert_split_kernel<<<(DMODEL * FDIM + 255) / 256, 256>>>(ff2_w, ff2Wh, ff2Wl, DMODEL * FDIM);
    // 8. ff2 -> y planes
    mma_gemm<false, false, false, true><<<gD, 256, GEMM_SMEM>>>(
        hh, hl, ff2Wh, ff2Wl, ff2_b, nullptr, nullptr, yh, yl, MTOT, DMODEL, FDIM);
    // 9. qkv weight
    convert_split_kernel<<<(DMODEL * QKVDIM + 255) / 256, 256>>>(qkv_w, qkvWh, qkvWl, DMODEL * QKVDIM);
    // 10. qkv -> fp32
    mma_gemm<false, false, true, false><<<gQ, 256, GEMM_SMEM>>>(
        yh, yl, qkvWh, qkvWl, qkv_b, nullptr, qkvb, nullptr, nullptr, MTOT, QKVDIM, DMODEL);
    // 11. attention -> planes
    attn_kernel<<<BATCH * NWIN * NHEAD, 256, ATTN_SMEM>>>(qkvb, attnh, attnl);
    // 12. proj weight
    convert_split_kernel<<<(DMODEL * DMODEL + 255) / 256, 256>>>(proj_w, projWh, projWl, DMODEL * DMODEL);
    // 13. proj + residual(x0) -> x2 fp32 + planes
    mma_gemm<false, true, true, true><<<gD, 256, GEMM_SMEM>>>(
        attnh, attnl, projWh, projWl, proj_b, x0, x2, x2h, x2l, MTOT, DMODEL, DMODEL);
    // 14. ff1 + gelu -> h planes
    mma_gemm<true, false, false, true><<<gF, 256, GEMM_SMEM>>>(
        x2h, x2l, ff1Wh, ff1Wl, ff1_b, nullptr, nullptr, hh, hl, MTOT, FDIM, DMODEL);
    // 15. ff2 + residual(x2) -> d_out
    mma_gemm<false, true, true, false><<<gD, 256, GEMM_SMEM>>>(
        hh, hl, ff2Wh, ff2Wl, ff2_b, x2, out, nullptr, nullptr, MTOT, DMODEL, FDIM);
}

// round 10
// speedup vs baseline: 3.2400x; 1.3097x over previous
#include <cuda_runtime.h>
#include <cuda_fp16.h>
#include <math.h>
#include <stdint.h>

// ---------------------------------------------------------------------------
// Problem constants
// ---------------------------------------------------------------------------
#define BATCH 16
#define CH 3
#define IMG 512
#define PATCH 16
#define NTOK 1024
#define MTOT (BATCH * NTOK)    // 16384
#define DMODEL 768
#define FDIM 3072
#define QKVDIM 2304
#define NHEAD 12
#define DHEAD 64
#define WINSZ 64
#define NWIN 16

typedef __half f16;

// ---------------------------------------------------------------------------
// Static device scratch: activations = fp16 hi/lo planes (22-bit effective),
// weights = single fp16 plane.
// ---------------------------------------------------------------------------
__device__ f16 g_Ah0[(size_t)MTOT * DMODEL];   // im2col hi
__device__ f16 g_Al0[(size_t)MTOT * DMODEL];   // im2col lo
__device__ f16 g_wT[(size_t)DMODEL * DMODEL];  // patch weight T [k][d]
__device__ f16 g_qkvW[(size_t)DMODEL * QKVDIM];
__device__ f16 g_projW[(size_t)DMODEL * DMODEL];
__device__ f16 g_ff1W[(size_t)DMODEL * FDIM];
__device__ f16 g_ff2W[(size_t)FDIM * DMODEL];

__device__ float g_y[(size_t)MTOT * DMODEL];
__device__ float g_x0[(size_t)MTOT * DMODEL];
__device__ f16   g_x0h[(size_t)MTOT * DMODEL];
__device__ f16   g_x0l[(size_t)MTOT * DMODEL];
__device__ f16   g_hh[(size_t)MTOT * FDIM];
__device__ f16   g_hl[(size_t)MTOT * FDIM];
__device__ f16   g_yh[(size_t)MTOT * DMODEL];
__device__ f16   g_yl[(size_t)MTOT * DMODEL];
__device__ float g_qkv[(size_t)MTOT * QKVDIM];
__device__ f16   g_attnh[(size_t)MTOT * DMODEL];
__device__ f16   g_attnl[(size_t)MTOT * DMODEL];
__device__ float g_x2[(size_t)MTOT * DMODEL];
__device__ f16   g_x2h[(size_t)MTOT * DMODEL];
__device__ f16   g_x2l[(size_t)MTOT * DMODEL];

// ---------------------------------------------------------------------------
// Helpers
// ---------------------------------------------------------------------------
__device__ __forceinline__ void split1h(float x, f16& hi, f16& lo) {
    hi = __float2half_rn(x);
    lo = __float2half_rn(x - __half2float(hi));
}
__device__ __forceinline__ float gelu_tanh(float x) {
    float x3 = x * x * x;
    return 0.5f * x * (1.0f + tanhf(0.7978845608028654f * (x + 0.044715f * x3)));
}
__device__ __forceinline__ uint32_t smem_u32(const void* p) {
    return (uint32_t)__cvta_generic_to_shared(p);
}
__device__ __forceinline__ void cpa16(uint32_t dst, const void* src) {
    asm volatile("cp.async.cg.shared.global [%0], [%1], 16;" :: "r"(dst), "l"(src) : "memory");
}
__device__ __forceinline__ void cpa_commit() {
    asm volatile("cp.async.commit_group;" ::: "memory");
}
template <int N>
__device__ __forceinline__ void cpa_wait() {
    asm volatile("cp.async.wait_group %0;" :: "n"(N) : "memory");
}
__device__ __forceinline__ void ldsmx4(uint32_t& r0, uint32_t& r1, uint32_t& r2, uint32_t& r3, uint32_t a) {
    asm volatile("ldmatrix.sync.aligned.m8n8.x4.shared.b16 {%0,%1,%2,%3},[%4];"
                 : "=r"(r0), "=r"(r1), "=r"(r2), "=r"(r3) : "r"(a));
}
__device__ __forceinline__ void ldsmx4t(uint32_t& r0, uint32_t& r1, uint32_t& r2, uint32_t& r3, uint32_t a) {
    asm volatile("ldmatrix.sync.aligned.m8n8.x4.trans.shared.b16 {%0,%1,%2,%3},[%4];"
                 : "=r"(r0), "=r"(r1), "=r"(r2), "=r"(r3) : "r"(a));
}
__device__ __forceinline__ void mma_f16(float* d, const uint32_t* a, const uint32_t* b) {
    asm volatile("mma.sync.aligned.m16n8k16.row.col.f32.f16.f16.f32 "
                 "{%0,%1,%2,%3},{%4,%5,%6,%7},{%8,%9},{%0,%1,%2,%3};"
                 : "+f"(d[0]), "+f"(d[1]), "+f"(d[2]), "+f"(d[3])
                 : "r"(a[0]), "r"(a[1]), "r"(a[2]), "r"(a[3]), "r"(b[0]), "r"(b[1]));
}

// ---------------------------------------------------------------------------
// Producers
// ---------------------------------------------------------------------------
__global__ void im2col_split_kernel(const float* __restrict__ in) {
    size_t idx = (size_t)blockIdx.x * blockDim.x + threadIdx.x;
    size_t total = (size_t)MTOT * DMODEL;
    if (idx >= total) return;
    int k = (int)(idx % DMODEL);
    int m = (int)(idx / DMODEL);
    int q = k & 15;
    int p = (k >> 4) & 15;
    int c = k >> 8;
    int wp = m & 31;
    int hp = (m >> 5) & 31;
    int b = m >> 10;
    size_t src = (((size_t)(b * CH + c) * IMG) + (hp * PATCH + p)) * IMG + (wp * PATCH + q);
    f16 hi, lo;
    split1h(in[src], hi, lo);
    g_Ah0[idx] = hi;
    g_Al0[idx] = lo;
}

// patch_w [d][k] -> wT[k][d], single fp16 plane
__global__ void pack_wT_kernel(const float* __restrict__ pw) {
    int idx = blockIdx.x * blockDim.x + threadIdx.x;
    if (idx >= DMODEL * DMODEL) return;
    int d = idx % DMODEL;
    int k = idx / DMODEL;
    g_wT[idx] = __float2half_rn(pw[(size_t)d * DMODEL + k]);
}

__global__ void convert_kernel(const float* __restrict__ src, f16* __restrict__ dst, int n) {
    int idx = blockIdx.x * blockDim.x + threadIdx.x;
    if (idx >= n) return;
    dst[idx] = __float2half_rn(src[idx]);
}

// ---------------------------------------------------------------------------
// Tensor-core GEMM: block 128x128, BK=32, 8 warps (warp 64x32),
// fp16 2-plane scheme: acc += ah*bh + al*bh  (2 MMAs per fp32 product).
// 3-stage cp.async ring, 2 CTAs/SM, anti-phased warp halves.
// ---------------------------------------------------------------------------
#define AST 40    // As row stride (f16): 32 + 8 pad
#define BST 136   // Bs row stride: 128 + 8 pad
#define A_BYTES (128 * AST * 2)    // 10240
#define B_BYTES (32 * BST * 2)     // 8704
#define STAGE_BYTES (2 * A_BYTES + B_BYTES)   // 29184
#define NSTAGE 3
#define GEMM_SMEM (NSTAGE * STAGE_BYTES)      // 87552

template <bool GELU, bool RES, bool WF32, bool WSPLIT>
__global__ __launch_bounds__(256, 2) void mma_gemm(
    const f16* __restrict__ Ah, const f16* __restrict__ Al,
    const f16* __restrict__ B,
    const float* __restrict__ bias, const float* __restrict__ res,
    float* __restrict__ Cf, f16* __restrict__ Ch, f16* __restrict__ Cl,
    int M, int N, int K)
{
    extern __shared__ char dsm[];
    const uint32_t base = smem_u32(dsm);
    auto offAh = [&](int st) { return (uint32_t)(st * STAGE_BYTES); };
    auto offAl = [&](int st) { return (uint32_t)(st * STAGE_BYTES + A_BYTES); };
    auto offB  = [&](int st) { return (uint32_t)(st * STAGE_BYTES + 2 * A_BYTES); };

    const int tid = threadIdx.x;
    const int l = tid & 31;
    const int w = tid >> 5;
    const int wm = (w & 1) * 64;
    const int wn = (w >> 1) * 32;
    const int phase = (w >> 2) & 1;
    const int m0 = blockIdx.y * 128;
    const int n0 = blockIdx.x * 128;

    float acc[4][4][4];
#pragma unroll
    for (int i = 0; i < 4; i++)
#pragma unroll
        for (int j = 0; j < 4; j++)
#pragma unroll
            for (int r = 0; r < 4; r++) acc[i][j][r] = 0.f;

    auto load_tile = [&](int st, int k0) {
#pragma unroll
        for (int s = 0; s < 2; s++) {
            int c = tid + s * 256;
            int row = c >> 2, cc = (c & 3) * 8;
            size_t g = (size_t)(m0 + row) * K + k0 + cc;
            uint32_t d = (uint32_t)(row * AST + cc) * 2;
            cpa16(base + offAh(st) + d, Ah + g);
            cpa16(base + offAl(st) + d, Al + g);
        }
#pragma unroll
        for (int s = 0; s < 2; s++) {
            int c = tid + s * 256;
            int row = c >> 4, cc = (c & 15) * 8;
            size_t g = (size_t)(k0 + row) * N + n0 + cc;
            uint32_t d = (uint32_t)(row * BST + cc) * 2;
            cpa16(base + offB(st) + d, B + g);
        }
        cpa_commit();
    };

    auto compute_tile = [&](int st) {
        const uint32_t sAh = base + offAh(st), sAl = base + offAl(st);
        const uint32_t sB = base + offB(st);
#pragma unroll
        for (int ksi = 0; ksi < 2; ksi++) {
            const int ks = ksi ^ phase;
            uint32_t ah[4][4], al[4][4], bh[4][2];
#pragma unroll
            for (int mf = 0; mf < 4; mf++) {
                int row = wm + mf * 16 + (l & 7) + ((l >> 3) & 1) * 8;
                int col = ks * 16 + (l >> 4) * 8;
                uint32_t off = (uint32_t)(row * AST + col) * 2;
                ldsmx4(ah[mf][0], ah[mf][1], ah[mf][2], ah[mf][3], sAh + off);
                ldsmx4(al[mf][0], al[mf][1], al[mf][2], al[mf][3], sAl + off);
            }
            {
                int row = ks * 16 + (l & 7) + ((l >> 3) & 1) * 8;
                int col = wn + (l >> 4) * 8;
                uint32_t off = (uint32_t)(row * BST + col) * 2;
                ldsmx4t(bh[0][0], bh[0][1], bh[1][0], bh[1][1], sB + off);
                ldsmx4t(bh[2][0], bh[2][1], bh[3][0], bh[3][1], sB + off + 32);
            }
#pragma unroll
            for (int mf = 0; mf < 4; mf++)
#pragma unroll
                for (int nf = 0; nf < 4; nf++)
                    mma_f16(acc[mf][nf], ah[mf], bh[nf]);
#pragma unroll
            for (int mf = 0; mf < 4; mf++)
#pragma unroll
                for (int nf = 0; nf < 4; nf++)
                    mma_f16(acc[mf][nf], al[mf], bh[nf]);
        }
    };

    const int NT = K / 32;
    load_tile(0, 0);
    load_tile(1, 32);
    for (int t = 0; t < NT; t++) {
        cpa_wait<NSTAGE - 2>();
        __syncthreads();
        if (t + NSTAGE - 1 < NT)
            load_tile((t + NSTAGE - 1) % NSTAGE, (t + NSTAGE - 1) * 32);
        else
            cpa_commit();            // keep group count invariant
        compute_tile(t % NSTAGE);
    }

    // ---- epilogue ----
#pragma unroll
    for (int mf = 0; mf < 4; mf++) {
        int r0 = m0 + wm + mf * 16 + (l >> 2);
#pragma unroll
        for (int nf = 0; nf < 4; nf++) {
            int col = n0 + wn + nf * 8 + (l & 3) * 2;
            float bx = bias[col], by = bias[col + 1];
            float2 o0 = make_float2(acc[mf][nf][0] + bx, acc[mf][nf][1] + by);
            float2 o1 = make_float2(acc[mf][nf][2] + bx, acc[mf][nf][3] + by);
            if (GELU) {
                o0.x = gelu_tanh(o0.x); o0.y = gelu_tanh(o0.y);
                o1.x = gelu_tanh(o1.x); o1.y = gelu_tanh(o1.y);
            }
            if (RES) {
                float2 ra = *(const float2*)(res + (size_t)r0 * N + col);
                float2 rb = *(const float2*)(res + (size_t)(r0 + 8) * N + col);
                o0.x += ra.x; o0.y += ra.y;
                o1.x += rb.x; o1.y += rb.y;
            }
            size_t i0 = (size_t)r0 * N + col;
            size_t i1 = (size_t)(r0 + 8) * N + col;
            if (WF32) {
                *(float2*)(Cf + i0) = o0;
                *(float2*)(Cf + i1) = o1;
            }
            if (WSPLIT) {
                f16 h0, l0h, h1, l1h, h2, l2h, h3, l3h;
                split1h(o0.x, h0, l0h); split1h(o0.y, h1, l1h);
                split1h(o1.x, h2, l2h); split1h(o1.y, h3, l3h);
                *(__half2*)(Ch + i0) = __halves2half2(h0, h1);
                *(__half2*)(Cl + i0) = __halves2half2(l0h, l1h);
                *(__half2*)(Ch + i1) = __halves2half2(h2, h3);
                *(__half2*)(Cl + i1) = __halves2half2(l2h, l3h);
            }
        }
    }
}

// ---------------------------------------------------------------------------
// LayerNorm + sinusoidal PE -> fp32 + fp16 split planes
// ---------------------------------------------------------------------------
__global__ void ln_pe_kernel(const float* __restrict__ x,
                             const float* __restrict__ gamma,
                             const float* __restrict__ beta,
                             float* __restrict__ outf,
                             f16* __restrict__ outh, f16* __restrict__ outl)
{
    const int row = blockIdx.x;
    const int tid = threadIdx.x;
    const float* xr = x + (size_t)row * DMODEL;

    float v0 = xr[tid], v1 = xr[tid + 256], v2 = xr[tid + 512];

    __shared__ float red[8];

    float s = v0 + v1 + v2;
#pragma unroll
    for (int o = 16; o > 0; o >>= 1) s += __shfl_xor_sync(0xffffffffu, s, o);
    if ((tid & 31) == 0) red[tid >> 5] = s;
    __syncthreads();
    float tot = red[0] + red[1] + red[2] + red[3] + red[4] + red[5] + red[6] + red[7];
    const float mean = tot / (float)DMODEL;
    __syncthreads();

    float d0 = v0 - mean, d1 = v1 - mean, d2 = v2 - mean;

    float sq = d0 * d0 + d1 * d1 + d2 * d2;
#pragma unroll
    for (int o = 16; o > 0; o >>= 1) sq += __shfl_xor_sync(0xffffffffu, sq, o);
    if ((tid & 31) == 0) red[tid >> 5] = sq;
    __syncthreads();
    float tot2 = red[0] + red[1] + red[2] + red[3] + red[4] + red[5] + red[6] + red[7];
    const float inv = rsqrtf(tot2 / (float)DMODEL + 1e-5f);

    const float n = (float)(row & (NTOK - 1));
    const float dv[3] = {d0, d1, d2};
    size_t rbase = (size_t)row * DMODEL;
#pragma unroll
    for (int j = 0; j < 3; j++) {
        int d = tid + j * 256;
        float freq = expf((float)(d & ~1) * (-9.210340371976184f / (float)DMODEL));
        float ang = n * freq;
        float pe = (d & 1) ? cosf(ang) : sinf(ang);
        float val = dv[j] * inv * gamma[d] + beta[d] + pe;
        outf[rbase + d] = val;
        f16 hi, lo;
        split1h(val, hi, lo);
        outh[rbase + d] = hi;
        outl[rbase + d] = lo;
    }
}

// ---------------------------------------------------------------------------
// Windowed attention -> fp16 split planes
// ---------------------------------------------------------------------------
__global__ void attn_kernel(const float* __restrict__ qkv,
                            f16* __restrict__ outh, f16* __restrict__ outl) {
    extern __shared__ float sm[];
    float* Qs = sm;
    float* Ks = sm + 64 * 65;
    float* Vs = sm + 2 * 64 * 65;
    float* Ss = sm + 3 * 64 * 65;

    const int blk = blockIdx.x;
    const int h = blk % NHEAD;
    const int w = (blk / NHEAD) % NWIN;
    const int b = blk / (NHEAD * NWIN);
    const int m0 = b * NTOK + w * WINSZ;
    const int tid = threadIdx.x;

    for (int idx = tid; idx < WINSZ * DHEAD; idx += 256) {
        int t = idx >> 6, d = idx & 63;
        size_t base = (size_t)(m0 + t) * QKVDIM + h * DHEAD + d;
        Qs[t * 65 + d] = qkv[base];
        Ks[t * 65 + d] = qkv[base + DMODEL];
        Vs[t * 65 + d] = qkv[base + 2 * DMODEL];
    }
    __syncthreads();

    for (int idx = tid; idx < WINSZ * WINSZ; idx += 256) {
        int q = idx >> 6, k = idx & 63;
        float s = 0.f;
#pragma unroll
        for (int i = 0; i < DHEAD; i++) s = fmaf(Qs[q * 65 + i], Ks[k * 65 + i], s);
        Ss[q * 65 + k] = s * 0.125f;
    }
    __syncthreads();

    if (tid < WINSZ) {
        float mx = -1e30f;
#pragma unroll 8
        for (int k = 0; k < WINSZ; k++) mx = fmaxf(mx, Ss[tid * 65 + k]);
        float sum = 0.f;
#pragma unroll 8
        for (int k = 0; k < WINSZ; k++) {
            float e = expf(Ss[tid * 65 + k] - mx);
            Ss[tid * 65 + k] = e;
            sum += e;
        }
        float invs = 1.f / sum;
#pragma unroll 8
        for (int k = 0; k < WINSZ; k++) Ss[tid * 65 + k] *= invs;
    }
    __syncthreads();

    for (int idx = tid; idx < WINSZ * DHEAD; idx += 256) {
        int q = idx >> 6, d = idx & 63;
        float o = 0.f;
#pragma unroll
        for (int k = 0; k < WINSZ; k++) o = fmaf(Ss[q * 65 + k], Vs[k * 65 + d], o);
        size_t oi = (size_t)(m0 + q) * DMODEL + h * DHEAD + d;
        f16 hi, lo;
        split1h(o, hi, lo);
        outh[oi] = hi;
        outl[oi] = lo;
    }
}

// ---------------------------------------------------------------------------
// Launch pipeline
// ---------------------------------------------------------------------------
extern "C" void kernel_launch(void* const* d_in, const int* in_sizes, int n_in,
                              void* d_out, int out_size)
{
    const float* input   = (const float*)d_in[0];
    const float* patch_w = (const float*)d_in[1];
    const float* patch_b = (const float*)d_in[2];
    const float* ln_g    = (const float*)d_in[3];
    const float* ln_b    = (const float*)d_in[4];
    const float* qkv_w   = (const float*)d_in[5];
    const float* qkv_b   = (const float*)d_in[6];
    const float* proj_w  = (const float*)d_in[7];
    const float* proj_b  = (const float*)d_in[8];
    const float* ff1_w   = (const float*)d_in[9];
    const float* ff1_b   = (const float*)d_in[10];
    const float* ff2_w   = (const float*)d_in[11];
    const float* ff2_b   = (const float*)d_in[12];
    float* out = (float*)d_out;

    f16 *Ah0, *Al0, *wT, *qkvW, *projW, *ff1W, *ff2W;
    f16 *x0h, *x0l, *hh, *hl, *yh, *yl, *attnh, *attnl, *x2h, *x2l;
    float *y, *x0, *qkvb, *x2;
    cudaGetSymbolAddress((void**)&Ah0, g_Ah0);   cudaGetSymbolAddress((void**)&Al0, g_Al0);
    cudaGetSymbolAddress((void**)&wT, g_wT);
    cudaGetSymbolAddress((void**)&qkvW, g_qkvW);
    cudaGetSymbolAddress((void**)&projW, g_projW);
    cudaGetSymbolAddress((void**)&ff1W, g_ff1W);
    cudaGetSymbolAddress((void**)&ff2W, g_ff2W);
    cudaGetSymbolAddress((void**)&x0h, g_x0h);   cudaGetSymbolAddress((void**)&x0l, g_x0l);
    cudaGetSymbolAddress((void**)&hh, g_hh);     cudaGetSymbolAddress((void**)&hl, g_hl);
    cudaGetSymbolAddress((void**)&yh, g_yh);     cudaGetSymbolAddress((void**)&yl, g_yl);
    cudaGetSymbolAddress((void**)&attnh, g_attnh); cudaGetSymbolAddress((void**)&attnl, g_attnl);
    cudaGetSymbolAddress((void**)&x2h, g_x2h);   cudaGetSymbolAddress((void**)&x2l, g_x2l);
    cudaGetSymbolAddress((void**)&y, g_y);
    cudaGetSymbolAddress((void**)&x0, g_x0);
    cudaGetSymbolAddress((void**)&qkvb, g_qkv);
    cudaGetSymbolAddress((void**)&x2, g_x2);

    const int ATTN_SMEM = 4 * 64 * 65 * sizeof(float);
    cudaFuncSetAttribute(attn_kernel, cudaFuncAttributeMaxDynamicSharedMemorySize, ATTN_SMEM);
    cudaFuncSetAttribute(mma_gemm<false, false, true, false>, cudaFuncAttributeMaxDynamicSharedMemorySize, GEMM_SMEM);
    cudaFuncSetAttribute(mma_gemm<true, false, false, true>, cudaFuncAttributeMaxDynamicSharedMemorySize, GEMM_SMEM);
    cudaFuncSetAttribute(mma_gemm<false, false, false, true>, cudaFuncAttributeMaxDynamicSharedMemorySize, GEMM_SMEM);
    cudaFuncSetAttribute(mma_gemm<false, true, true, true>, cudaFuncAttributeMaxDynamicSharedMemorySize, GEMM_SMEM);
    cudaFuncSetAttribute(mma_gemm<false, true, true, false>, cudaFuncAttributeMaxDynamicSharedMemorySize, GEMM_SMEM);

    dim3 gD(DMODEL / 128, MTOT / 128);     // (6,128)
    dim3 gF(FDIM / 128, MTOT / 128);       // (24,128)
    dim3 gQ(QKVDIM / 128, MTOT / 128);     // (18,128)

    // 1. im2col
    {
        size_t total = (size_t)MTOT * DMODEL;
        im2col_split_kernel<<<(unsigned)((total + 255) / 256), 256>>>(input);
    }
    // 2. patch weight
    pack_wT_kernel<<<(DMODEL * DMODEL + 255) / 256, 256>>>(patch_w);
    // 3. ff1 weight
    convert_kernel<<<(DMODEL * FDIM + 255) / 256, 256>>>(ff1_w, ff1W, DMODEL * FDIM);
    // 4. patch embed -> fp32 y
    mma_gemm<false, false, true, false><<<gD, 256, GEMM_SMEM>>>(
        Ah0, Al0, wT, patch_b, nullptr, y, nullptr, nullptr, MTOT, DMODEL, DMODEL);
    // 5. LN + PE -> x0 fp32 + planes
    ln_pe_kernel<<<MTOT, 256>>>(y, ln_g, ln_b, x0, x0h, x0l);
    // 6. ff1 + gelu -> h planes
    mma_gemm<true, false, false, true><<<gF, 256, GEMM_SMEM>>>(
        x0h, x0l, ff1W, ff1_b, nullptr, nullptr, hh, hl, MTOT, FDIM, DMODEL);
    // 7. ff2 weight
    convert_kernel<<<(DMODEL * FDIM + 255) / 256, 256>>>(ff2_w, ff2W, DMODEL * FDIM);
    // 8. ff2 -> y planes
    mma_gemm<false, false, false, true><<<gD, 256, GEMM_SMEM>>>(
        hh, hl, ff2W, ff2_b, nullptr, nullptr, yh, yl, MTOT, DMODEL, FDIM);
    // 9. qkv weight
    convert_kernel<<<(DMODEL * QKVDIM + 255) / 256, 256>>>(qkv_w, qkvW, DMODEL * QKVDIM);
    // 10. qkv -> fp32
    mma_gemm<false, false, true, false><<<gQ, 256, GEMM_SMEM>>>(
        yh, yl, qkvW, qkv_b, nullptr, qkvb, nullptr, nullptr, MTOT, QKVDIM, DMODEL);
    // 11. attention -> planes
    attn_kernel<<<BATCH * NWIN * NHEAD, 256, ATTN_SMEM>>>(qkvb, attnh, attnl);
    // 12. proj weight
    convert_kernel<<<(DMODEL * DMODEL + 255) / 256, 256>>>(proj_w, projW, DMODEL * DMODEL);
    // 13. proj + residual(x0) -> x2 fp32 + planes
    mma_gemm<false, true, true, true><<<gD, 256, GEMM_SMEM>>>(
        attnh, attnl, projW, proj_b, x0, x2, x2h, x2l, MTOT, DMODEL, DMODEL);
    // 14. ff1 + gelu -> h planes
    mma_gemm<true, false, false, true><<<gF, 256, GEMM_SMEM>>>(
        x2h, x2l, ff1W, ff1_b, nullptr, nullptr, hh, hl, MTOT, FDIM, DMODEL);
    // 15. ff2 + residual(x2) -> d_out
    mma_gemm<false, true, true, false><<<gD, 256, GEMM_SMEM>>>(
        hh, hl, ff2W, ff2_b, x2, out, nullptr, nullptr, MTOT, DMODEL, FDIM);
}

// round 11
// speedup vs baseline: 5.2641x; 1.6247x over previous
#include <cuda_runtime.h>
#include <cuda_fp16.h>
#include <math.h>
#include <stdint.h>

// ---------------------------------------------------------------------------
// Problem constants
// ---------------------------------------------------------------------------
#define BATCH 16
#define CH 3
#define IMG 512
#define PATCH 16
#define NTOK 1024
#define MTOT (BATCH * NTOK)    // 16384
#define DMODEL 768
#define FDIM 3072
#define QKVDIM 2304
#define NHEAD 12
#define DHEAD 64
#define WINSZ 64
#define NWIN 16

typedef __half f16;

// ---------------------------------------------------------------------------
// Static device scratch: single fp16 plane everywhere (pure fp16 GEMMs,
// fp32 accumulate). fp32 kept for LN input, qkv, residuals, output.
// ---------------------------------------------------------------------------
__device__ f16 g_A0[(size_t)MTOT * DMODEL];    // im2col
__device__ f16 g_wT[(size_t)DMODEL * DMODEL];  // patch weight T [k][d]
__device__ f16 g_qkvW[(size_t)DMODEL * QKVDIM];
__device__ f16 g_projW[(size_t)DMODEL * DMODEL];
__device__ f16 g_ff1W[(size_t)DMODEL * FDIM];
__device__ f16 g_ff2W[(size_t)FDIM * DMODEL];

__device__ float g_y[(size_t)MTOT * DMODEL];
__device__ float g_x0[(size_t)MTOT * DMODEL];
__device__ f16   g_x0h[(size_t)MTOT * DMODEL];
__device__ f16   g_hh[(size_t)MTOT * FDIM];
__device__ f16   g_yh[(size_t)MTOT * DMODEL];
__device__ float g_qkv[(size_t)MTOT * QKVDIM];
__device__ f16   g_attnh[(size_t)MTOT * DMODEL];
__device__ float g_x2[(size_t)MTOT * DMODEL];
__device__ f16   g_x2h[(size_t)MTOT * DMODEL];

// ---------------------------------------------------------------------------
// Helpers
// ---------------------------------------------------------------------------
__device__ __forceinline__ float gelu_tanh(float x) {
    float x3 = x * x * x;
    return 0.5f * x * (1.0f + tanhf(0.7978845608028654f * (x + 0.044715f * x3)));
}
__device__ __forceinline__ uint32_t smem_u32(const void* p) {
    return (uint32_t)__cvta_generic_to_shared(p);
}
__device__ __forceinline__ void cpa16(uint32_t dst, const void* src) {
    asm volatile("cp.async.cg.shared.global [%0], [%1], 16;" :: "r"(dst), "l"(src) : "memory");
}
__device__ __forceinline__ void cpa_commit() {
    asm volatile("cp.async.commit_group;" ::: "memory");
}
template <int N>
__device__ __forceinline__ void cpa_wait() {
    asm volatile("cp.async.wait_group %0;" :: "n"(N) : "memory");
}
__device__ __forceinline__ void ldsmx4(uint32_t& r0, uint32_t& r1, uint32_t& r2, uint32_t& r3, uint32_t a) {
    asm volatile("ldmatrix.sync.aligned.m8n8.x4.shared.b16 {%0,%1,%2,%3},[%4];"
                 : "=r"(r0), "=r"(r1), "=r"(r2), "=r"(r3) : "r"(a));
}
__device__ __forceinline__ void ldsmx4t(uint32_t& r0, uint32_t& r1, uint32_t& r2, uint32_t& r3, uint32_t a) {
    asm volatile("ldmatrix.sync.aligned.m8n8.x4.trans.shared.b16 {%0,%1,%2,%3},[%4];"
                 : "=r"(r0), "=r"(r1), "=r"(r2), "=r"(r3) : "r"(a));
}
__device__ __forceinline__ void mma_f16(float* d, const uint32_t* a, const uint32_t* b) {
    asm volatile("mma.sync.aligned.m16n8k16.row.col.f32.f16.f16.f32 "
                 "{%0,%1,%2,%3},{%4,%5,%6,%7},{%8,%9},{%0,%1,%2,%3};"
                 : "+f"(d[0]), "+f"(d[1]), "+f"(d[2]), "+f"(d[3])
                 : "r"(a[0]), "r"(a[1]), "r"(a[2]), "r"(a[3]), "r"(b[0]), "r"(b[1]));
}

// ---------------------------------------------------------------------------
// Producers
// ---------------------------------------------------------------------------
__global__ void im2col_kernel(const float* __restrict__ in) {
    size_t idx = (size_t)blockIdx.x * blockDim.x + threadIdx.x;
    size_t total = (size_t)MTOT * DMODEL;
    if (idx >= total) return;
    int k = (int)(idx % DMODEL);
    int m = (int)(idx / DMODEL);
    int q = k & 15;
    int p = (k >> 4) & 15;
    int c = k >> 8;
    int wp = m & 31;
    int hp = (m >> 5) & 31;
    int b = m >> 10;
    size_t src = (((size_t)(b * CH + c) * IMG) + (hp * PATCH + p)) * IMG + (wp * PATCH + q);
    g_A0[idx] = __float2half_rn(in[src]);
}

// patch_w [d][k] -> wT[k][d]
__global__ void pack_wT_kernel(const float* __restrict__ pw) {
    int idx = blockIdx.x * blockDim.x + threadIdx.x;
    if (idx >= DMODEL * DMODEL) return;
    int d = idx % DMODEL;
    int k = idx / DMODEL;
    g_wT[idx] = __float2half_rn(pw[(size_t)d * DMODEL + k]);
}

__global__ void convert_kernel(const float* __restrict__ src, f16* __restrict__ dst, int n) {
    int idx = blockIdx.x * blockDim.x + threadIdx.x;
    if (idx >= n) return;
    dst[idx] = __float2half_rn(src[idx]);
}

// ---------------------------------------------------------------------------
// Tensor-core GEMM: block 128x128, BK=64, 8 warps (warp 64x32), pure fp16,
// 1 MMA per product, 3-stage cp.async ring, 2 CTAs/SM, anti-phased warps.
// ---------------------------------------------------------------------------
#define AST 72    // As row stride (f16): 64 + 8 pad
#define BST 136   // Bs row stride: 128 + 8 pad
#define A_BYTES (128 * AST * 2)    // 18432
#define B_BYTES (64 * BST * 2)     // 17408
#define STAGE_BYTES (A_BYTES + B_BYTES)   // 35840
#define NSTAGE 3
#define GEMM_SMEM (NSTAGE * STAGE_BYTES)  // 107520

template <bool GELU, bool RES, bool WF32, bool WH>
__global__ __launch_bounds__(256, 2) void mma_gemm(
    const f16* __restrict__ A, const f16* __restrict__ B,
    const float* __restrict__ bias, const float* __restrict__ res,
    float* __restrict__ Cf, f16* __restrict__ Ch,
    int M, int N, int K)
{
    extern __shared__ char dsm[];
    const uint32_t base = smem_u32(dsm);
    auto offA = [&](int st) { return (uint32_t)(st * STAGE_BYTES); };
    auto offB = [&](int st) { return (uint32_t)(st * STAGE_BYTES + A_BYTES); };

    const int tid = threadIdx.x;
    const int l = tid & 31;
    const int w = tid >> 5;
    const int wm = (w & 1) * 64;
    const int wn = (w >> 1) * 32;
    const int phase = (w >> 2) & 1;   // anti-phase: half the warps start at ks=2
    const int m0 = blockIdx.y * 128;
    const int n0 = blockIdx.x * 128;

    float acc[4][4][4];
#pragma unroll
    for (int i = 0; i < 4; i++)
#pragma unroll
        for (int j = 0; j < 4; j++)
#pragma unroll
            for (int r = 0; r < 4; r++) acc[i][j][r] = 0.f;

    auto load_tile = [&](int st, int k0) {
        // A: 128x64 f16 = 1024 16B-lanes
#pragma unroll
        for (int s = 0; s < 4; s++) {
            int c = tid + s * 256;
            int row = c >> 3, cc = (c & 7) * 8;
            size_t g = (size_t)(m0 + row) * K + k0 + cc;
            uint32_t d = (uint32_t)(row * AST + cc) * 2;
            cpa16(base + offA(st) + d, A + g);
        }
        // B: 64x128 f16 = 1024 lanes
#pragma unroll
        for (int s = 0; s < 4; s++) {
            int c = tid + s * 256;
            int row = c >> 4, cc = (c & 15) * 8;
            size_t g = (size_t)(k0 + row) * N + n0 + cc;
            uint32_t d = (uint32_t)(row * BST + cc) * 2;
            cpa16(base + offB(st) + d, B + g);
        }
        cpa_commit();
    };

    auto compute_tile = [&](int st) {
        const uint32_t sA = base + offA(st);
        const uint32_t sB = base + offB(st);
#pragma unroll
        for (int ksi = 0; ksi < 4; ksi++) {
            const int ks = (ksi + phase * 2) & 3;
            uint32_t ah[4][4], bh[4][2];
#pragma unroll
            for (int mf = 0; mf < 4; mf++) {
                int row = wm + mf * 16 + (l & 7) + ((l >> 3) & 1) * 8;
                int col = ks * 16 + (l >> 4) * 8;
                uint32_t off = (uint32_t)(row * AST + col) * 2;
                ldsmx4(ah[mf][0], ah[mf][1], ah[mf][2], ah[mf][3], sA + off);
            }
            {
                int row = ks * 16 + (l & 7) + ((l >> 3) & 1) * 8;
                int col = wn + (l >> 4) * 8;
                uint32_t off = (uint32_t)(row * BST + col) * 2;
                ldsmx4t(bh[0][0], bh[0][1], bh[1][0], bh[1][1], sB + off);
                ldsmx4t(bh[2][0], bh[2][1], bh[3][0], bh[3][1], sB + off + 32);
            }
#pragma unroll
            for (int mf = 0; mf < 4; mf++)
#pragma unroll
                for (int nf = 0; nf < 4; nf++)
                    mma_f16(acc[mf][nf], ah[mf], bh[nf]);
        }
    };

    const int NT = K / 64;
    load_tile(0, 0);
    load_tile(1, 64);
    for (int t = 0; t < NT; t++) {
        cpa_wait<NSTAGE - 2>();
        __syncthreads();
        if (t + NSTAGE - 1 < NT)
            load_tile((t + NSTAGE - 1) % NSTAGE, (t + NSTAGE - 1) * 64);
        else
            cpa_commit();            // keep group count invariant
        compute_tile(t % NSTAGE);
    }

    // ---- epilogue ----
#pragma unroll
    for (int mf = 0; mf < 4; mf++) {
        int r0 = m0 + wm + mf * 16 + (l >> 2);
#pragma unroll
        for (int nf = 0; nf < 4; nf++) {
            int col = n0 + wn + nf * 8 + (l & 3) * 2;
            float bx = bias[col], by = bias[col + 1];
            float2 o0 = make_float2(acc[mf][nf][0] + bx, acc[mf][nf][1] + by);
            float2 o1 = make_float2(acc[mf][nf][2] + bx, acc[mf][nf][3] + by);
            if (GELU) {
                o0.x = gelu_tanh(o0.x); o0.y = gelu_tanh(o0.y);
                o1.x = gelu_tanh(o1.x); o1.y = gelu_tanh(o1.y);
            }
            if (RES) {
                float2 ra = *(const float2*)(res + (size_t)r0 * N + col);
                float2 rb = *(const float2*)(res + (size_t)(r0 + 8) * N + col);
                o0.x += ra.x; o0.y += ra.y;
                o1.x += rb.x; o1.y += rb.y;
            }
            size_t i0 = (size_t)r0 * N + col;
            size_t i1 = (size_t)(r0 + 8) * N + col;
            if (WF32) {
                *(float2*)(Cf + i0) = o0;
                *(float2*)(Cf + i1) = o1;
            }
            if (WH) {
                *(__half2*)(Ch + i0) = __halves2half2(__float2half_rn(o0.x), __float2half_rn(o0.y));
                *(__half2*)(Ch + i1) = __halves2half2(__float2half_rn(o1.x), __float2half_rn(o1.y));
            }
        }
    }
}

// ---------------------------------------------------------------------------
// LayerNorm + sinusoidal PE -> fp32 + fp16 plane
// ---------------------------------------------------------------------------
__global__ void ln_pe_kernel(const float* __restrict__ x,
                             const float* __restrict__ gamma,
                             const float* __restrict__ beta,
                             float* __restrict__ outf,
                             f16* __restrict__ outh)
{
    const int row = blockIdx.x;
    const int tid = threadIdx.x;
    const float* xr = x + (size_t)row * DMODEL;

    float v0 = xr[tid], v1 = xr[tid + 256], v2 = xr[tid + 512];

    __shared__ float red[8];

    float s = v0 + v1 + v2;
#pragma unroll
    for (int o = 16; o > 0; o >>= 1) s += __shfl_xor_sync(0xffffffffu, s, o);
    if ((tid & 31) == 0) red[tid >> 5] = s;
    __syncthreads();
    float tot = red[0] + red[1] + red[2] + red[3] + red[4] + red[5] + red[6] + red[7];
    const float mean = tot / (float)DMODEL;
    __syncthreads();

    float d0 = v0 - mean, d1 = v1 - mean, d2 = v2 - mean;

    float sq = d0 * d0 + d1 * d1 + d2 * d2;
#pragma unroll
    for (int o = 16; o > 0; o >>= 1) sq += __shfl_xor_sync(0xffffffffu, sq, o);
    if ((tid & 31) == 0) red[tid >> 5] = sq;
    __syncthreads();
    float tot2 = red[0] + red[1] + red[2] + red[3] + red[4] + red[5] + red[6] + red[7];
    const float inv = rsqrtf(tot2 / (float)DMODEL + 1e-5f);

    const float n = (float)(row & (NTOK - 1));
    const float dv[3] = {d0, d1, d2};
    size_t rbase = (size_t)row * DMODEL;
#pragma unroll
    for (int j = 0; j < 3; j++) {
        int d = tid + j * 256;
        float freq = expf((float)(d & ~1) * (-9.210340371976184f / (float)DMODEL));
        float ang = n * freq;
        float pe = (d & 1) ? cosf(ang) : sinf(ang);
        float val = dv[j] * inv * gamma[d] + beta[d] + pe;
        outf[rbase + d] = val;
        outh[rbase + d] = __float2half_rn(val);
    }
}

// ---------------------------------------------------------------------------
// Windowed attention -> fp16 plane
// ---------------------------------------------------------------------------
__global__ void attn_kernel(const float* __restrict__ qkv,
                            f16* __restrict__ outh) {
    extern __shared__ float sm[];
    float* Qs = sm;
    float* Ks = sm + 64 * 65;
    float* Vs = sm + 2 * 64 * 65;
    float* Ss = sm + 3 * 64 * 65;

    const int blk = blockIdx.x;
    const int h = blk % NHEAD;
    const int w = (blk / NHEAD) % NWIN;
    const int b = blk / (NHEAD * NWIN);
    const int m0 = b * NTOK + w * WINSZ;
    const int tid = threadIdx.x;

    for (int idx = tid; idx < WINSZ * DHEAD; idx += 256) {
        int t = idx >> 6, d = idx & 63;
        size_t base = (size_t)(m0 + t) * QKVDIM + h * DHEAD + d;
        Qs[t * 65 + d] = qkv[base];
        Ks[t * 65 + d] = qkv[base + DMODEL];
        Vs[t * 65 + d] = qkv[base + 2 * DMODEL];
    }
    __syncthreads();

    for (int idx = tid; idx < WINSZ * WINSZ; idx += 256) {
        int q = idx >> 6, k = idx & 63;
        float s = 0.f;
#pragma unroll
        for (int i = 0; i < DHEAD; i++) s = fmaf(Qs[q * 65 + i], Ks[k * 65 + i], s);
        Ss[q * 65 + k] = s * 0.125f;
    }
    __syncthreads();

    if (tid < WINSZ) {
        float mx = -1e30f;
#pragma unroll 8
        for (int k = 0; k < WINSZ; k++) mx = fmaxf(mx, Ss[tid * 65 + k]);
        float sum = 0.f;
#pragma unroll 8
        for (int k = 0; k < WINSZ; k++) {
            float e = expf(Ss[tid * 65 + k] - mx);
            Ss[tid * 65 + k] = e;
            sum += e;
        }
        float invs = 1.f / sum;
#pragma unroll 8
        for (int k = 0; k < WINSZ; k++) Ss[tid * 65 + k] *= invs;
    }
    __syncthreads();

    for (int idx = tid; idx < WINSZ * DHEAD; idx += 256) {
        int q = idx >> 6, d = idx & 63;
        float o = 0.f;
#pragma unroll
        for (int k = 0; k < WINSZ; k++) o = fmaf(Ss[q * 65 + k], Vs[k * 65 + d], o);
        size_t oi = (size_t)(m0 + q) * DMODEL + h * DHEAD + d;
        outh[oi] = __float2half_rn(o);
    }
}

// ---------------------------------------------------------------------------
// Launch pipeline
// ---------------------------------------------------------------------------
extern "C" void kernel_launch(void* const* d_in, const int* in_sizes, int n_in,
                              void* d_out, int out_size)
{
    const float* input   = (const float*)d_in[0];
    const float* patch_w = (const float*)d_in[1];
    const float* patch_b = (const float*)d_in[2];
    const float* ln_g    = (const float*)d_in[3];
    const float* ln_b    = (const float*)d_in[4];
    const float* qkv_w   = (const float*)d_in[5];
    const float* qkv_b   = (const float*)d_in[6];
    const float* proj_w  = (const float*)d_in[7];
    const float* proj_b  = (const float*)d_in[8];
    const float* ff1_w   = (const float*)d_in[9];
    const float* ff1_b   = (const float*)d_in[10];
    const float* ff2_w   = (const float*)d_in[11];
    const float* ff2_b   = (const float*)d_in[12];
    float* out = (float*)d_out;

    f16 *A0, *wT, *qkvW, *projW, *ff1W, *ff2W;
    f16 *x0h, *hh, *yh, *attnh, *x2h;
    float *y, *x0, *qkvb, *x2;
    cudaGetSymbolAddress((void**)&A0, g_A0);
    cudaGetSymbolAddress((void**)&wT, g_wT);
    cudaGetSymbolAddress((void**)&qkvW, g_qkvW);
    cudaGetSymbolAddress((void**)&projW, g_projW);
    cudaGetSymbolAddress((void**)&ff1W, g_ff1W);
    cudaGetSymbolAddress((void**)&ff2W, g_ff2W);
    cudaGetSymbolAddress((void**)&x0h, g_x0h);
    cudaGetSymbolAddress((void**)&hh, g_hh);
    cudaGetSymbolAddress((void**)&yh, g_yh);
    cudaGetSymbolAddress((void**)&attnh, g_attnh);
    cudaGetSymbolAddress((void**)&x2h, g_x2h);
    cudaGetSymbolAddress((void**)&y, g_y);
    cudaGetSymbolAddress((void**)&x0, g_x0);
    cudaGetSymbolAddress((void**)&qkvb, g_qkv);
    cudaGetSymbolAddress((void**)&x2, g_x2);

    const int ATTN_SMEM = 4 * 64 * 65 * sizeof(float);
    cudaFuncSetAttribute(attn_kernel, cudaFuncAttributeMaxDynamicSharedMemorySize, ATTN_SMEM);
    cudaFuncSetAttribute(mma_gemm<false, false, true, false>, cudaFuncAttributeMaxDynamicSharedMemorySize, GEMM_SMEM);
    cudaFuncSetAttribute(mma_gemm<true, false, false, true>, cudaFuncAttributeMaxDynamicSharedMemorySize, GEMM_SMEM);
    cudaFuncSetAttribute(mma_gemm<false, false, false, true>, cudaFuncAttributeMaxDynamicSharedMemorySize, GEMM_SMEM);
    cudaFuncSetAttribute(mma_gemm<false, true, true, true>, cudaFuncAttributeMaxDynamicSharedMemorySize, GEMM_SMEM);
    cudaFuncSetAttribute(mma_gemm<false, true, true, false>, cudaFuncAttributeMaxDynamicSharedMemorySize, GEMM_SMEM);

    dim3 gD(DMODEL / 128, MTOT / 128);     // (6,128)
    dim3 gF(FDIM / 128, MTOT / 128);       // (24,128)
    dim3 gQ(QKVDIM / 128, MTOT / 128);     // (18,128)

    // 1. im2col
    {
        size_t total = (size_t)MTOT * DMODEL;
        im2col_kernel<<<(unsigned)((total + 255) / 256), 256>>>(input);
    }
    // 2. patch weight
    pack_wT_kernel<<<(DMODEL * DMODEL + 255) / 256, 256>>>(patch_w);
    // 3. ff1 weight
    convert_kernel<<<(DMODEL * FDIM + 255) / 256, 256>>>(ff1_w, ff1W, DMODEL * FDIM);
    // 4. patch embed -> fp32 y
    mma_gemm<false, false, true, false><<<gD, 256, GEMM_SMEM>>>(
        A0, wT, patch_b, nullptr, y, nullptr, MTOT, DMODEL, DMODEL);
    // 5. LN + PE -> x0 fp32 + plane
    ln_pe_kernel<<<MTOT, 256>>>(y, ln_g, ln_b, x0, x0h);
    // 6. ff1 + gelu -> h plane   (profiled launch)
    mma_gemm<true, false, false, true><<<gF, 256, GEMM_SMEM>>>(
        x0h, ff1W, ff1_b, nullptr, nullptr, hh, MTOT, FDIM, DMODEL);
    // 7. ff2 weight
    convert_kernel<<<(DMODEL * FDIM + 255) / 256, 256>>>(ff2_w, ff2W, DMODEL * FDIM);
    // 8. ff2 -> y plane
    mma_gemm<false, false, false, true><<<gD, 256, GEMM_SMEM>>>(
        hh, ff2W, ff2_b, nullptr, nullptr, yh, MTOT, DMODEL, FDIM);
    // 9. qkv weight
    convert_kernel<<<(DMODEL * QKVDIM + 255) / 256, 256>>>(qkv_w, qkvW, DMODEL * QKVDIM);
    // 10. qkv -> fp32
    mma_gemm<false, false, true, false><<<gQ, 256, GEMM_SMEM>>>(
        yh, qkvW, qkv_b, nullptr, qkvb, nullptr, MTOT, QKVDIM, DMODEL);
    // 11. attention -> plane
    attn_kernel<<<BATCH * NWIN * NHEAD, 256, ATTN_SMEM>>>(qkvb, attnh);
    // 12. proj weight
    convert_kernel<<<(DMODEL * DMODEL + 255) / 256, 256>>>(proj_w, projW, DMODEL * DMODEL);
    // 13. proj + residual(x0) -> x2 fp32 + plane
    mma_gemm<false, true, true, true><<<gD, 256, GEMM_SMEM>>>(
        attnh, projW, proj_b, x0, x2, x2h, MTOT, DMODEL, DMODEL);
    // 14. ff1 + gelu -> h plane
    mma_gemm<true, false, false, true><<<gF, 256, GEMM_SMEM>>>(
        x2h, ff1W, ff1_b, nullptr, nullptr, hh, MTOT, FDIM, DMODEL);
    // 15. ff2 + residual(x2) -> d_out
    mma_gemm<false, true, true, false><<<gD, 256, GEMM_SMEM>>>(
        hh, ff2W, ff2_b, x2, out, nullptr, MTOT, DMODEL, FDIM);
}

// round 12
// speedup vs baseline: 5.2719x; 1.0015x over previous
#include <cuda_runtime.h>
#include <cuda_fp16.h>
#include <math.h>
#include <stdint.h>

// ---------------------------------------------------------------------------
// Problem constants
// ---------------------------------------------------------------------------
#define BATCH 16
#define CH 3
#define IMG 512
#define PATCH 16
#define NTOK 1024
#define MTOT (BATCH * NTOK)    // 16384
#define DMODEL 768
#define FDIM 3072
#define QKVDIM 2304
#define NHEAD 12
#define DHEAD 64
#define WINSZ 64
#define NWIN 16

typedef __half f16;

// ---------------------------------------------------------------------------
// Static device scratch: single fp16 plane everywhere (pure fp16 GEMMs,
// fp32 accumulate). fp32 kept for LN input, qkv, residuals, output.
// ---------------------------------------------------------------------------
__device__ f16 g_A0[(size_t)MTOT * DMODEL];    // im2col
__device__ f16 g_wT[(size_t)DMODEL * DMODEL];  // patch weight T [k][d]
__device__ f16 g_qkvW[(size_t)DMODEL * QKVDIM];
__device__ f16 g_projW[(size_t)DMODEL * DMODEL];
__device__ f16 g_ff1W[(size_t)DMODEL * FDIM];
__device__ f16 g_ff2W[(size_t)FDIM * DMODEL];

__device__ float g_y[(size_t)MTOT * DMODEL];
__device__ float g_x0[(size_t)MTOT * DMODEL];
__device__ f16   g_x0h[(size_t)MTOT * DMODEL];
__device__ f16   g_hh[(size_t)MTOT * FDIM];
__device__ f16   g_yh[(size_t)MTOT * DMODEL];
__device__ float g_qkv[(size_t)MTOT * QKVDIM];
__device__ f16   g_attnh[(size_t)MTOT * DMODEL];
__device__ float g_x2[(size_t)MTOT * DMODEL];
__device__ f16   g_x2h[(size_t)MTOT * DMODEL];

// ---------------------------------------------------------------------------
// Helpers
// ---------------------------------------------------------------------------
__device__ __forceinline__ float gelu_tanh(float x) {
    float x3 = x * x * x;
    return 0.5f * x * (1.0f + tanhf(0.7978845608028654f * (x + 0.044715f * x3)));
}
__device__ __forceinline__ uint32_t smem_u32(const void* p) {
    return (uint32_t)__cvta_generic_to_shared(p);
}
__device__ __forceinline__ void cpa16(uint32_t dst, const void* src) {
    asm volatile("cp.async.cg.shared.global [%0], [%1], 16;" :: "r"(dst), "l"(src) : "memory");
}
__device__ __forceinline__ void cpa_commit() {
    asm volatile("cp.async.commit_group;" ::: "memory");
}
template <int N>
__device__ __forceinline__ void cpa_wait() {
    asm volatile("cp.async.wait_group %0;" :: "n"(N) : "memory");
}
__device__ __forceinline__ void ldsmx4(uint32_t& r0, uint32_t& r1, uint32_t& r2, uint32_t& r3, uint32_t a) {
    asm volatile("ldmatrix.sync.aligned.m8n8.x4.shared.b16 {%0,%1,%2,%3},[%4];"
                 : "=r"(r0), "=r"(r1), "=r"(r2), "=r"(r3) : "r"(a));
}
__device__ __forceinline__ void ldsmx4t(uint32_t& r0, uint32_t& r1, uint32_t& r2, uint32_t& r3, uint32_t a) {
    asm volatile("ldmatrix.sync.aligned.m8n8.x4.trans.shared.b16 {%0,%1,%2,%3},[%4];"
                 : "=r"(r0), "=r"(r1), "=r"(r2), "=r"(r3) : "r"(a));
}
__device__ __forceinline__ void mma_f16(float* d, const uint32_t* a, const uint32_t* b) {
    asm volatile("mma.sync.aligned.m16n8k16.row.col.f32.f16.f16.f32 "
                 "{%0,%1,%2,%3},{%4,%5,%6,%7},{%8,%9},{%0,%1,%2,%3};"
                 : "+f"(d[0]), "+f"(d[1]), "+f"(d[2]), "+f"(d[3])
                 : "r"(a[0]), "r"(a[1]), "r"(a[2]), "r"(a[3]), "r"(b[0]), "r"(b[1]));
}

// ---------------------------------------------------------------------------
// Producers
// ---------------------------------------------------------------------------
__global__ void im2col_kernel(const float* __restrict__ in) {
    size_t idx = (size_t)blockIdx.x * blockDim.x + threadIdx.x;
    size_t total = (size_t)MTOT * DMODEL;
    if (idx >= total) return;
    int k = (int)(idx % DMODEL);
    int m = (int)(idx / DMODEL);
    int q = k & 15;
    int p = (k >> 4) & 15;
    int c = k >> 8;
    int wp = m & 31;
    int hp = (m >> 5) & 31;
    int b = m >> 10;
    size_t src = (((size_t)(b * CH + c) * IMG) + (hp * PATCH + p)) * IMG + (wp * PATCH + q);
    g_A0[idx] = __float2half_rn(in[src]);
}

// patch_w [d][k] -> wT[k][d]
__global__ void pack_wT_kernel(const float* __restrict__ pw) {
    int idx = blockIdx.x * blockDim.x + threadIdx.x;
    if (idx >= DMODEL * DMODEL) return;
    int d = idx % DMODEL;
    int k = idx / DMODEL;
    g_wT[idx] = __float2half_rn(pw[(size_t)d * DMODEL + k]);
}

__global__ void convert_kernel(const float* __restrict__ src, f16* __restrict__ dst, int n) {
    int idx = blockIdx.x * blockDim.x + threadIdx.x;
    if (idx >= n) return;
    dst[idx] = __float2half_rn(src[idx]);
}

// ---------------------------------------------------------------------------
// Tensor-core GEMM: block 128x128, BK=64, 8 warps (warp 64x32), pure fp16,
// 1 MMA per product, 3-stage cp.async ring, 2 CTAs/SM, anti-phased warps.
// ---------------------------------------------------------------------------
#define AST 72    // As row stride (f16): 64 + 8 pad
#define BST 136   // Bs row stride: 128 + 8 pad
#define A_BYTES (128 * AST * 2)    // 18432
#define B_BYTES (64 * BST * 2)     // 17408
#define STAGE_BYTES (A_BYTES + B_BYTES)   // 35840
#define NSTAGE 3
#define GEMM_SMEM (NSTAGE * STAGE_BYTES)  // 107520

template <bool GELU, bool RES, bool WF32, bool WH>
__global__ __launch_bounds__(256, 2) void mma_gemm(
    const f16* __restrict__ A, const f16* __restrict__ B,
    const float* __restrict__ bias, const float* __restrict__ res,
    float* __restrict__ Cf, f16* __restrict__ Ch,
    int M, int N, int K)
{
    extern __shared__ char dsm[];
    const uint32_t base = smem_u32(dsm);
    auto offA = [&](int st) { return (uint32_t)(st * STAGE_BYTES); };
    auto offB = [&](int st) { return (uint32_t)(st * STAGE_BYTES + A_BYTES); };

    const int tid = threadIdx.x;
    const int l = tid & 31;
    const int w = tid >> 5;
    const int wm = (w & 1) * 64;
    const int wn = (w >> 1) * 32;
    const int phase = (w >> 2) & 1;   // anti-phase: half the warps start at ks=2
    const int m0 = blockIdx.y * 128;
    const int n0 = blockIdx.x * 128;

    float acc[4][4][4];
#pragma unroll
    for (int i = 0; i < 4; i++)
#pragma unroll
        for (int j = 0; j < 4; j++)
#pragma unroll
            for (int r = 0; r < 4; r++) acc[i][j][r] = 0.f;

    auto load_tile = [&](int st, int k0) {
        // A: 128x64 f16 = 1024 16B-lanes
#pragma unroll
        for (int s = 0; s < 4; s++) {
            int c = tid + s * 256;
            int row = c >> 3, cc = (c & 7) * 8;
            size_t g = (size_t)(m0 + row) * K + k0 + cc;
            uint32_t d = (uint32_t)(row * AST + cc) * 2;
            cpa16(base + offA(st) + d, A + g);
        }
        // B: 64x128 f16 = 1024 lanes
#pragma unroll
        for (int s = 0; s < 4; s++) {
            int c = tid + s * 256;
            int row = c >> 4, cc = (c & 15) * 8;
            size_t g = (size_t)(k0 + row) * N + n0 + cc;
            uint32_t d = (uint32_t)(row * BST + cc) * 2;
            cpa16(base + offB(st) + d, B + g);
        }
        cpa_commit();
    };

    auto compute_tile = [&](int st) {
        const uint32_t sA = base + offA(st);
        const uint32_t sB = base + offB(st);
#pragma unroll
        for (int ksi = 0; ksi < 4; ksi++) {
            const int ks = (ksi + phase * 2) & 3;
            uint32_t ah[4][4], bh[4][2];
#pragma unroll
            for (int mf = 0; mf < 4; mf++) {
                int row = wm + mf * 16 + (l & 7) + ((l >> 3) & 1) * 8;
                int col = ks * 16 + (l >> 4) * 8;
                uint32_t off = (uint32_t)(row * AST + col) * 2;
                ldsmx4(ah[mf][0], ah[mf][1], ah[mf][2], ah[mf][3], sA + off);
            }
            {
                int row = ks * 16 + (l & 7) + ((l >> 3) & 1) * 8;
                int col = wn + (l >> 4) * 8;
                uint32_t off = (uint32_t)(row * BST + col) * 2;
                ldsmx4t(bh[0][0], bh[0][1], bh[1][0], bh[1][1], sB + off);
                ldsmx4t(bh[2][0], bh[2][1], bh[3][0], bh[3][1], sB + off + 32);
            }
#pragma unroll
            for (int mf = 0; mf < 4; mf++)
#pragma unroll
                for (int nf = 0; nf < 4; nf++)
                    mma_f16(acc[mf][nf], ah[mf], bh[nf]);
        }
    };

    const int NT = K / 64;
    load_tile(0, 0);
    load_tile(1, 64);
    for (int t = 0; t < NT; t++) {
        cpa_wait<NSTAGE - 2>();
        __syncthreads();
        if (t + NSTAGE - 1 < NT)
            load_tile((t + NSTAGE - 1) % NSTAGE, (t + NSTAGE - 1) * 64);
        else
            cpa_commit();            // keep group count invariant
        compute_tile(t % NSTAGE);
    }

    // ---- epilogue ----
#pragma unroll
    for (int mf = 0; mf < 4; mf++) {
        int r0 = m0 + wm + mf * 16 + (l >> 2);
#pragma unroll
        for (int nf = 0; nf < 4; nf++) {
            int col = n0 + wn + nf * 8 + (l & 3) * 2;
            float bx = bias[col], by = bias[col + 1];
            float2 o0 = make_float2(acc[mf][nf][0] + bx, acc[mf][nf][1] + by);
            float2 o1 = make_float2(acc[mf][nf][2] + bx, acc[mf][nf][3] + by);
            if (GELU) {
                o0.x = gelu_tanh(o0.x); o0.y = gelu_tanh(o0.y);
                o1.x = gelu_tanh(o1.x); o1.y = gelu_tanh(o1.y);
            }
            if (RES) {
                float2 ra = *(const float2*)(res + (size_t)r0 * N + col);
                float2 rb = *(const float2*)(res + (size_t)(r0 + 8) * N + col);
                o0.x += ra.x; o0.y += ra.y;
                o1.x += rb.x; o1.y += rb.y;
            }
            size_t i0 = (size_t)r0 * N + col;
            size_t i1 = (size_t)(r0 + 8) * N + col;
            if (WF32) {
                *(float2*)(Cf + i0) = o0;
                *(float2*)(Cf + i1) = o1;
            }
            if (WH) {
                *(__half2*)(Ch + i0) = __halves2half2(__float2half_rn(o0.x), __float2half_rn(o0.y));
                *(__half2*)(Ch + i1) = __halves2half2(__float2half_rn(o1.x), __float2half_rn(o1.y));
            }
        }
    }
}

// ---------------------------------------------------------------------------
// LayerNorm + sinusoidal PE -> fp32 + fp16 plane
// ---------------------------------------------------------------------------
__global__ void ln_pe_kernel(const float* __restrict__ x,
                             const float* __restrict__ gamma,
                             const float* __restrict__ beta,
                             float* __restrict__ outf,
                             f16* __restrict__ outh)
{
    const int row = blockIdx.x;
    const int tid = threadIdx.x;
    const float* xr = x + (size_t)row * DMODEL;

    float v0 = xr[tid], v1 = xr[tid + 256], v2 = xr[tid + 512];

    __shared__ float red[8];

    float s = v0 + v1 + v2;
#pragma unroll
    for (int o = 16; o > 0; o >>= 1) s += __shfl_xor_sync(0xffffffffu, s, o);
    if ((tid & 31) == 0) red[tid >> 5] = s;
    __syncthreads();
    float tot = red[0] + red[1] + red[2] + red[3] + red[4] + red[5] + red[6] + red[7];
    const float mean = tot / (float)DMODEL;
    __syncthreads();

    float d0 = v0 - mean, d1 = v1 - mean, d2 = v2 - mean;

    float sq = d0 * d0 + d1 * d1 + d2 * d2;
#pragma unroll
    for (int o = 16; o > 0; o >>= 1) sq += __shfl_xor_sync(0xffffffffu, sq, o);
    if ((tid & 31) == 0) red[tid >> 5] = sq;
    __syncthreads();
    float tot2 = red[0] + red[1] + red[2] + red[3] + red[4] + red[5] + red[6] + red[7];
    const float inv = rsqrtf(tot2 / (float)DMODEL + 1e-5f);

    const float n = (float)(row & (NTOK - 1));
    const float dv[3] = {d0, d1, d2};
    size_t rbase = (size_t)row * DMODEL;
#pragma unroll
    for (int j = 0; j < 3; j++) {
        int d = tid + j * 256;
        float freq = expf((float)(d & ~1) * (-9.210340371976184f / (float)DMODEL));
        float ang = n * freq;
        float pe = (d & 1) ? cosf(ang) : sinf(ang);
        float val = dv[j] * inv * gamma[d] + beta[d] + pe;
        outf[rbase + d] = val;
        outh[rbase + d] = __float2half_rn(val);
    }
}

// ---------------------------------------------------------------------------
// Windowed attention -> fp16 plane
// ---------------------------------------------------------------------------
__global__ void attn_kernel(const float* __restrict__ qkv,
                            f16* __restrict__ outh) {
    extern __shared__ float sm[];
    float* Qs = sm;
    float* Ks = sm + 64 * 65;
    float* Vs = sm + 2 * 64 * 65;
    float* Ss = sm + 3 * 64 * 65;

    const int blk = blockIdx.x;
    const int h = blk % NHEAD;
    const int w = (blk / NHEAD) % NWIN;
    const int b = blk / (NHEAD * NWIN);
    const int m0 = b * NTOK + w * WINSZ;
    const int tid = threadIdx.x;

    for (int idx = tid; idx < WINSZ * DHEAD; idx += 256) {
        int t = idx >> 6, d = idx & 63;
        size_t base = (size_t)(m0 + t) * QKVDIM + h * DHEAD + d;
        Qs[t * 65 + d] = qkv[base];
        Ks[t * 65 + d] = qkv[base + DMODEL];
        Vs[t * 65 + d] = qkv[base + 2 * DMODEL];
    }
    __syncthreads();

    for (int idx = tid; idx < WINSZ * WINSZ; idx += 256) {
        int q = idx >> 6, k = idx & 63;
        float s = 0.f;
#pragma unroll
        for (int i = 0; i < DHEAD; i++) s = fmaf(Qs[q * 65 + i], Ks[k * 65 + i], s);
        Ss[q * 65 + k] = s * 0.125f;
    }
    __syncthreads();

    if (tid < WINSZ) {
        float mx = -1e30f;
#pragma unroll 8
        for (int k = 0; k < WINSZ; k++) mx = fmaxf(mx, Ss[tid * 65 + k]);
        float sum = 0.f;
#pragma unroll 8
        for (int k = 0; k < WINSZ; k++) {
            float e = expf(Ss[tid * 65 + k] - mx);
            Ss[tid * 65 + k] = e;
            sum += e;
        }
        float invs = 1.f / sum;
#pragma unroll 8
        for (int k = 0; k < WINSZ; k++) Ss[tid * 65 + k] *= invs;
    }
    __syncthreads();

    for (int idx = tid; idx < WINSZ * DHEAD; idx += 256) {
        int q = idx >> 6, d = idx & 63;
        float o = 0.f;
#pragma unroll
        for (int k = 0; k < WINSZ; k++) o = fmaf(Ss[q * 65 + k], Vs[k * 65 + d], o);
        size_t oi = (size_t)(m0 + q) * DMODEL + h * DHEAD + d;
        outh[oi] = __float2half_rn(o);
    }
}

// ---------------------------------------------------------------------------
// Launch pipeline
// ---------------------------------------------------------------------------
extern "C" void kernel_launch(void* const* d_in, const int* in_sizes, int n_in,
                              void* d_out, int out_size)
{
    const float* input   = (const float*)d_in[0];
    const float* patch_w = (const float*)d_in[1];
    const float* patch_b = (const float*)d_in[2];
    const float* ln_g    = (const float*)d_in[3];
    const float* ln_b    = (const float*)d_in[4];
    const float* qkv_w   = (const float*)d_in[5];
    const float* qkv_b   = (const float*)d_in[6];
    const float* proj_w  = (const float*)d_in[7];
    const float* proj_b  = (const float*)d_in[8];
    const float* ff1_w   = (const float*)d_in[9];
    const float* ff1_b   = (const float*)d_in[10];
    const float* ff2_w   = (const float*)d_in[11];
    const float* ff2_b   = (const float*)d_in[12];
    float* out = (float*)d_out;

    f16 *A0, *wT, *qkvW, *projW, *ff1W, *ff2W;
    f16 *x0h, *hh, *yh, *attnh, *x2h;
    float *y, *x0, *qkvb, *x2;
    cudaGetSymbolAddress((void**)&A0, g_A0);
    cudaGetSymbolAddress((void**)&wT, g_wT);
    cudaGetSymbolAddress((void**)&qkvW, g_qkvW);
    cudaGetSymbolAddress((void**)&projW, g_projW);
    cudaGetSymbolAddress((void**)&ff1W, g_ff1W);
    cudaGetSymbolAddress((void**)&ff2W, g_ff2W);
    cudaGetSymbolAddress((void**)&x0h, g_x0h);
    cudaGetSymbolAddress((void**)&hh, g_hh);
    cudaGetSymbolAddress((void**)&yh, g_yh);
    cudaGetSymbolAddress((void**)&attnh, g_attnh);
    cudaGetSymbolAddress((void**)&x2h, g_x2h);
    cudaGetSymbolAddress((void**)&y, g_y);
    cudaGetSymbolAddress((void**)&x0, g_x0);
    cudaGetSymbolAddress((void**)&qkvb, g_qkv);
    cudaGetSymbolAddress((void**)&x2, g_x2);

    const int ATTN_SMEM = 4 * 64 * 65 * sizeof(float);
    cudaFuncSetAttribute(attn_kernel, cudaFuncAttributeMaxDynamicSharedMemorySize, ATTN_SMEM);
    cudaFuncSetAttribute(mma_gemm<false, false, true, false>, cudaFuncAttributeMaxDynamicSharedMemorySize, GEMM_SMEM);
    cudaFuncSetAttribute(mma_gemm<true, false, false, true>, cudaFuncAttributeMaxDynamicSharedMemorySize, GEMM_SMEM);
    cudaFuncSetAttribute(mma_gemm<false, false, false, true>, cudaFuncAttributeMaxDynamicSharedMemorySize, GEMM_SMEM);
    cudaFuncSetAttribute(mma_gemm<false, true, true, true>, cudaFuncAttributeMaxDynamicSharedMemorySize, GEMM_SMEM);
    cudaFuncSetAttribute(mma_gemm<false, true, true, false>, cudaFuncAttributeMaxDynamicSharedMemorySize, GEMM_SMEM);

    dim3 gD(DMODEL / 128, MTOT / 128);     // (6,128)
    dim3 gF(FDIM / 128, MTOT / 128);       // (24,128)
    dim3 gQ(QKVDIM / 128, MTOT / 128);     // (18,128)

    // 1. im2col
    {
        size_t total = (size_t)MTOT * DMODEL;
        im2col_kernel<<<(unsigned)((total + 255) / 256), 256>>>(input);
    }
    // 2. patch weight
    pack_wT_kernel<<<(DMODEL * DMODEL + 255) / 256, 256>>>(patch_w);
    // 3. ff1 weight
    convert_kernel<<<(DMODEL * FDIM + 255) / 256, 256>>>(ff1_w, ff1W, DMODEL * FDIM);
    // 4. patch embed -> fp32 y
    mma_gemm<false, false, true, false><<<gD, 256, GEMM_SMEM>>>(
        A0, wT, patch_b, nullptr, y, nullptr, MTOT, DMODEL, DMODEL);
    // 5. LN + PE -> x0 fp32 + plane
    ln_pe_kernel<<<MTOT, 256>>>(y, ln_g, ln_b, x0, x0h);
    // 6. ff1 + gelu -> h plane   (profiled launch)
    mma_gemm<true, false, false, true><<<gF, 256, GEMM_SMEM>>>(
        x0h, ff1W, ff1_b, nullptr, nullptr, hh, MTOT, FDIM, DMODEL);
    // 7. ff2 weight
    convert_kernel<<<(DMODEL * FDIM + 255) / 256, 256>>>(ff2_w, ff2W, DMODEL * FDIM);
    // 8. ff2 -> y plane
    mma_gemm<false, false, false, true><<<gD, 256, GEMM_SMEM>>>(
        hh, ff2W, ff2_b, nullptr, nullptr, yh, MTOT, DMODEL, FDIM);
    // 9. qkv weight
    convert_kernel<<<(DMODEL * QKVDIM + 255) / 256, 256>>>(qkv_w, qkvW, DMODEL * QKVDIM);
    // 10. qkv -> fp32
    mma_gemm<false, false, true, false><<<gQ, 256, GEMM_SMEM>>>(
        yh, qkvW, qkv_b, nullptr, qkvb, nullptr, MTOT, QKVDIM, DMODEL);
    // 11. attention -> plane
    attn_kernel<<<BATCH * NWIN * NHEAD, 256, ATTN_SMEM>>>(qkvb, attnh);
    // 12. proj weight
    convert_kernel<<<(DMODEL * DMODEL + 255) / 256, 256>>>(proj_w, projW, DMODEL * DMODEL);
    // 13. proj + residual(x0) -> x2 fp32 + plane
    mma_gemm<false, true, true, true><<<gD, 256, GEMM_SMEM>>>(
        attnh, projW, proj_b, x0, x2, x2h, MTOT, DMODEL, DMODEL);
    // 14. ff1 + gelu -> h plane
    mma_gemm<true, false, false, true><<<gF, 256, GEMM_SMEM>>>(
        x2h, ff1W, ff1_b, nullptr, nullptr, hh, MTOT, FDIM, DMODEL);
    // 15. ff2 + residual(x2) -> d_out
    mma_gemm<false, true, true, false><<<gD, 256, GEMM_SMEM>>>(
        hh, ff2W, ff2_b, x2, out, nullptr, MTOT, DMODEL, FDIM);
}